// round 1
// baseline (speedup 1.0000x reference)
#include <cuda_runtime.h>
#include <math.h>
#include <stdint.h>
#include <stddef.h>

#define NB   8
#define LQ   512
#define EMB  768
#define NH   12
#define DH   64
#define NPOS 1023   // 2*MAXLEN-1

#define QT 128      // q rows per attention block
#define KT 64       // k cols per tile
#define QS_STRIDE 65
#define RT_STRIDE 193

// Scratch (allocation-free rule: __device__ globals)
__device__ __align__(16) float g_pe[NPOS*EMB];
__device__ __align__(16) float g_R [NPOS*EMB];
__device__ __align__(16) float g_Q [NB*LQ*EMB];
__device__ __align__(16) float g_K [NB*LQ*EMB];
__device__ __align__(16) float g_V [NB*LQ*EMB];
__device__ __align__(16) float g_AO[NB*LQ*EMB];

// ---------------------------------------------------------------------------
// Sinusoid table: pe[p][2i] = sin(p*div_i), pe[p][2i+1] = cos(p*div_i)
// div_i = exp(-2i * ln(10000)/E)
// ---------------------------------------------------------------------------
__global__ void pe_kernel() {
  int idx = blockIdx.x * 256 + threadIdx.x;
  if (idx >= NPOS*EMB) return;
  int p = idx / EMB;
  int e = idx - p * EMB;
  int i2 = e & ~1;
  float div = expf(-(float)i2 * (9.210340371976184f / (float)EMB));
  float ang = (float)p * div;
  g_pe[idx] = (e & 1) ? cosf(ang) : sinf(ang);
}

// ---------------------------------------------------------------------------
// SGEMM: C[M,Ncol] = A[M,K] @ B[K,Ncol] + bias[Ncol]
// 128x128 block tile, BK=8, 256 threads, 8x8 micro-tile.
// Requires: K % 8 == 0, Ncol % 128 == 0. M arbitrary (guarded).
// ---------------------------------------------------------------------------
__global__ __launch_bounds__(256) void sgemm_bias(
    const float* __restrict__ A, const float* __restrict__ B,
    const float* __restrict__ bias, float* __restrict__ C,
    int M, int K, int Ncol)
{
  __shared__ float As[8][128];   // transposed A tile
  __shared__ float Bs[8][128];
  int tid = threadIdx.x;
  int bm = blockIdx.y * 128, bn = blockIdx.x * 128;
  int tr = tid >> 4, tc = tid & 15;
  int arow = tid >> 1, acol = (tid & 1) * 4;
  int brow = tid >> 5, bcol = (tid & 31) * 4;

  float acc[8][8];
  #pragma unroll
  for (int i = 0; i < 8; i++)
    #pragma unroll
    for (int j = 0; j < 8; j++) acc[i][j] = 0.f;

  for (int k0 = 0; k0 < K; k0 += 8) {
    float4 av = make_float4(0.f, 0.f, 0.f, 0.f);
    if (bm + arow < M)
      av = *(const float4*)(A + (size_t)(bm + arow) * K + (k0 + acol));
    As[acol+0][arow] = av.x; As[acol+1][arow] = av.y;
    As[acol+2][arow] = av.z; As[acol+3][arow] = av.w;
    *(float4*)(&Bs[brow][bcol]) =
        *(const float4*)(B + (size_t)(k0 + brow) * Ncol + (bn + bcol));
    __syncthreads();
    #pragma unroll
    for (int kk = 0; kk < 8; kk++) {
      float a[8], b[8];
      *(float4*)(a)     = *(const float4*)(&As[kk][tr*4]);
      *(float4*)(a + 4) = *(const float4*)(&As[kk][64 + tr*4]);
      *(float4*)(b)     = *(const float4*)(&Bs[kk][tc*4]);
      *(float4*)(b + 4) = *(const float4*)(&Bs[kk][64 + tc*4]);
      #pragma unroll
      for (int i = 0; i < 8; i++)
        #pragma unroll
        for (int j = 0; j < 8; j++)
          acc[i][j] = fmaf(a[i], b[j], acc[i][j]);
    }
    __syncthreads();
  }

  int c0 = bn + tc*4, c1 = bn + 64 + tc*4;
  float4 bs0 = *(const float4*)(bias + c0);
  float4 bs1 = *(const float4*)(bias + c1);
  #pragma unroll
  for (int i = 0; i < 8; i++) {
    int row = bm + ((i < 4) ? (tr*4 + i) : (64 + tr*4 + (i - 4)));
    if (row < M) {
      float4 v0 = make_float4(acc[i][0]+bs0.x, acc[i][1]+bs0.y,
                              acc[i][2]+bs0.z, acc[i][3]+bs0.w);
      float4 v1 = make_float4(acc[i][4]+bs1.x, acc[i][5]+bs1.y,
                              acc[i][6]+bs1.z, acc[i][7]+bs1.w);
      *(float4*)(C + (size_t)row * Ncol + c0) = v0;
      *(float4*)(C + (size_t)row * Ncol + c1) = v1;
    }
  }
}

// ---------------------------------------------------------------------------
// Fused attention with relative position term.
// Block = (n, h, q-tile of 128). 128 threads; thread qi owns q-row q0+qi.
//   s[k]  = (Q[q]+rwb)·K[k]  +  (Q[q]+rrb)·R[q-k+511]      (then *1/8)
// Online softmax over k tiles of 64; O accumulated in registers.
// R window per k-tile stored TRANSPOSED in smem (Rt[d][r]) so the diagonal
// access r = qi-ki+63 is lane-consecutive -> conflict-free scalar LDS.
// ---------------------------------------------------------------------------
__global__ __launch_bounds__(128) void attn_kernel(
    const float* __restrict__ rwb, const float* __restrict__ rrb)
{
  extern __shared__ float smem[];
  float* Qs   = smem;                     // QT * 65
  float* Ks   = Qs + QT*QS_STRIDE;        // KT * 64
  float* Vs   = Ks + KT*DH;               // KT * 64
  float* Rt   = Vs + KT*DH;               // 64 * 193 (transposed window)
  float* Ps   = Rt + DH*RT_STRIDE;        // QT * 65 (probabilities)
  float* rwbs = Ps + QT*QS_STRIDE;        // 64
  float* rrbs = rwbs + DH;                // 64

  int b = blockIdx.x;
  int qt = b & 3; b >>= 2;
  int h = b % NH;
  int n = b / NH;
  int q0 = qt * QT;
  int tid = threadIdx.x;

  // Load Q tile (odd stride -> conflict-free per-lane scalar reads later)
  const float* Qg = g_Q + ((size_t)n*LQ + q0)*EMB + h*DH;
  for (int u = tid; u < QT*16; u += 128) {
    int r = u >> 4, c4 = (u & 15) << 2;
    float4 v = *(const float4*)(Qg + (size_t)r*EMB + c4);
    Qs[r*QS_STRIDE + c4+0] = v.x;
    Qs[r*QS_STRIDE + c4+1] = v.y;
    Qs[r*QS_STRIDE + c4+2] = v.z;
    Qs[r*QS_STRIDE + c4+3] = v.w;
  }
  if (tid < DH) { rwbs[tid] = rwb[h*DH + tid]; rrbs[tid] = rrb[h*DH + tid]; }
  __syncthreads();

  int qi = tid;
  float m = -1e30f, l = 0.f;
  float acc[DH];
  #pragma unroll
  for (int d = 0; d < DH; d++) acc[d] = 0.f;

  for (int k0 = 0; k0 < LQ; k0 += KT) {
    // --- load K,V tiles ---
    const float* Kg = g_K + ((size_t)n*LQ + k0)*EMB + h*DH;
    const float* Vg = g_V + ((size_t)n*LQ + k0)*EMB + h*DH;
    for (int u = tid; u < KT*16; u += 128) {
      int r = u >> 4, c4 = (u & 15) << 2;
      *(float4*)(Ks + r*DH + c4) = *(const float4*)(Kg + (size_t)r*EMB + c4);
      *(float4*)(Vs + r*DH + c4) = *(const float4*)(Vg + (size_t)r*EMB + c4);
    }
    // --- load R window transposed: Rt[d][r] = R[(base+r)*E + h*64 + d] ---
    // j = (q0+qi) - (k0+ki) + 511 = base + (qi - ki + 63), base = q0-k0+448
    // needed r in [0, 190], always 0 <= base+r <= 1022 for these shapes.
    int base = q0 - k0 + 448;
    for (int u = tid; u < 191*16; u += 128) {
      int r = u / 16, c4 = (u & 15) << 2;
      float4 v = *(const float4*)(g_R + (size_t)(base + r)*EMB + h*DH + c4);
      Rt[(c4+0)*RT_STRIDE + r] = v.x;
      Rt[(c4+1)*RT_STRIDE + r] = v.y;
      Rt[(c4+2)*RT_STRIDE + r] = v.z;
      Rt[(c4+3)*RT_STRIDE + r] = v.w;
    }
    __syncthreads();

    float s[KT];
    #pragma unroll
    for (int ki = 0; ki < KT; ki++) s[ki] = 0.f;

    // --- ac: (Q + r_w_bias) . K ---
    #pragma unroll 1
    for (int dc = 0; dc < 16; dc++) {
      float a0 = Qs[qi*QS_STRIDE + dc*4+0] + rwbs[dc*4+0];
      float a1 = Qs[qi*QS_STRIDE + dc*4+1] + rwbs[dc*4+1];
      float a2 = Qs[qi*QS_STRIDE + dc*4+2] + rwbs[dc*4+2];
      float a3 = Qs[qi*QS_STRIDE + dc*4+3] + rwbs[dc*4+3];
      #pragma unroll
      for (int ki = 0; ki < KT; ki++) {
        float4 kk = *(const float4*)(Ks + ki*DH + dc*4);
        s[ki] = fmaf(a0, kk.x, s[ki]);
        s[ki] = fmaf(a1, kk.y, s[ki]);
        s[ki] = fmaf(a2, kk.z, s[ki]);
        s[ki] = fmaf(a3, kk.w, s[ki]);
      }
    }
    // --- bd: (Q + r_r_bias) . R[q-k+511]  via transposed window ---
    #pragma unroll 1
    for (int d = 0; d < DH; d++) {
      float bq = Qs[qi*QS_STRIDE + d] + rrbs[d];
      const float* rp = Rt + d*RT_STRIDE + qi + 63;
      #pragma unroll
      for (int ki = 0; ki < KT; ki++)
        s[ki] = fmaf(bq, rp[-ki], s[ki]);
    }

    // --- online softmax update ---
    float mnew = m;
    #pragma unroll
    for (int ki = 0; ki < KT; ki++) { s[ki] *= 0.125f; mnew = fmaxf(mnew, s[ki]); }
    float corr = __expf(m - mnew);
    m = mnew;
    l *= corr;
    #pragma unroll
    for (int d = 0; d < DH; d++) acc[d] *= corr;
    float lsum = 0.f;
    #pragma unroll
    for (int ki = 0; ki < KT; ki++) {
      float p = __expf(s[ki] - mnew);
      lsum += p;
      Ps[qi*QS_STRIDE + ki] = p;   // stage P so the PV loop can index ki dynamically
    }
    l += lsum;

    // --- PV accumulate ---
    #pragma unroll 1
    for (int ki = 0; ki < KT; ki++) {
      float p = Ps[qi*QS_STRIDE + ki];
      const float4* vrow = (const float4*)(Vs + ki*DH);
      #pragma unroll
      for (int dc = 0; dc < 16; dc++) {
        float4 vv = vrow[dc];
        acc[dc*4+0] = fmaf(p, vv.x, acc[dc*4+0]);
        acc[dc*4+1] = fmaf(p, vv.y, acc[dc*4+1]);
        acc[dc*4+2] = fmaf(p, vv.z, acc[dc*4+2]);
        acc[dc*4+3] = fmaf(p, vv.w, acc[dc*4+3]);
      }
    }
    __syncthreads();
  }

  // --- write O row: AO[n][q0+qi][h*64 + d] ---
  float inv = 1.f / l;
  float* og = g_AO + ((size_t)n*LQ + q0 + qi)*EMB + h*DH;
  #pragma unroll
  for (int dc = 0; dc < 16; dc++) {
    float4 o = make_float4(acc[dc*4+0]*inv, acc[dc*4+1]*inv,
                           acc[dc*4+2]*inv, acc[dc*4+3]*inv);
    *(float4*)(og + dc*4) = o;
  }
}

// ---------------------------------------------------------------------------
extern "C" void kernel_launch(void* const* d_in, const int* in_sizes, int n_in,
                              void* d_out, int out_size) {
  (void)in_sizes; (void)n_in; (void)out_size;
  const float* values = (const float*)d_in[0];
  const float* keys   = (const float*)d_in[1];
  const float* query  = (const float*)d_in[2];
  const float* Wq   = (const float*)d_in[3];
  const float* bq   = (const float*)d_in[4];
  const float* Wk   = (const float*)d_in[5];
  const float* bk   = (const float*)d_in[6];
  const float* Wv   = (const float*)d_in[7];
  const float* bv   = (const float*)d_in[8];
  const float* Wo   = (const float*)d_in[9];
  const float* bo   = (const float*)d_in[10];
  const float* Wpos = (const float*)d_in[11];
  const float* bpos = (const float*)d_in[12];
  const float* rwb  = (const float*)d_in[13];
  const float* rrb  = (const float*)d_in[14];
  float* out = (float*)d_out;

  float *pe_p, *R_p, *Q_p, *K_p, *V_p, *AO_p;
  cudaGetSymbolAddress((void**)&pe_p, g_pe);
  cudaGetSymbolAddress((void**)&R_p,  g_R);
  cudaGetSymbolAddress((void**)&Q_p,  g_Q);
  cudaGetSymbolAddress((void**)&K_p,  g_K);
  cudaGetSymbolAddress((void**)&V_p,  g_V);
  cudaGetSymbolAddress((void**)&AO_p, g_AO);

  int smem_bytes = (QT*QS_STRIDE + KT*DH + KT*DH + DH*RT_STRIDE
                    + QT*QS_STRIDE + 2*DH) * (int)sizeof(float);
  cudaFuncSetAttribute(attn_kernel, cudaFuncAttributeMaxDynamicSharedMemorySize,
                       smem_bytes);

  // 1) sinusoid table
  pe_kernel<<<(NPOS*EMB + 255)/256, 256>>>();
  // 2) R = pe @ Wpos + bpos   (1023 x 768)
  sgemm_bias<<<dim3(6, 8), 256>>>(pe_p, Wpos, bpos, R_p, NPOS, EMB, EMB);
  // 3) Q/K/V projections (4096 x 768)
  sgemm_bias<<<dim3(6, 32), 256>>>(query,  Wq, bq, Q_p, NB*LQ, EMB, EMB);
  sgemm_bias<<<dim3(6, 32), 256>>>(keys,   Wk, bk, K_p, NB*LQ, EMB, EMB);
  sgemm_bias<<<dim3(6, 32), 256>>>(values, Wv, bv, V_p, NB*LQ, EMB, EMB);
  // 4) fused rel-pos attention
  attn_kernel<<<NB*NH*(LQ/QT), 128, smem_bytes>>>(rwb, rrb);
  // 5) output projection
  sgemm_bias<<<dim3(6, 32), 256>>>(AO_p, Wo, bo, out, NB*LQ, EMB, EMB);
}

// round 2
// speedup vs baseline: 1.4281x; 1.4281x over previous
#include <cuda_runtime.h>
#include <math.h>
#include <stdint.h>
#include <stddef.h>

#define NB   8
#define LQ   512
#define EMB  768
#define NH   12
#define DH   64
#define NPOS 1023   // 2*MAXLEN-1
#define JPAD 1024   // padded j dimension for T / RT

#define QT 128      // q rows per attention block
#define KT 64       // k cols per tile
#define QS_STRIDE 65

// ---------------- scratch (__device__ globals: allocation-free rule) --------
__device__ __align__(16) float g_pe[NPOS*EMB];
__device__ __align__(16) float g_R [NPOS*EMB];
__device__ __align__(16) float g_RT[EMB*JPAD];            // RT[e][j] = R[j][e] (j=1023 -> 0)
__device__ __align__(16) float g_Q [NB*LQ*EMB];
__device__ __align__(16) float g_Qr[NB*LQ*EMB];           // Q + r_r_bias
__device__ __align__(16) float g_K [NB*LQ*EMB];
__device__ __align__(16) float g_V [NB*LQ*EMB];
__device__ __align__(16) float g_T [(size_t)NH*NB*LQ*JPAD]; // T[h][m][j]
__device__ __align__(16) float g_BD[(size_t)NB*NH*LQ*LQ]; // bd[n][h][q][k]
__device__ __align__(16) float g_AO[NB*LQ*EMB];

// ---------------------------------------------------------------------------
// Sinusoid table
// ---------------------------------------------------------------------------
__global__ void pe_kernel() {
  int idx = blockIdx.x * 256 + threadIdx.x;
  if (idx >= NPOS*EMB) return;
  int p = idx / EMB;
  int e = idx - p * EMB;
  int i2 = e & ~1;
  float div = expf(-(float)i2 * (9.210340371976184f / (float)EMB));
  float ang = (float)p * div;
  g_pe[idx] = (e & 1) ? cosf(ang) : sinf(ang);
}

// ---------------------------------------------------------------------------
// TF32 tensor-core GEMM: C[M,N] = A[M,K] @ B[K,N] (+ bias)
// Requirements: K % 32 == 0, N % 128 == 0 (grid.x = N/128). M guarded.
// 256 threads = 8 warps (2x4), warp tile 64x32, mma m16n8k8.
// ---------------------------------------------------------------------------
__device__ __forceinline__ uint32_t f2tf(float f) {
  uint32_t u; asm("cvt.rna.tf32.f32 %0, %1;" : "=r"(u) : "f"(f)); return u;
}

__global__ __launch_bounds__(256) void gemm_tf32(
    const float* __restrict__ A, const float* __restrict__ B,
    const float* __restrict__ bias, float* __restrict__ C,
    int M, int K, int N, int lda, int ldb, int ldc)
{
  __shared__ uint32_t As[128][36];   // [m][k], stride 36 -> conflict-free frags
  __shared__ uint32_t Bs[32][136];   // [k][n], stride 136 -> conflict-free frags
  int tid  = threadIdx.x;
  int lane = tid & 31;
  int wid  = tid >> 5;
  int g = lane >> 2, c = lane & 3;
  int wm0 = (wid >> 2) * 64, wn0 = (wid & 3) * 32;
  int bm = blockIdx.y * 128, bn = blockIdx.x * 128;

  float acc[4][4][4];
  #pragma unroll
  for (int i = 0; i < 4; i++)
    #pragma unroll
    for (int j = 0; j < 4; j++)
      #pragma unroll
      for (int r = 0; r < 4; r++) acc[i][j][r] = 0.f;

  int ar  = tid >> 1;            // 0..127
  int ac4 = (tid & 1) * 16;      // 0 / 16
  int bkr = tid >> 3;            // 0..31
  int bc4 = (tid & 7) * 16;      // 0..112
  bool arow_ok = (bm + ar) < M;

  for (int k0 = 0; k0 < K; k0 += 32) {
    const float* Ap = A + (size_t)(bm + ar) * lda + k0 + ac4;
    #pragma unroll
    for (int i = 0; i < 4; i++) {
      float4 v = arow_ok ? *(const float4*)(Ap + i*4) : make_float4(0.f,0.f,0.f,0.f);
      As[ar][ac4 + i*4 + 0] = f2tf(v.x);
      As[ar][ac4 + i*4 + 1] = f2tf(v.y);
      As[ar][ac4 + i*4 + 2] = f2tf(v.z);
      As[ar][ac4 + i*4 + 3] = f2tf(v.w);
    }
    const float* Bp = B + (size_t)(k0 + bkr) * ldb + bn + bc4;
    #pragma unroll
    for (int i = 0; i < 4; i++) {
      float4 v = *(const float4*)(Bp + i*4);
      Bs[bkr][bc4 + i*4 + 0] = f2tf(v.x);
      Bs[bkr][bc4 + i*4 + 1] = f2tf(v.y);
      Bs[bkr][bc4 + i*4 + 2] = f2tf(v.z);
      Bs[bkr][bc4 + i*4 + 3] = f2tf(v.w);
    }
    __syncthreads();

    #pragma unroll
    for (int ks = 0; ks < 4; ks++) {
      uint32_t af[4][4], bf[4][2];
      #pragma unroll
      for (int i = 0; i < 4; i++) {
        int m0 = wm0 + i*16;
        af[i][0] = As[m0 + g    ][ks*8 + c    ];
        af[i][1] = As[m0 + g + 8][ks*8 + c    ];
        af[i][2] = As[m0 + g    ][ks*8 + c + 4];
        af[i][3] = As[m0 + g + 8][ks*8 + c + 4];
      }
      #pragma unroll
      for (int j = 0; j < 4; j++) {
        bf[j][0] = Bs[ks*8 + c    ][wn0 + j*8 + g];
        bf[j][1] = Bs[ks*8 + c + 4][wn0 + j*8 + g];
      }
      #pragma unroll
      for (int i = 0; i < 4; i++)
        #pragma unroll
        for (int j = 0; j < 4; j++)
          asm volatile(
            "mma.sync.aligned.m16n8k8.row.col.f32.tf32.tf32.f32 "
            "{%0,%1,%2,%3},{%4,%5,%6,%7},{%8,%9},{%0,%1,%2,%3};"
            : "+f"(acc[i][j][0]), "+f"(acc[i][j][1]),
              "+f"(acc[i][j][2]), "+f"(acc[i][j][3])
            : "r"(af[i][0]), "r"(af[i][1]), "r"(af[i][2]), "r"(af[i][3]),
              "r"(bf[j][0]), "r"(bf[j][1]));
    }
    __syncthreads();
  }

  #pragma unroll
  for (int j = 0; j < 4; j++) {
    int col = bn + wn0 + j*8 + 2*c;
    float b0 = bias ? bias[col]     : 0.f;
    float b1 = bias ? bias[col + 1] : 0.f;
    #pragma unroll
    for (int i = 0; i < 4; i++) {
      int r0 = bm + wm0 + i*16 + g;
      if (r0 < M) {
        float2 v = make_float2(acc[i][j][0] + b0, acc[i][j][1] + b1);
        *(float2*)(C + (size_t)r0 * ldc + col) = v;
      }
      int r1 = r0 + 8;
      if (r1 < M) {
        float2 v = make_float2(acc[i][j][2] + b0, acc[i][j][3] + b1);
        *(float2*)(C + (size_t)r1 * ldc + col) = v;
      }
    }
  }
}

// ---------------------------------------------------------------------------
// Qr = Q + r_r_bias (broadcast over rows)
// ---------------------------------------------------------------------------
__global__ void qr_prep(const float* __restrict__ rrb) {
  int idx = blockIdx.x * 256 + threadIdx.x;
  if (idx >= NB*LQ*EMB) return;
  int e = idx % EMB;
  g_Qr[idx] = g_Q[idx] + rrb[e];
}

// ---------------------------------------------------------------------------
// RT[e][j] = R[j][e] (transpose, pad j=1023 with 0)
// ---------------------------------------------------------------------------
__global__ void rt_kernel() {
  __shared__ float t[32][33];
  int e0 = blockIdx.x * 32, j0 = blockIdx.y * 32;
  int tx = threadIdx.x, ty = threadIdx.y;
  #pragma unroll
  for (int i = 0; i < 4; i++) {
    int j = j0 + ty + i*8;
    t[ty + i*8][tx] = (j < NPOS) ? g_R[(size_t)j * EMB + e0 + tx] : 0.f;
  }
  __syncthreads();
  #pragma unroll
  for (int i = 0; i < 4; i++) {
    g_RT[(size_t)(e0 + ty + i*8) * JPAD + j0 + tx] = t[tx][ty + i*8];
  }
}

// ---------------------------------------------------------------------------
// Gather: BD[n][h][q][k] = T[h][n*L+q][q-k+511]
// ---------------------------------------------------------------------------
__global__ void gather_bd() {
  size_t idx = (size_t)blockIdx.x * 256 + threadIdx.x;
  if (idx >= (size_t)NB*NH*LQ*(LQ/4)) return;
  int k4 = (int)(idx & 127);
  int q  = (int)((idx >> 7) & 511);
  int nh = (int)(idx >> 16);
  int h = nh % NH, n = nh / NH;
  const float* Tr = g_T + ((size_t)h * (NB*LQ) + (size_t)n*LQ + q) * JPAD;
  int j0 = q + 511 - k4*4;
  float4 v = make_float4(Tr[j0], Tr[j0-1], Tr[j0-2], Tr[j0-3]);
  *(float4*)(g_BD + ((size_t)nh * LQ + q) * LQ + k4*4) = v;
}

// ---------------------------------------------------------------------------
// Fused attention: s initialized from precomputed BD, ac added per tile,
// online softmax + PV in registers.
// ---------------------------------------------------------------------------
__global__ __launch_bounds__(128) void attn_kernel(const float* __restrict__ rwb)
{
  extern __shared__ float smem[];
  float* Qs   = smem;                     // QT * 65
  float* Ks   = Qs + QT*QS_STRIDE;        // KT * 64
  float* Vs   = Ks + KT*DH;               // KT * 64
  float* Ps   = Vs + KT*DH;               // QT * 65
  float* rwbs = Ps + QT*QS_STRIDE;        // 64

  int b = blockIdx.x;
  int qt = b & 3; b >>= 2;
  int h = b % NH;
  int n = b / NH;
  int q0 = qt * QT;
  int tid = threadIdx.x;

  const float* Qg = g_Q + ((size_t)n*LQ + q0)*EMB + h*DH;
  for (int u = tid; u < QT*16; u += 128) {
    int r = u >> 4, c4 = (u & 15) << 2;
    float4 v = *(const float4*)(Qg + (size_t)r*EMB + c4);
    Qs[r*QS_STRIDE + c4+0] = v.x;
    Qs[r*QS_STRIDE + c4+1] = v.y;
    Qs[r*QS_STRIDE + c4+2] = v.z;
    Qs[r*QS_STRIDE + c4+3] = v.w;
  }
  if (tid < DH) rwbs[tid] = rwb[h*DH + tid];
  __syncthreads();

  int qi = tid;
  float m = -1e30f, l = 0.f;
  float acc[DH];
  #pragma unroll
  for (int d = 0; d < DH; d++) acc[d] = 0.f;

  const float* bdrow = g_BD + ((size_t)(n*NH + h)*LQ + q0 + qi)*LQ;

  for (int k0 = 0; k0 < LQ; k0 += KT) {
    const float* Kg = g_K + ((size_t)n*LQ + k0)*EMB + h*DH;
    const float* Vg = g_V + ((size_t)n*LQ + k0)*EMB + h*DH;
    for (int u = tid; u < KT*16; u += 128) {
      int r = u >> 4, c4 = (u & 15) << 2;
      *(float4*)(Ks + r*DH + c4) = *(const float4*)(Kg + (size_t)r*EMB + c4);
      *(float4*)(Vs + r*DH + c4) = *(const float4*)(Vg + (size_t)r*EMB + c4);
    }
    __syncthreads();

    // s initialized from BD (coalesced global float4 loads)
    float s[KT];
    #pragma unroll
    for (int c4 = 0; c4 < 16; c4++) {
      float4 v = *(const float4*)(bdrow + k0 + c4*4);
      s[c4*4+0] = v.x; s[c4*4+1] = v.y; s[c4*4+2] = v.z; s[c4*4+3] = v.w;
    }

    // ac: (Q + r_w_bias) . K
    #pragma unroll 1
    for (int dc = 0; dc < 16; dc++) {
      float a0 = Qs[qi*QS_STRIDE + dc*4+0] + rwbs[dc*4+0];
      float a1 = Qs[qi*QS_STRIDE + dc*4+1] + rwbs[dc*4+1];
      float a2 = Qs[qi*QS_STRIDE + dc*4+2] + rwbs[dc*4+2];
      float a3 = Qs[qi*QS_STRIDE + dc*4+3] + rwbs[dc*4+3];
      #pragma unroll
      for (int ki = 0; ki < KT; ki++) {
        float4 kk = *(const float4*)(Ks + ki*DH + dc*4);
        s[ki] = fmaf(a0, kk.x, s[ki]);
        s[ki] = fmaf(a1, kk.y, s[ki]);
        s[ki] = fmaf(a2, kk.z, s[ki]);
        s[ki] = fmaf(a3, kk.w, s[ki]);
      }
    }

    // online softmax
    float mnew = m;
    #pragma unroll
    for (int ki = 0; ki < KT; ki++) { s[ki] *= 0.125f; mnew = fmaxf(mnew, s[ki]); }
    float corr = __expf(m - mnew);
    m = mnew;
    l *= corr;
    #pragma unroll
    for (int d = 0; d < DH; d++) acc[d] *= corr;
    float lsum = 0.f;
    #pragma unroll
    for (int ki = 0; ki < KT; ki++) {
      float p = __expf(s[ki] - mnew);
      lsum += p;
      Ps[qi*QS_STRIDE + ki] = p;
    }
    l += lsum;

    // PV accumulate
    #pragma unroll 1
    for (int ki = 0; ki < KT; ki++) {
      float p = Ps[qi*QS_STRIDE + ki];
      const float4* vrow = (const float4*)(Vs + ki*DH);
      #pragma unroll
      for (int dc = 0; dc < 16; dc++) {
        float4 vv = vrow[dc];
        acc[dc*4+0] = fmaf(p, vv.x, acc[dc*4+0]);
        acc[dc*4+1] = fmaf(p, vv.y, acc[dc*4+1]);
        acc[dc*4+2] = fmaf(p, vv.z, acc[dc*4+2]);
        acc[dc*4+3] = fmaf(p, vv.w, acc[dc*4+3]);
      }
    }
    __syncthreads();
  }

  float inv = 1.f / l;
  float* og = g_AO + ((size_t)n*LQ + q0 + qi)*EMB + h*DH;
  #pragma unroll
  for (int dc = 0; dc < 16; dc++) {
    float4 o = make_float4(acc[dc*4+0]*inv, acc[dc*4+1]*inv,
                           acc[dc*4+2]*inv, acc[dc*4+3]*inv);
    *(float4*)(og + dc*4) = o;
  }
}

// ---------------------------------------------------------------------------
extern "C" void kernel_launch(void* const* d_in, const int* in_sizes, int n_in,
                              void* d_out, int out_size) {
  (void)in_sizes; (void)n_in; (void)out_size;
  const float* values = (const float*)d_in[0];
  const float* keys   = (const float*)d_in[1];
  const float* query  = (const float*)d_in[2];
  const float* Wq   = (const float*)d_in[3];
  const float* bq   = (const float*)d_in[4];
  const float* Wk   = (const float*)d_in[5];
  const float* bk   = (const float*)d_in[6];
  const float* Wv   = (const float*)d_in[7];
  const float* bv   = (const float*)d_in[8];
  const float* Wo   = (const float*)d_in[9];
  const float* bo   = (const float*)d_in[10];
  const float* Wpos = (const float*)d_in[11];
  const float* bpos = (const float*)d_in[12];
  const float* rwb  = (const float*)d_in[13];
  const float* rrb  = (const float*)d_in[14];
  float* out = (float*)d_out;

  float *pe_p, *R_p, *RT_p, *Q_p, *Qr_p, *K_p, *V_p, *T_p, *AO_p;
  cudaGetSymbolAddress((void**)&pe_p, g_pe);
  cudaGetSymbolAddress((void**)&R_p,  g_R);
  cudaGetSymbolAddress((void**)&RT_p, g_RT);
  cudaGetSymbolAddress((void**)&Q_p,  g_Q);
  cudaGetSymbolAddress((void**)&Qr_p, g_Qr);
  cudaGetSymbolAddress((void**)&K_p,  g_K);
  cudaGetSymbolAddress((void**)&V_p,  g_V);
  cudaGetSymbolAddress((void**)&T_p,  g_T);
  cudaGetSymbolAddress((void**)&AO_p, g_AO);

  int smem_bytes = (QT*QS_STRIDE + KT*DH + KT*DH + QT*QS_STRIDE + DH)
                   * (int)sizeof(float);
  cudaFuncSetAttribute(attn_kernel, cudaFuncAttributeMaxDynamicSharedMemorySize,
                       smem_bytes);

  // 1) sinusoid table
  pe_kernel<<<(NPOS*EMB + 255)/256, 256>>>();
  // 2) R = pe @ Wpos + bpos (1023 x 768)
  gemm_tf32<<<dim3(6, 8), 256>>>(pe_p, Wpos, bpos, R_p, NPOS, EMB, EMB,
                                 EMB, EMB, EMB);
  // 3) projections
  gemm_tf32<<<dim3(6, 32), 256>>>(query,  Wq, bq, Q_p, NB*LQ, EMB, EMB,
                                  EMB, EMB, EMB);
  gemm_tf32<<<dim3(6, 32), 256>>>(keys,   Wk, bk, K_p, NB*LQ, EMB, EMB,
                                  EMB, EMB, EMB);
  gemm_tf32<<<dim3(6, 32), 256>>>(values, Wv, bv, V_p, NB*LQ, EMB, EMB,
                                  EMB, EMB, EMB);
  // 4) Qr = Q + rrb ; RT = R^T (padded)
  qr_prep<<<(NB*LQ*EMB + 255)/256, 256>>>(rrb);
  rt_kernel<<<dim3(EMB/32, JPAD/32), dim3(32, 8)>>>();
  // 5) T_h = Qr_h @ RT_h  (per-head batched, N=1024 padded, no bias)
  for (int h = 0; h < NH; h++) {
    gemm_tf32<<<dim3(JPAD/128, 32), 256>>>(
        Qr_p + h*DH, RT_p + (size_t)h*DH*JPAD, nullptr,
        T_p + (size_t)h*(NB*LQ)*JPAD,
        NB*LQ, DH, JPAD, EMB, JPAD, JPAD);
  }
  // 6) gather BD[n,h,q,k] = T[h][n*L+q][q-k+511]
  gather_bd<<<(int)(((size_t)NB*NH*LQ*(LQ/4) + 255)/256), 256>>>();
  // 7) fused attention
  attn_kernel<<<NB*NH*(LQ/QT), 128, smem_bytes>>>(rwb);
  // 8) output projection
  gemm_tf32<<<dim3(6, 32), 256>>>(AO_p, Wo, bo, out, NB*LQ, EMB, EMB,
                                  EMB, EMB, EMB);
}

// round 3
// speedup vs baseline: 1.7240x; 1.2072x over previous
#include <cuda_runtime.h>
#include <math.h>
#include <stdint.h>
#include <stddef.h>

#define NB   8
#define LQ   512
#define EMB  768
#define NH   12
#define DH   64
#define NPOS 1023   // 2*MAXLEN-1
#define JPAD 1024   // padded j dimension for RT / BD gemm

#define QT 128      // q rows per attention block
#define KT 64       // k cols per tile
#define QS_STRIDE 65

// ---------------- scratch (__device__ globals: allocation-free rule) --------
__device__ __align__(16) float g_pe[NPOS*EMB];
__device__ __align__(16) float g_R [NPOS*EMB];
__device__ __align__(16) float g_RT[EMB*JPAD];            // RT[e][j] = R[j][e]
__device__ __align__(16) float g_Q [NB*LQ*EMB];
__device__ __align__(16) float g_K [NB*LQ*EMB];
__device__ __align__(16) float g_V [NB*LQ*EMB];
__device__ __align__(16) float g_BD[(size_t)NB*NH*LQ*LQ]; // bd[n][h][q][k]
__device__ __align__(16) float g_AO[NB*LQ*EMB];

// ---------------------------------------------------------------------------
__global__ void pe_kernel() {
  int idx = blockIdx.x * 256 + threadIdx.x;
  if (idx >= NPOS*EMB) return;
  int p = idx / EMB;
  int e = idx - p * EMB;
  int i2 = e & ~1;
  float div = expf(-(float)i2 * (9.210340371976184f / (float)EMB));
  float ang = (float)p * div;
  g_pe[idx] = (e & 1) ? cosf(ang) : sinf(ang);
}

// ---------------------------------------------------------------------------
// RT[e][j] = R[j][e] (transpose, pad j=1023 with 0)
// ---------------------------------------------------------------------------
__global__ void rt_kernel() {
  __shared__ float t[32][33];
  int e0 = blockIdx.x * 32, j0 = blockIdx.y * 32;
  int tx = threadIdx.x, ty = threadIdx.y;
  #pragma unroll
  for (int i = 0; i < 4; i++) {
    int j = j0 + ty + i*8;
    t[ty + i*8][tx] = (j < NPOS) ? g_R[(size_t)j * EMB + e0 + tx] : 0.f;
  }
  __syncthreads();
  #pragma unroll
  for (int i = 0; i < 4; i++) {
    g_RT[(size_t)(e0 + ty + i*8) * JPAD + j0 + tx] = t[tx][ty + i*8];
  }
}

// ---------------------------------------------------------------------------
// TF32 tensor-core GEMM, double-buffered.
// MODE 0: C[M,N] = A@B + bias (row guards on M).
// MODE 1: BD scatter epilogue. A = Q (+rrb added at staging, per-head offset),
//         B = RT (per-head offset), C unused; writes g_BD[n,h,q,k], k=q+511-j.
// 256 threads = 8 warps (2x4), warp tile 64x32, mma m16n8k8, K%32==0.
// ---------------------------------------------------------------------------
__device__ __forceinline__ uint32_t f2tf(float f) {
  uint32_t u; asm("cvt.rna.tf32.f32 %0, %1;" : "=r"(u) : "f"(f)); return u;
}

#define AS_ELEMS (128*36)
#define BS_ELEMS (32*136)

template<int MODE>
__global__ __launch_bounds__(256, 2) void gemm_core(
    const float* __restrict__ A, const float* __restrict__ B,
    const float* __restrict__ bias, float* __restrict__ C,
    int M, int K, int N, int lda, int ldb, int ldc)
{
  extern __shared__ uint32_t sm[];
  uint32_t* Asm = sm;                    // [2][128][36]
  uint32_t* Bsm = sm + 2*AS_ELEMS;       // [2][32][136]

  int tid  = threadIdx.x;
  int lane = tid & 31;
  int wid  = tid >> 5;
  int g = lane >> 2, c = lane & 3;
  int wm0 = (wid >> 2) * 64, wn0 = (wid & 3) * 32;
  int bm = blockIdx.y * 128, bn = blockIdx.x * 128;

  if (MODE == 1) {
    int h = blockIdx.z;
    A += h * DH;
    B += (size_t)h * DH * ldb;
    bias += h * DH;  // rrb slice
    int q0 = bm & (LQ - 1);
    if (bn > q0 + 638 || bn + 127 < q0) return;
  }

  int ar  = tid >> 1;            // 0..127
  int ac4 = (tid & 1) * 16;      // 0 / 16
  int bkr = tid >> 3;            // 0..31
  int bc4 = (tid & 7) * 16;      // 0..112
  bool arow_ok = (MODE == 1) || (bm + ar < M);

  float acc[4][4][4];
  #pragma unroll
  for (int i = 0; i < 4; i++)
    #pragma unroll
    for (int j = 0; j < 4; j++)
      #pragma unroll
      for (int r = 0; r < 4; r++) acc[i][j][r] = 0.f;

  float areg[16], breg[16];

  auto ldg_step = [&](int k0) {
    const float* Ap = A + (size_t)(bm + ar) * lda + k0 + ac4;
    #pragma unroll
    for (int i = 0; i < 4; i++) {
      float4 v = arow_ok ? *(const float4*)(Ap + i*4) : make_float4(0.f,0.f,0.f,0.f);
      areg[i*4+0] = v.x; areg[i*4+1] = v.y; areg[i*4+2] = v.z; areg[i*4+3] = v.w;
    }
    if (MODE == 1) {
      #pragma unroll
      for (int e = 0; e < 16; e++) areg[e] += __ldg(bias + k0 + ac4 + e);
    }
    const float* Bp = B + (size_t)(k0 + bkr) * ldb + bn + bc4;
    #pragma unroll
    for (int i = 0; i < 4; i++) {
      float4 v = *(const float4*)(Bp + i*4);
      breg[i*4+0] = v.x; breg[i*4+1] = v.y; breg[i*4+2] = v.z; breg[i*4+3] = v.w;
    }
  };

  auto sts_step = [&](int buf) {
    uint32_t* Ab = Asm + buf*AS_ELEMS + ar*36 + ac4;
    #pragma unroll
    for (int i = 0; i < 4; i++) {
      uint4 u = make_uint4(f2tf(areg[i*4+0]), f2tf(areg[i*4+1]),
                           f2tf(areg[i*4+2]), f2tf(areg[i*4+3]));
      *(uint4*)(Ab + i*4) = u;
    }
    uint32_t* Bb = Bsm + buf*BS_ELEMS + bkr*136 + bc4;
    #pragma unroll
    for (int i = 0; i < 4; i++) {
      uint4 u = make_uint4(f2tf(breg[i*4+0]), f2tf(breg[i*4+1]),
                           f2tf(breg[i*4+2]), f2tf(breg[i*4+3]));
      *(uint4*)(Bb + i*4) = u;
    }
  };

  int nsteps = K >> 5;
  ldg_step(0);
  sts_step(0);
  __syncthreads();

  for (int s = 0; s < nsteps; s++) {
    int buf = s & 1;
    if (s + 1 < nsteps) ldg_step((s + 1) << 5);

    const uint32_t* Ab = Asm + buf*AS_ELEMS;
    const uint32_t* Bb = Bsm + buf*BS_ELEMS;
    #pragma unroll
    for (int ks = 0; ks < 4; ks++) {
      uint32_t af[4][4], bf[4][2];
      #pragma unroll
      for (int i = 0; i < 4; i++) {
        int m0 = wm0 + i*16;
        af[i][0] = Ab[(m0 + g    )*36 + ks*8 + c    ];
        af[i][1] = Ab[(m0 + g + 8)*36 + ks*8 + c    ];
        af[i][2] = Ab[(m0 + g    )*36 + ks*8 + c + 4];
        af[i][3] = Ab[(m0 + g + 8)*36 + ks*8 + c + 4];
      }
      #pragma unroll
      for (int j = 0; j < 4; j++) {
        bf[j][0] = Bb[(ks*8 + c    )*136 + wn0 + j*8 + g];
        bf[j][1] = Bb[(ks*8 + c + 4)*136 + wn0 + j*8 + g];
      }
      #pragma unroll
      for (int i = 0; i < 4; i++)
        #pragma unroll
        for (int j = 0; j < 4; j++)
          asm volatile(
            "mma.sync.aligned.m16n8k8.row.col.f32.tf32.tf32.f32 "
            "{%0,%1,%2,%3},{%4,%5,%6,%7},{%8,%9},{%0,%1,%2,%3};"
            : "+f"(acc[i][j][0]), "+f"(acc[i][j][1]),
              "+f"(acc[i][j][2]), "+f"(acc[i][j][3])
            : "r"(af[i][0]), "r"(af[i][1]), "r"(af[i][2]), "r"(af[i][3]),
              "r"(bf[j][0]), "r"(bf[j][1]));
    }

    if (s + 1 < nsteps) sts_step(buf ^ 1);
    __syncthreads();
  }

  if (MODE == 0) {
    #pragma unroll
    for (int j = 0; j < 4; j++) {
      int col = bn + wn0 + j*8 + 2*c;
      float b0 = bias ? bias[col]     : 0.f;
      float b1 = bias ? bias[col + 1] : 0.f;
      #pragma unroll
      for (int i = 0; i < 4; i++) {
        int r0 = bm + wm0 + i*16 + g;
        if (r0 < M) {
          float2 v = make_float2(acc[i][j][0] + b0, acc[i][j][1] + b1);
          *(float2*)(C + (size_t)r0 * ldc + col) = v;
        }
        int r1 = r0 + 8;
        if (r1 < M) {
          float2 v = make_float2(acc[i][j][2] + b0, acc[i][j][3] + b1);
          *(float2*)(C + (size_t)r1 * ldc + col) = v;
        }
      }
    }
  } else {
    int h = blockIdx.z;
    #pragma unroll
    for (int j = 0; j < 4; j++) {
      int col = bn + wn0 + j*8 + 2*c;
      #pragma unroll
      for (int i = 0; i < 4; i++) {
        #pragma unroll
        for (int rr = 0; rr < 2; rr++) {
          int r = bm + wm0 + i*16 + g + rr*8;
          int n = r >> 9, q = r & (LQ - 1);
          float* rowp = g_BD + (((size_t)(n*NH + h) * LQ) + q) * LQ;
          int k0c = q + 511 - col;
          if (k0c >= 0 && k0c < LQ)         rowp[k0c]     = acc[i][j][rr*2+0];
          if (k0c - 1 >= 0 && k0c - 1 < LQ) rowp[k0c - 1] = acc[i][j][rr*2+1];
        }
      }
    }
  }
}

// ---------------------------------------------------------------------------
// Fused attention: s initialized from precomputed BD, ac added per tile,
// online softmax + PV in registers.
// ---------------------------------------------------------------------------
__global__ __launch_bounds__(128) void attn_kernel(const float* __restrict__ rwb)
{
  extern __shared__ float smem[];
  float* Qs   = smem;                     // QT * 65
  float* Ks   = Qs + QT*QS_STRIDE;        // KT * 64
  float* Vs   = Ks + KT*DH;               // KT * 64
  float* Ps   = Vs + KT*DH;               // QT * 65
  float* rwbs = Ps + QT*QS_STRIDE;        // 64

  int b = blockIdx.x;
  int qt = b & 3; b >>= 2;
  int h = b % NH;
  int n = b / NH;
  int q0 = qt * QT;
  int tid = threadIdx.x;

  const float* Qg = g_Q + ((size_t)n*LQ + q0)*EMB + h*DH;
  for (int u = tid; u < QT*16; u += 128) {
    int r = u >> 4, c4 = (u & 15) << 2;
    float4 v = *(const float4*)(Qg + (size_t)r*EMB + c4);
    Qs[r*QS_STRIDE + c4+0] = v.x;
    Qs[r*QS_STRIDE + c4+1] = v.y;
    Qs[r*QS_STRIDE + c4+2] = v.z;
    Qs[r*QS_STRIDE + c4+3] = v.w;
  }
  if (tid < DH) rwbs[tid] = rwb[h*DH + tid];
  __syncthreads();

  int qi = tid;
  float m = -1e30f, l = 0.f;
  float acc[DH];
  #pragma unroll
  for (int d = 0; d < DH; d++) acc[d] = 0.f;

  const float* bdrow = g_BD + ((size_t)(n*NH + h)*LQ + q0 + qi)*LQ;

  for (int k0 = 0; k0 < LQ; k0 += KT) {
    const float* Kg = g_K + ((size_t)n*LQ + k0)*EMB + h*DH;
    const float* Vg = g_V + ((size_t)n*LQ + k0)*EMB + h*DH;
    for (int u = tid; u < KT*16; u += 128) {
      int r = u >> 4, c4 = (u & 15) << 2;
      *(float4*)(Ks + r*DH + c4) = *(const float4*)(Kg + (size_t)r*EMB + c4);
      *(float4*)(Vs + r*DH + c4) = *(const float4*)(Vg + (size_t)r*EMB + c4);
    }
    __syncthreads();

    float s[KT];
    #pragma unroll
    for (int c4 = 0; c4 < 16; c4++) {
      float4 v = *(const float4*)(bdrow + k0 + c4*4);
      s[c4*4+0] = v.x; s[c4*4+1] = v.y; s[c4*4+2] = v.z; s[c4*4+3] = v.w;
    }

    #pragma unroll 1
    for (int dc = 0; dc < 16; dc++) {
      float a0 = Qs[qi*QS_STRIDE + dc*4+0] + rwbs[dc*4+0];
      float a1 = Qs[qi*QS_STRIDE + dc*4+1] + rwbs[dc*4+1];
      float a2 = Qs[qi*QS_STRIDE + dc*4+2] + rwbs[dc*4+2];
      float a3 = Qs[qi*QS_STRIDE + dc*4+3] + rwbs[dc*4+3];
      #pragma unroll
      for (int ki = 0; ki < KT; ki++) {
        float4 kk = *(const float4*)(Ks + ki*DH + dc*4);
        s[ki] = fmaf(a0, kk.x, s[ki]);
        s[ki] = fmaf(a1, kk.y, s[ki]);
        s[ki] = fmaf(a2, kk.z, s[ki]);
        s[ki] = fmaf(a3, kk.w, s[ki]);
      }
    }

    float mnew = m;
    #pragma unroll
    for (int ki = 0; ki < KT; ki++) { s[ki] *= 0.125f; mnew = fmaxf(mnew, s[ki]); }
    float corr = __expf(m - mnew);
    m = mnew;
    l *= corr;
    #pragma unroll
    for (int d = 0; d < DH; d++) acc[d] *= corr;
    float lsum = 0.f;
    #pragma unroll
    for (int ki = 0; ki < KT; ki++) {
      float p = __expf(s[ki] - mnew);
      lsum += p;
      Ps[qi*QS_STRIDE + ki] = p;
    }
    l += lsum;

    #pragma unroll 1
    for (int ki = 0; ki < KT; ki++) {
      float p = Ps[qi*QS_STRIDE + ki];
      const float4* vrow = (const float4*)(Vs + ki*DH);
      #pragma unroll
      for (int dc = 0; dc < 16; dc++) {
        float4 vv = vrow[dc];
        acc[dc*4+0] = fmaf(p, vv.x, acc[dc*4+0]);
        acc[dc*4+1] = fmaf(p, vv.y, acc[dc*4+1]);
        acc[dc*4+2] = fmaf(p, vv.z, acc[dc*4+2]);
        acc[dc*4+3] = fmaf(p, vv.w, acc[dc*4+3]);
      }
    }
    __syncthreads();
  }

  float inv = 1.f / l;
  float* og = g_AO + ((size_t)n*LQ + q0 + qi)*EMB + h*DH;
  #pragma unroll
  for (int dc = 0; dc < 16; dc++) {
    float4 o = make_float4(acc[dc*4+0]*inv, acc[dc*4+1]*inv,
                           acc[dc*4+2]*inv, acc[dc*4+3]*inv);
    *(float4*)(og + dc*4) = o;
  }
}

// ---------------------------------------------------------------------------
extern "C" void kernel_launch(void* const* d_in, const int* in_sizes, int n_in,
                              void* d_out, int out_size) {
  (void)in_sizes; (void)n_in; (void)out_size;
  const float* values = (const float*)d_in[0];
  const float* keys   = (const float*)d_in[1];
  const float* query  = (const float*)d_in[2];
  const float* Wq   = (const float*)d_in[3];
  const float* bq   = (const float*)d_in[4];
  const float* Wk   = (const float*)d_in[5];
  const float* bk   = (const float*)d_in[6];
  const float* Wv   = (const float*)d_in[7];
  const float* bv   = (const float*)d_in[8];
  const float* Wo   = (const float*)d_in[9];
  const float* bo   = (const float*)d_in[10];
  const float* Wpos = (const float*)d_in[11];
  const float* bpos = (const float*)d_in[12];
  const float* rwb  = (const float*)d_in[13];
  const float* rrb  = (const float*)d_in[14];
  float* out = (float*)d_out;

  float *pe_p, *R_p, *RT_p, *Q_p, *K_p, *V_p, *AO_p;
  cudaGetSymbolAddress((void**)&pe_p, g_pe);
  cudaGetSymbolAddress((void**)&R_p,  g_R);
  cudaGetSymbolAddress((void**)&RT_p, g_RT);
  cudaGetSymbolAddress((void**)&Q_p,  g_Q);
  cudaGetSymbolAddress((void**)&K_p,  g_K);
  cudaGetSymbolAddress((void**)&V_p,  g_V);
  cudaGetSymbolAddress((void**)&AO_p, g_AO);

  int gemm_smem = (2*AS_ELEMS + 2*BS_ELEMS) * (int)sizeof(uint32_t);
  cudaFuncSetAttribute(gemm_core<0>, cudaFuncAttributeMaxDynamicSharedMemorySize,
                       gemm_smem);
  cudaFuncSetAttribute(gemm_core<1>, cudaFuncAttributeMaxDynamicSharedMemorySize,
                       gemm_smem);

  int attn_smem = (QT*QS_STRIDE + KT*DH + KT*DH + QT*QS_STRIDE + DH)
                  * (int)sizeof(float);
  cudaFuncSetAttribute(attn_kernel, cudaFuncAttributeMaxDynamicSharedMemorySize,
                       attn_smem);

  // 1) sinusoid table
  pe_kernel<<<(NPOS*EMB + 255)/256, 256>>>();
  // 2) R = pe @ Wpos + bpos (1023 x 768)
  gemm_core<0><<<dim3(6, 8), 256, gemm_smem>>>(
      pe_p, Wpos, bpos, R_p, NPOS, EMB, EMB, EMB, EMB, EMB);
  // 3) projections (4096 x 768)
  gemm_core<0><<<dim3(6, 32), 256, gemm_smem>>>(
      query,  Wq, bq, Q_p, NB*LQ, EMB, EMB, EMB, EMB, EMB);
  gemm_core<0><<<dim3(6, 32), 256, gemm_smem>>>(
      keys,   Wk, bk, K_p, NB*LQ, EMB, EMB, EMB, EMB, EMB);
  gemm_core<0><<<dim3(6, 32), 256, gemm_smem>>>(
      values, Wv, bv, V_p, NB*LQ, EMB, EMB, EMB, EMB, EMB);
  // 4) RT = R^T (padded)
  rt_kernel<<<dim3(EMB/32, JPAD/32), dim3(32, 8)>>>();
  // 5) BD gemm: one batched launch over heads, direct scatter epilogue
  gemm_core<1><<<dim3(JPAD/128, 32, NH), 256, gemm_smem>>>(
      Q_p, RT_p, rrb, nullptr, NB*LQ, DH, JPAD, EMB, JPAD, 0);
  // 6) fused attention
  attn_kernel<<<NB*NH*(LQ/QT), 128, attn_smem>>>(rwb);
  // 7) output projection
  gemm_core<0><<<dim3(6, 32), 256, gemm_smem>>>(
      AO_p, Wo, bo, out, NB*LQ, EMB, EMB, EMB, EMB, EMB);
}

// round 4
// speedup vs baseline: 2.3094x; 1.3395x over previous
#include <cuda_runtime.h>
#include <cuda_fp16.h>
#include <math.h>
#include <stdint.h>
#include <stddef.h>

#define NB   8
#define LQ   512
#define EMB  768
#define NH   12
#define DH   64
#define NPOS 1023   // 2*MAXLEN-1
#define JPAD 1024   // padded j dimension for RT / BD gemm

// ---------------- scratch (__device__ globals: allocation-free rule) --------
__device__ __align__(16) float g_pe[NPOS*EMB];
__device__ __align__(16) float g_R [NPOS*EMB];
__device__ __align__(16) float g_RT[EMB*JPAD];            // RT[e][j] = R[j][e]
__device__ __align__(16) float g_Q [NB*LQ*EMB];
__device__ __align__(16) float g_K [NB*LQ*EMB];
__device__ __align__(16) float g_V [NB*LQ*EMB];
__device__ __align__(16) float g_BD[(size_t)NB*NH*LQ*LQ]; // bd[n][h][q][k]
__device__ __align__(16) float g_AO[NB*LQ*EMB];

// ---------------------------------------------------------------------------
__global__ void pe_kernel() {
  int idx = blockIdx.x * 256 + threadIdx.x;
  if (idx >= NPOS*EMB) return;
  int p = idx / EMB;
  int e = idx - p * EMB;
  int i2 = e & ~1;
  float div = expf(-(float)i2 * (9.210340371976184f / (float)EMB));
  float ang = (float)p * div;
  g_pe[idx] = (e & 1) ? cosf(ang) : sinf(ang);
}

// ---------------------------------------------------------------------------
__global__ void rt_kernel() {
  __shared__ float t[32][33];
  int e0 = blockIdx.x * 32, j0 = blockIdx.y * 32;
  int tx = threadIdx.x, ty = threadIdx.y;
  #pragma unroll
  for (int i = 0; i < 4; i++) {
    int j = j0 + ty + i*8;
    t[ty + i*8][tx] = (j < NPOS) ? g_R[(size_t)j * EMB + e0 + tx] : 0.f;
  }
  __syncthreads();
  #pragma unroll
  for (int i = 0; i < 4; i++) {
    g_RT[(size_t)(e0 + ty + i*8) * JPAD + j0 + tx] = t[tx][ty + i*8];
  }
}

// ---------------------------------------------------------------------------
// TF32 tensor-core GEMM, double-buffered (unchanged from R3).
// ---------------------------------------------------------------------------
__device__ __forceinline__ uint32_t f2tf(float f) {
  uint32_t u; asm("cvt.rna.tf32.f32 %0, %1;" : "=r"(u) : "f"(f)); return u;
}
__device__ __forceinline__ uint32_t packh2(float lo, float hi) {
  __half2 h = __floats2half2_rn(lo, hi);
  return *(uint32_t*)&h;
}

#define AS_ELEMS (128*36)
#define BS_ELEMS (32*136)

template<int MODE>
__global__ __launch_bounds__(256, 2) void gemm_core(
    const float* __restrict__ A, const float* __restrict__ B,
    const float* __restrict__ bias, float* __restrict__ C,
    int M, int K, int N, int lda, int ldb, int ldc)
{
  extern __shared__ uint32_t sm[];
  uint32_t* Asm = sm;                    // [2][128][36]
  uint32_t* Bsm = sm + 2*AS_ELEMS;       // [2][32][136]

  int tid  = threadIdx.x;
  int lane = tid & 31;
  int wid  = tid >> 5;
  int g = lane >> 2, c = lane & 3;
  int wm0 = (wid >> 2) * 64, wn0 = (wid & 3) * 32;
  int bm = blockIdx.y * 128, bn = blockIdx.x * 128;

  if (MODE == 1) {
    int h = blockIdx.z;
    A += h * DH;
    B += (size_t)h * DH * ldb;
    bias += h * DH;  // rrb slice
    int q0 = bm & (LQ - 1);
    if (bn > q0 + 638 || bn + 127 < q0) return;
  }

  int ar  = tid >> 1;
  int ac4 = (tid & 1) * 16;
  int bkr = tid >> 3;
  int bc4 = (tid & 7) * 16;
  bool arow_ok = (MODE == 1) || (bm + ar < M);

  float acc[4][4][4];
  #pragma unroll
  for (int i = 0; i < 4; i++)
    #pragma unroll
    for (int j = 0; j < 4; j++)
      #pragma unroll
      for (int r = 0; r < 4; r++) acc[i][j][r] = 0.f;

  float areg[16], breg[16];

  auto ldg_step = [&](int k0) {
    const float* Ap = A + (size_t)(bm + ar) * lda + k0 + ac4;
    #pragma unroll
    for (int i = 0; i < 4; i++) {
      float4 v = arow_ok ? *(const float4*)(Ap + i*4) : make_float4(0.f,0.f,0.f,0.f);
      areg[i*4+0] = v.x; areg[i*4+1] = v.y; areg[i*4+2] = v.z; areg[i*4+3] = v.w;
    }
    if (MODE == 1) {
      #pragma unroll
      for (int e = 0; e < 16; e++) areg[e] += __ldg(bias + k0 + ac4 + e);
    }
    const float* Bp = B + (size_t)(k0 + bkr) * ldb + bn + bc4;
    #pragma unroll
    for (int i = 0; i < 4; i++) {
      float4 v = *(const float4*)(Bp + i*4);
      breg[i*4+0] = v.x; breg[i*4+1] = v.y; breg[i*4+2] = v.z; breg[i*4+3] = v.w;
    }
  };

  auto sts_step = [&](int buf) {
    uint32_t* Ab = Asm + buf*AS_ELEMS + ar*36 + ac4;
    #pragma unroll
    for (int i = 0; i < 4; i++) {
      uint4 u = make_uint4(f2tf(areg[i*4+0]), f2tf(areg[i*4+1]),
                           f2tf(areg[i*4+2]), f2tf(areg[i*4+3]));
      *(uint4*)(Ab + i*4) = u;
    }
    uint32_t* Bb = Bsm + buf*BS_ELEMS + bkr*136 + bc4;
    #pragma unroll
    for (int i = 0; i < 4; i++) {
      uint4 u = make_uint4(f2tf(breg[i*4+0]), f2tf(breg[i*4+1]),
                           f2tf(breg[i*4+2]), f2tf(breg[i*4+3]));
      *(uint4*)(Bb + i*4) = u;
    }
  };

  int nsteps = K >> 5;
  ldg_step(0);
  sts_step(0);
  __syncthreads();

  for (int s = 0; s < nsteps; s++) {
    int buf = s & 1;
    if (s + 1 < nsteps) ldg_step((s + 1) << 5);

    const uint32_t* Ab = Asm + buf*AS_ELEMS;
    const uint32_t* Bb = Bsm + buf*BS_ELEMS;
    #pragma unroll
    for (int ks = 0; ks < 4; ks++) {
      uint32_t af[4][4], bf[4][2];
      #pragma unroll
      for (int i = 0; i < 4; i++) {
        int m0 = wm0 + i*16;
        af[i][0] = Ab[(m0 + g    )*36 + ks*8 + c    ];
        af[i][1] = Ab[(m0 + g + 8)*36 + ks*8 + c    ];
        af[i][2] = Ab[(m0 + g    )*36 + ks*8 + c + 4];
        af[i][3] = Ab[(m0 + g + 8)*36 + ks*8 + c + 4];
      }
      #pragma unroll
      for (int j = 0; j < 4; j++) {
        bf[j][0] = Bb[(ks*8 + c    )*136 + wn0 + j*8 + g];
        bf[j][1] = Bb[(ks*8 + c + 4)*136 + wn0 + j*8 + g];
      }
      #pragma unroll
      for (int i = 0; i < 4; i++)
        #pragma unroll
        for (int j = 0; j < 4; j++)
          asm volatile(
            "mma.sync.aligned.m16n8k8.row.col.f32.tf32.tf32.f32 "
            "{%0,%1,%2,%3},{%4,%5,%6,%7},{%8,%9},{%0,%1,%2,%3};"
            : "+f"(acc[i][j][0]), "+f"(acc[i][j][1]),
              "+f"(acc[i][j][2]), "+f"(acc[i][j][3])
            : "r"(af[i][0]), "r"(af[i][1]), "r"(af[i][2]), "r"(af[i][3]),
              "r"(bf[j][0]), "r"(bf[j][1]));
    }

    if (s + 1 < nsteps) sts_step(buf ^ 1);
    __syncthreads();
  }

  if (MODE == 0) {
    #pragma unroll
    for (int j = 0; j < 4; j++) {
      int col = bn + wn0 + j*8 + 2*c;
      float b0 = bias ? bias[col]     : 0.f;
      float b1 = bias ? bias[col + 1] : 0.f;
      #pragma unroll
      for (int i = 0; i < 4; i++) {
        int r0 = bm + wm0 + i*16 + g;
        if (r0 < M) {
          float2 v = make_float2(acc[i][j][0] + b0, acc[i][j][1] + b1);
          *(float2*)(C + (size_t)r0 * ldc + col) = v;
        }
        int r1 = r0 + 8;
        if (r1 < M) {
          float2 v = make_float2(acc[i][j][2] + b0, acc[i][j][3] + b1);
          *(float2*)(C + (size_t)r1 * ldc + col) = v;
        }
      }
    }
  } else {
    int h = blockIdx.z;
    #pragma unroll
    for (int j = 0; j < 4; j++) {
      int col = bn + wn0 + j*8 + 2*c;
      #pragma unroll
      for (int i = 0; i < 4; i++) {
        #pragma unroll
        for (int rr = 0; rr < 2; rr++) {
          int r = bm + wm0 + i*16 + g + rr*8;
          int n = r >> 9, q = r & (LQ - 1);
          float* rowp = g_BD + (((size_t)(n*NH + h) * LQ) + q) * LQ;
          int k0c = q + 511 - col;
          if (k0c >= 0 && k0c < LQ)         rowp[k0c]     = acc[i][j][rr*2+0];
          if (k0c - 1 >= 0 && k0c - 1 < LQ) rowp[k0c - 1] = acc[i][j][rr*2+1];
        }
      }
    }
  }
}

// ---------------------------------------------------------------------------
// Tensor-core fused attention.
// Block = (n, h, 128 q-rows), 256 threads = 8 warps, warp owns m16 q-rows.
// S = BD + (Q+rwb)K^T via tf32 m16n8k8 ; softmax in regs ; P.V via fp16
// m16n8k16 with P packed straight from S accumulators (no smem round trip).
// ---------------------------------------------------------------------------
#define QS_W 68     // stride for Qs/Ks (words)
#define VS_W 72     // stride for Vs (fp16x2 words)
#define ATTN_SMEM ((128*QS_W + 64*QS_W + 32*VS_W) * 4)

__global__ __launch_bounds__(256) void attn_mma(const float* __restrict__ rwb)
{
  extern __shared__ uint32_t sm[];
  uint32_t* Qs = sm;                 // [128][QS_W] tf32 (rwb folded in)
  uint32_t* Ks = Qs + 128*QS_W;      // [64][QS_W] tf32
  uint32_t* Vs = Ks + 64*QS_W;       // [32][VS_W] fp16x2 (k-pairs packed)

  int tid = threadIdx.x, lane = tid & 31, wid = tid >> 5;
  int g = lane >> 2, c = lane & 3;
  int b = blockIdx.x;
  int qt = b & 3; b >>= 2;
  int h = b % NH, n = b / NH;
  int q0 = qt * 128;
  int wm = wid * 16;

  // stage Q tile once, fold rwb, convert tf32
  const float* Qg = g_Q + ((size_t)n*LQ + q0)*EMB + h*DH;
  for (int u = tid; u < 128*16; u += 256) {
    int r = u >> 4, c4 = (u & 15) << 2;
    float4 v = *(const float4*)(Qg + (size_t)r*EMB + c4);
    float4 w = *(const float4*)(rwb + h*DH + c4);
    Qs[r*QS_W + c4+0] = f2tf(v.x + w.x);
    Qs[r*QS_W + c4+1] = f2tf(v.y + w.y);
    Qs[r*QS_W + c4+2] = f2tf(v.z + w.z);
    Qs[r*QS_W + c4+3] = f2tf(v.w + w.w);
  }

  float oacc[8][4];
  #pragma unroll
  for (int j = 0; j < 8; j++)
    #pragma unroll
    for (int r = 0; r < 4; r++) oacc[j][r] = 0.f;
  float m_a = -1e30f, m_b = -1e30f, l_a = 0.f, l_b = 0.f;

  int qa = q0 + wm + g;
  const float* bdra = g_BD + ((size_t)(n*NH + h)*LQ + qa)*LQ;
  const float* bdrb = bdra + 8*LQ;

  for (int k0 = 0; k0 < LQ; k0 += 64) {
    const float* Kg = g_K + ((size_t)n*LQ + k0)*EMB + h*DH;
    const float* Vg = g_V + ((size_t)n*LQ + k0)*EMB + h*DH;
    for (int u = tid; u < 64*16; u += 256) {
      int r = u >> 4, c4 = (u & 15) << 2;
      float4 v = *(const float4*)(Kg + (size_t)r*EMB + c4);
      Ks[r*QS_W + c4+0] = f2tf(v.x);
      Ks[r*QS_W + c4+1] = f2tf(v.y);
      Ks[r*QS_W + c4+2] = f2tf(v.z);
      Ks[r*QS_W + c4+3] = f2tf(v.w);
    }
    for (int u = tid; u < 32*16; u += 256) {
      int kk = u >> 4, c4 = (u & 15) << 2;
      float4 v0 = *(const float4*)(Vg + (size_t)(2*kk  )*EMB + c4);
      float4 v1 = *(const float4*)(Vg + (size_t)(2*kk+1)*EMB + c4);
      Vs[kk*VS_W + c4+0] = packh2(v0.x, v1.x);
      Vs[kk*VS_W + c4+1] = packh2(v0.y, v1.y);
      Vs[kk*VS_W + c4+2] = packh2(v0.z, v1.z);
      Vs[kk*VS_W + c4+3] = packh2(v0.w, v1.w);
    }
    __syncthreads();

    // init S accumulators from BD
    float sacc[8][4];
    #pragma unroll
    for (int j = 0; j < 8; j++) {
      float2 b0 = *(const float2*)(bdra + k0 + j*8 + 2*c);
      float2 b1 = *(const float2*)(bdrb + k0 + j*8 + 2*c);
      sacc[j][0] = b0.x; sacc[j][1] = b0.y;
      sacc[j][2] = b1.x; sacc[j][3] = b1.y;
    }

    // S += (Q+rwb) . K^T
    #pragma unroll
    for (int ks = 0; ks < 8; ks++) {
      uint32_t a0 = Qs[(wm+g  )*QS_W + ks*8 + c  ];
      uint32_t a1 = Qs[(wm+g+8)*QS_W + ks*8 + c  ];
      uint32_t a2 = Qs[(wm+g  )*QS_W + ks*8 + c+4];
      uint32_t a3 = Qs[(wm+g+8)*QS_W + ks*8 + c+4];
      #pragma unroll
      for (int j = 0; j < 8; j++) {
        uint32_t b0 = Ks[(j*8+g)*QS_W + ks*8 + c  ];
        uint32_t b1 = Ks[(j*8+g)*QS_W + ks*8 + c+4];
        asm volatile(
          "mma.sync.aligned.m16n8k8.row.col.f32.tf32.tf32.f32 "
          "{%0,%1,%2,%3},{%4,%5,%6,%7},{%8,%9},{%0,%1,%2,%3};"
          : "+f"(sacc[j][0]), "+f"(sacc[j][1]),
            "+f"(sacc[j][2]), "+f"(sacc[j][3])
          : "r"(a0), "r"(a1), "r"(a2), "r"(a3), "r"(b0), "r"(b1));
      }
    }

    // scale + row max
    float mx_a = -1e30f, mx_b = -1e30f;
    #pragma unroll
    for (int j = 0; j < 8; j++) {
      sacc[j][0] *= 0.125f; sacc[j][1] *= 0.125f;
      sacc[j][2] *= 0.125f; sacc[j][3] *= 0.125f;
      mx_a = fmaxf(mx_a, fmaxf(sacc[j][0], sacc[j][1]));
      mx_b = fmaxf(mx_b, fmaxf(sacc[j][2], sacc[j][3]));
    }
    mx_a = fmaxf(mx_a, __shfl_xor_sync(0xffffffffu, mx_a, 1));
    mx_a = fmaxf(mx_a, __shfl_xor_sync(0xffffffffu, mx_a, 2));
    mx_b = fmaxf(mx_b, __shfl_xor_sync(0xffffffffu, mx_b, 1));
    mx_b = fmaxf(mx_b, __shfl_xor_sync(0xffffffffu, mx_b, 2));
    float mna = fmaxf(m_a, mx_a), mnb = fmaxf(m_b, mx_b);
    float ca = __expf(m_a - mna), cb = __expf(m_b - mnb);
    m_a = mna; m_b = mnb;
    l_a *= ca; l_b *= cb;
    #pragma unroll
    for (int j = 0; j < 8; j++) {
      oacc[j][0] *= ca; oacc[j][1] *= ca;
      oacc[j][2] *= cb; oacc[j][3] *= cb;
    }
    // exp (l reduction deferred to the end; thread-partial sums)
    #pragma unroll
    for (int j = 0; j < 8; j++) {
      sacc[j][0] = __expf(sacc[j][0] - m_a); l_a += sacc[j][0];
      sacc[j][1] = __expf(sacc[j][1] - m_a); l_a += sacc[j][1];
      sacc[j][2] = __expf(sacc[j][2] - m_b); l_b += sacc[j][2];
      sacc[j][3] = __expf(sacc[j][3] - m_b); l_b += sacc[j][3];
    }

    // O += P . V  (P packed straight from S accumulators)
    #pragma unroll
    for (int jj = 0; jj < 4; jj++) {
      uint32_t a0 = packh2(sacc[2*jj  ][0], sacc[2*jj  ][1]);
      uint32_t a1 = packh2(sacc[2*jj  ][2], sacc[2*jj  ][3]);
      uint32_t a2 = packh2(sacc[2*jj+1][0], sacc[2*jj+1][1]);
      uint32_t a3 = packh2(sacc[2*jj+1][2], sacc[2*jj+1][3]);
      #pragma unroll
      for (int jd = 0; jd < 8; jd++) {
        uint32_t b0 = Vs[(jj*8 + c    )*VS_W + jd*8 + g];
        uint32_t b1 = Vs[(jj*8 + c + 4)*VS_W + jd*8 + g];
        asm volatile(
          "mma.sync.aligned.m16n8k16.row.col.f32.f16.f16.f32 "
          "{%0,%1,%2,%3},{%4,%5,%6,%7},{%8,%9},{%0,%1,%2,%3};"
          : "+f"(oacc[jd][0]), "+f"(oacc[jd][1]),
            "+f"(oacc[jd][2]), "+f"(oacc[jd][3])
          : "r"(a0), "r"(a1), "r"(a2), "r"(a3), "r"(b0), "r"(b1));
      }
    }
    __syncthreads();
  }

  // final l reduction + write-out
  l_a += __shfl_xor_sync(0xffffffffu, l_a, 1);
  l_a += __shfl_xor_sync(0xffffffffu, l_a, 2);
  l_b += __shfl_xor_sync(0xffffffffu, l_b, 1);
  l_b += __shfl_xor_sync(0xffffffffu, l_b, 2);
  float ia = 1.f / l_a, ib = 1.f / l_b;
  float* oa = g_AO + ((size_t)n*LQ + qa)*EMB + h*DH;
  float* ob = oa + 8*EMB;
  #pragma unroll
  for (int jd = 0; jd < 8; jd++) {
    *(float2*)(oa + jd*8 + 2*c) = make_float2(oacc[jd][0]*ia, oacc[jd][1]*ia);
    *(float2*)(ob + jd*8 + 2*c) = make_float2(oacc[jd][2]*ib, oacc[jd][3]*ib);
  }
}

// ---------------------------------------------------------------------------
extern "C" void kernel_launch(void* const* d_in, const int* in_sizes, int n_in,
                              void* d_out, int out_size) {
  (void)in_sizes; (void)n_in; (void)out_size;
  const float* values = (const float*)d_in[0];
  const float* keys   = (const float*)d_in[1];
  const float* query  = (const float*)d_in[2];
  const float* Wq   = (const float*)d_in[3];
  const float* bq   = (const float*)d_in[4];
  const float* Wk   = (const float*)d_in[5];
  const float* bk   = (const float*)d_in[6];
  const float* Wv   = (const float*)d_in[7];
  const float* bv   = (const float*)d_in[8];
  const float* Wo   = (const float*)d_in[9];
  const float* bo   = (const float*)d_in[10];
  const float* Wpos = (const float*)d_in[11];
  const float* bpos = (const float*)d_in[12];
  const float* rwb  = (const float*)d_in[13];
  const float* rrb  = (const float*)d_in[14];
  float* out = (float*)d_out;

  float *pe_p, *R_p, *RT_p, *Q_p, *K_p, *V_p, *AO_p;
  cudaGetSymbolAddress((void**)&pe_p, g_pe);
  cudaGetSymbolAddress((void**)&R_p,  g_R);
  cudaGetSymbolAddress((void**)&RT_p, g_RT);
  cudaGetSymbolAddress((void**)&Q_p,  g_Q);
  cudaGetSymbolAddress((void**)&K_p,  g_K);
  cudaGetSymbolAddress((void**)&V_p,  g_V);
  cudaGetSymbolAddress((void**)&AO_p, g_AO);

  int gemm_smem = (2*AS_ELEMS + 2*BS_ELEMS) * (int)sizeof(uint32_t);
  cudaFuncSetAttribute(gemm_core<0>, cudaFuncAttributeMaxDynamicSharedMemorySize,
                       gemm_smem);
  cudaFuncSetAttribute(gemm_core<1>, cudaFuncAttributeMaxDynamicSharedMemorySize,
                       gemm_smem);
  cudaFuncSetAttribute(attn_mma, cudaFuncAttributeMaxDynamicSharedMemorySize,
                       ATTN_SMEM);

  // 1) sinusoid table
  pe_kernel<<<(NPOS*EMB + 255)/256, 256>>>();
  // 2) R = pe @ Wpos + bpos (1023 x 768)
  gemm_core<0><<<dim3(6, 8), 256, gemm_smem>>>(
      pe_p, Wpos, bpos, R_p, NPOS, EMB, EMB, EMB, EMB, EMB);
  // 3) projections (4096 x 768)
  gemm_core<0><<<dim3(6, 32), 256, gemm_smem>>>(
      query,  Wq, bq, Q_p, NB*LQ, EMB, EMB, EMB, EMB, EMB);
  gemm_core<0><<<dim3(6, 32), 256, gemm_smem>>>(
      keys,   Wk, bk, K_p, NB*LQ, EMB, EMB, EMB, EMB, EMB);
  gemm_core<0><<<dim3(6, 32), 256, gemm_smem>>>(
      values, Wv, bv, V_p, NB*LQ, EMB, EMB, EMB, EMB, EMB);
  // 4) RT = R^T (padded)
  rt_kernel<<<dim3(EMB/32, JPAD/32), dim3(32, 8)>>>();
  // 5) BD gemm: batched over heads, direct scatter epilogue
  gemm_core<1><<<dim3(JPAD/128, 32, NH), 256, gemm_smem>>>(
      Q_p, RT_p, rrb, nullptr, NB*LQ, DH, JPAD, EMB, JPAD, 0);
  // 6) tensor-core fused attention
  attn_mma<<<NB*NH*(LQ/128), 256, ATTN_SMEM>>>(rwb);
  // 7) output projection
  gemm_core<0><<<dim3(6, 32), 256, gemm_smem>>>(
      AO_p, Wo, bo, out, NB*LQ, EMB, EMB, EMB, EMB, EMB);
}

// round 5
// speedup vs baseline: 3.6446x; 1.5781x over previous
#include <cuda_runtime.h>
#include <cuda_fp16.h>
#include <math.h>
#include <stdint.h>
#include <stddef.h>

#define NB   8
#define LQ   512
#define EMB  768
#define NH   12
#define DH   64
#define NPOS 1023   // 2*MAXLEN-1
#define JPAD 1024
#define WSZ  (EMB*EMB)

// ---------------- scratch (__device__ globals: allocation-free rule) --------
__device__ __align__(16) float  g_pe[NPOS*EMB];
__device__ __align__(16) __half g_Wh[5*WSZ];              // Wq,Wk,Wv,Wo,Wpos transposed [n][k] fp16
__device__ __align__(16) __half g_Rh[(size_t)JPAD*EMB];   // R[j][e] fp16 (row 1023 garbage, never used)
__device__ __align__(16) float g_Q [NB*LQ*EMB];
__device__ __align__(16) float g_K [NB*LQ*EMB];
__device__ __align__(16) float g_V [NB*LQ*EMB];
__device__ __align__(16) float g_BD[(size_t)NB*NH*LQ*LQ]; // bd[n][h][q][k]
__device__ __align__(16) float g_AO[NB*LQ*EMB];

__device__ __forceinline__ uint32_t f2tf(float f) {
  uint32_t u; asm("cvt.rna.tf32.f32 %0, %1;" : "=r"(u) : "f"(f)); return u;
}
__device__ __forceinline__ uint32_t packh2(float lo, float hi) {
  __half2 h = __floats2half2_rn(lo, hi);
  return *(uint32_t*)&h;
}

// ---------------------------------------------------------------------------
__global__ void pe_kernel() {
  int idx = blockIdx.x * 256 + threadIdx.x;
  if (idx >= NPOS*EMB) return;
  int p = idx / EMB;
  int e = idx - p * EMB;
  int i2 = e & ~1;
  float div = expf(-(float)i2 * (9.210340371976184f / (float)EMB));
  float ang = (float)p * div;
  g_pe[idx] = (e & 1) ? cosf(ang) : sinf(ang);
}

// ---------------------------------------------------------------------------
// Transpose-convert 5 weight matrices: W[k][n] f32 -> g_Wh[z][n][k] fp16
// ---------------------------------------------------------------------------
__global__ void wconv5(const float* __restrict__ W0, const float* __restrict__ W1,
                       const float* __restrict__ W2, const float* __restrict__ W3,
                       const float* __restrict__ W4) {
  __shared__ float t[32][33];
  int z = blockIdx.z;
  const float* W = (z==0)?W0:(z==1)?W1:(z==2)?W2:(z==3)?W3:W4;
  __half* Wh = g_Wh + (size_t)z*WSZ;
  int k0 = blockIdx.x*32, n0 = blockIdx.y*32;
  int tx = threadIdx.x, ty = threadIdx.y;
  #pragma unroll
  for (int i = 0; i < 4; i++)
    t[ty+8*i][tx] = W[(size_t)(k0+ty+8*i)*EMB + n0+tx];
  __syncthreads();
  #pragma unroll
  for (int i = 0; i < 4; i++)
    Wh[(size_t)(n0+ty+8*i)*EMB + k0+tx] = __float2half(t[tx][ty+8*i]);
}

// ---------------------------------------------------------------------------
// fp16 tensor-core GEMM core (m16n8k16), double-buffered.
// A fp32 global (packed to h2 at staging), B fp16 [n][k] global.
// MODE 0: out-proj  (A=g_AO, B=Wh[3], bias=b0p(bo), C=Cout f32)
// MODE 1: BD gemm   (A=g_Q+h*64 with rrb folded, B=g_Rh+h*64, scatter->g_BD)
// MODE 2: QKV+R batched over z (z<3: f32 out to g_Q/K/V; z=3: pe@Wpos -> g_Rh half)
// 256 threads = 8 warps (2x4), warp tile 64x32.
// ---------------------------------------------------------------------------
#define GA_W 20
#define GSZ  (128*GA_W)
#define GEMM_SMEM (4*GSZ*4)

template<int MODE>
__global__ __launch_bounds__(256, 2) void gemm_h(
    const float* __restrict__ Aq, const float* __restrict__ Ak,
    const float* __restrict__ Av,
    const float* __restrict__ b0p, const float* __restrict__ b1p,
    const float* __restrict__ b2p, const float* __restrict__ b3p,
    float* __restrict__ Cout)
{
  extern __shared__ uint32_t sm[];
  uint32_t* Asm = sm;            // [2][128][GA_W]
  uint32_t* Bsm = sm + 2*GSZ;    // [2][128][GA_W]

  int tid = threadIdx.x, lane = tid & 31, wid = tid >> 5;
  int g = lane >> 2, c = lane & 3;
  int wm0 = (wid >> 2) * 64, wn0 = (wid & 3) * 32;
  int bm = blockIdx.y * 128, bn = blockIdx.x * 128;

  const float* A; const __half* Bh; const float* bias;
  float* Cf = nullptr;
  int Mg = 1 << 30;
  constexpr int K = (MODE == 1) ? 64 : 768;
  constexpr int nsteps = K / 32;

  if (MODE == 0) {
    A = g_AO; Bh = g_Wh + 3*WSZ; bias = b0p; Cf = Cout;
  } else if (MODE == 1) {
    int h = blockIdx.z;
    A = g_Q + h*DH; Bh = g_Rh + h*DH; bias = b0p + h*DH;
    int q0 = bm & (LQ - 1);
    if (bn > q0 + 638 || bn + 127 < q0) return;
  } else {
    int z = blockIdx.z;
    if (z == 0)      { A = Aq; bias = b0p; Cf = g_Q; Bh = g_Wh; }
    else if (z == 1) { A = Ak; bias = b1p; Cf = g_K; Bh = g_Wh + WSZ; }
    else if (z == 2) { A = Av; bias = b2p; Cf = g_V; Bh = g_Wh + 2*WSZ; }
    else {
      if (blockIdx.y >= 8) return;
      A = g_pe; bias = b3p; Bh = g_Wh + 4*WSZ; Mg = NPOS;
    }
  }

  int ar = tid >> 1, aw = (tid & 1) * 8;   // row, word offset (8 words = 16 floats)
  bool arow_ok = (bm + ar) < Mg;

  float acc[4][4][4];
  #pragma unroll
  for (int i = 0; i < 4; i++)
    #pragma unroll
    for (int j = 0; j < 4; j++)
      #pragma unroll
      for (int r = 0; r < 4; r++) acc[i][j][r] = 0.f;

  float areg[16];
  uint4 bu0, bu1;

  auto ldg_step = [&](int k0) {
    const float* Ap = A + (size_t)(bm + ar) * EMB + k0 + aw*2;
    #pragma unroll
    for (int i = 0; i < 4; i++) {
      float4 v = arow_ok ? *(const float4*)(Ap + i*4) : make_float4(0.f,0.f,0.f,0.f);
      areg[i*4+0] = v.x; areg[i*4+1] = v.y; areg[i*4+2] = v.z; areg[i*4+3] = v.w;
    }
    if (MODE == 1) {
      #pragma unroll
      for (int e = 0; e < 16; e++) areg[e] += __ldg(bias + k0 + aw*2 + e);
    }
    const __half* Bp = Bh + (size_t)(bn + ar) * EMB + k0 + aw*2;
    bu0 = *(const uint4*)(Bp);
    bu1 = *(const uint4*)(Bp + 8);
  };

  auto sts_step = [&](int buf) {
    uint32_t* Ab = Asm + buf*GSZ + ar*GA_W + aw;
    uint4 u0 = make_uint4(packh2(areg[0],areg[1]),  packh2(areg[2],areg[3]),
                          packh2(areg[4],areg[5]),  packh2(areg[6],areg[7]));
    uint4 u1 = make_uint4(packh2(areg[8],areg[9]),  packh2(areg[10],areg[11]),
                          packh2(areg[12],areg[13]),packh2(areg[14],areg[15]));
    *(uint4*)(Ab)     = u0;
    *(uint4*)(Ab + 4) = u1;
    uint32_t* Bb = Bsm + buf*GSZ + ar*GA_W + aw;
    *(uint4*)(Bb)     = bu0;
    *(uint4*)(Bb + 4) = bu1;
  };

  ldg_step(0);
  sts_step(0);
  __syncthreads();

  for (int s = 0; s < nsteps; s++) {
    int buf = s & 1;
    if (s + 1 < nsteps) ldg_step((s + 1) * 32);

    const uint32_t* Ab = Asm + buf*GSZ;
    const uint32_t* Bb = Bsm + buf*GSZ;
    #pragma unroll
    for (int ks = 0; ks < 2; ks++) {
      uint32_t af[4][4], bf[4][2];
      #pragma unroll
      for (int i = 0; i < 4; i++) {
        int m0 = wm0 + i*16;
        af[i][0] = Ab[(m0 + g    )*GA_W + ks*8 + c    ];
        af[i][1] = Ab[(m0 + g + 8)*GA_W + ks*8 + c    ];
        af[i][2] = Ab[(m0 + g    )*GA_W + ks*8 + c + 4];
        af[i][3] = Ab[(m0 + g + 8)*GA_W + ks*8 + c + 4];
      }
      #pragma unroll
      for (int j = 0; j < 4; j++) {
        bf[j][0] = Bb[(wn0 + j*8 + g)*GA_W + ks*8 + c    ];
        bf[j][1] = Bb[(wn0 + j*8 + g)*GA_W + ks*8 + c + 4];
      }
      #pragma unroll
      for (int i = 0; i < 4; i++)
        #pragma unroll
        for (int j = 0; j < 4; j++)
          asm volatile(
            "mma.sync.aligned.m16n8k16.row.col.f32.f16.f16.f32 "
            "{%0,%1,%2,%3},{%4,%5,%6,%7},{%8,%9},{%0,%1,%2,%3};"
            : "+f"(acc[i][j][0]), "+f"(acc[i][j][1]),
              "+f"(acc[i][j][2]), "+f"(acc[i][j][3])
            : "r"(af[i][0]), "r"(af[i][1]), "r"(af[i][2]), "r"(af[i][3]),
              "r"(bf[j][0]), "r"(bf[j][1]));
    }

    if (s + 1 < nsteps) sts_step(buf ^ 1);
    __syncthreads();
  }

  if (MODE == 1) {
    int h = blockIdx.z;
    #pragma unroll
    for (int j = 0; j < 4; j++) {
      int col = bn + wn0 + j*8 + 2*c;
      #pragma unroll
      for (int i = 0; i < 4; i++) {
        #pragma unroll
        for (int rr = 0; rr < 2; rr++) {
          int r = bm + wm0 + i*16 + g + rr*8;
          int n = r >> 9, q = r & (LQ - 1);
          float* rowp = g_BD + (((size_t)(n*NH + h) * LQ) + q) * LQ;
          int k0c = q + 511 - col;
          if (k0c >= 0 && k0c < LQ)         rowp[k0c]     = acc[i][j][rr*2+0];
          if (k0c - 1 >= 0 && k0c - 1 < LQ) rowp[k0c - 1] = acc[i][j][rr*2+1];
        }
      }
    }
  } else if (MODE == 2 && blockIdx.z == 3) {
    // half epilogue -> g_Rh
    #pragma unroll
    for (int j = 0; j < 4; j++) {
      int col = bn + wn0 + j*8 + 2*c;
      float b0 = bias[col], b1 = bias[col + 1];
      #pragma unroll
      for (int i = 0; i < 4; i++) {
        int r0 = bm + wm0 + i*16 + g;
        if (r0 < NPOS)
          *(uint32_t*)(g_Rh + (size_t)r0*EMB + col) =
              packh2(acc[i][j][0] + b0, acc[i][j][1] + b1);
        int r1 = r0 + 8;
        if (r1 < NPOS)
          *(uint32_t*)(g_Rh + (size_t)r1*EMB + col) =
              packh2(acc[i][j][2] + b0, acc[i][j][3] + b1);
      }
    }
  } else {
    #pragma unroll
    for (int j = 0; j < 4; j++) {
      int col = bn + wn0 + j*8 + 2*c;
      float b0 = bias[col], b1 = bias[col + 1];
      #pragma unroll
      for (int i = 0; i < 4; i++) {
        int r0 = bm + wm0 + i*16 + g;
        *(float2*)(Cf + (size_t)r0 * EMB + col) =
            make_float2(acc[i][j][0] + b0, acc[i][j][1] + b1);
        int r1 = r0 + 8;
        *(float2*)(Cf + (size_t)r1 * EMB + col) =
            make_float2(acc[i][j][2] + b0, acc[i][j][3] + b1);
      }
    }
  }
}

// ---------------------------------------------------------------------------
// Tensor-core fused attention (unchanged from R4).
// ---------------------------------------------------------------------------
#define QS_W 68
#define VS_W 72
#define ATTN_SMEM ((128*QS_W + 64*QS_W + 32*VS_W) * 4)

__global__ __launch_bounds__(256) void attn_mma(const float* __restrict__ rwb)
{
  extern __shared__ uint32_t sm[];
  uint32_t* Qs = sm;
  uint32_t* Ks = Qs + 128*QS_W;
  uint32_t* Vs = Ks + 64*QS_W;

  int tid = threadIdx.x, lane = tid & 31, wid = tid >> 5;
  int g = lane >> 2, c = lane & 3;
  int b = blockIdx.x;
  int qt = b & 3; b >>= 2;
  int h = b % NH, n = b / NH;
  int q0 = qt * 128;
  int wm = wid * 16;

  const float* Qg = g_Q + ((size_t)n*LQ + q0)*EMB + h*DH;
  for (int u = tid; u < 128*16; u += 256) {
    int r = u >> 4, c4 = (u & 15) << 2;
    float4 v = *(const float4*)(Qg + (size_t)r*EMB + c4);
    float4 w = *(const float4*)(rwb + h*DH + c4);
    Qs[r*QS_W + c4+0] = f2tf(v.x + w.x);
    Qs[r*QS_W + c4+1] = f2tf(v.y + w.y);
    Qs[r*QS_W + c4+2] = f2tf(v.z + w.z);
    Qs[r*QS_W + c4+3] = f2tf(v.w + w.w);
  }

  float oacc[8][4];
  #pragma unroll
  for (int j = 0; j < 8; j++)
    #pragma unroll
    for (int r = 0; r < 4; r++) oacc[j][r] = 0.f;
  float m_a = -1e30f, m_b = -1e30f, l_a = 0.f, l_b = 0.f;

  int qa = q0 + wm + g;
  const float* bdra = g_BD + ((size_t)(n*NH + h)*LQ + qa)*LQ;
  const float* bdrb = bdra + 8*LQ;

  for (int k0 = 0; k0 < LQ; k0 += 64) {
    const float* Kg = g_K + ((size_t)n*LQ + k0)*EMB + h*DH;
    const float* Vg = g_V + ((size_t)n*LQ + k0)*EMB + h*DH;
    for (int u = tid; u < 64*16; u += 256) {
      int r = u >> 4, c4 = (u & 15) << 2;
      float4 v = *(const float4*)(Kg + (size_t)r*EMB + c4);
      Ks[r*QS_W + c4+0] = f2tf(v.x);
      Ks[r*QS_W + c4+1] = f2tf(v.y);
      Ks[r*QS_W + c4+2] = f2tf(v.z);
      Ks[r*QS_W + c4+3] = f2tf(v.w);
    }
    for (int u = tid; u < 32*16; u += 256) {
      int kk = u >> 4, c4 = (u & 15) << 2;
      float4 v0 = *(const float4*)(Vg + (size_t)(2*kk  )*EMB + c4);
      float4 v1 = *(const float4*)(Vg + (size_t)(2*kk+1)*EMB + c4);
      Vs[kk*VS_W + c4+0] = packh2(v0.x, v1.x);
      Vs[kk*VS_W + c4+1] = packh2(v0.y, v1.y);
      Vs[kk*VS_W + c4+2] = packh2(v0.z, v1.z);
      Vs[kk*VS_W + c4+3] = packh2(v0.w, v1.w);
    }
    __syncthreads();

    float sacc[8][4];
    #pragma unroll
    for (int j = 0; j < 8; j++) {
      float2 b0 = *(const float2*)(bdra + k0 + j*8 + 2*c);
      float2 b1 = *(const float2*)(bdrb + k0 + j*8 + 2*c);
      sacc[j][0] = b0.x; sacc[j][1] = b0.y;
      sacc[j][2] = b1.x; sacc[j][3] = b1.y;
    }

    #pragma unroll
    for (int ks = 0; ks < 8; ks++) {
      uint32_t a0 = Qs[(wm+g  )*QS_W + ks*8 + c  ];
      uint32_t a1 = Qs[(wm+g+8)*QS_W + ks*8 + c  ];
      uint32_t a2 = Qs[(wm+g  )*QS_W + ks*8 + c+4];
      uint32_t a3 = Qs[(wm+g+8)*QS_W + ks*8 + c+4];
      #pragma unroll
      for (int j = 0; j < 8; j++) {
        uint32_t b0 = Ks[(j*8+g)*QS_W + ks*8 + c  ];
        uint32_t b1 = Ks[(j*8+g)*QS_W + ks*8 + c+4];
        asm volatile(
          "mma.sync.aligned.m16n8k8.row.col.f32.tf32.tf32.f32 "
          "{%0,%1,%2,%3},{%4,%5,%6,%7},{%8,%9},{%0,%1,%2,%3};"
          : "+f"(sacc[j][0]), "+f"(sacc[j][1]),
            "+f"(sacc[j][2]), "+f"(sacc[j][3])
          : "r"(a0), "r"(a1), "r"(a2), "r"(a3), "r"(b0), "r"(b1));
      }
    }

    float mx_a = -1e30f, mx_b = -1e30f;
    #pragma unroll
    for (int j = 0; j < 8; j++) {
      sacc[j][0] *= 0.125f; sacc[j][1] *= 0.125f;
      sacc[j][2] *= 0.125f; sacc[j][3] *= 0.125f;
      mx_a = fmaxf(mx_a, fmaxf(sacc[j][0], sacc[j][1]));
      mx_b = fmaxf(mx_b, fmaxf(sacc[j][2], sacc[j][3]));
    }
    mx_a = fmaxf(mx_a, __shfl_xor_sync(0xffffffffu, mx_a, 1));
    mx_a = fmaxf(mx_a, __shfl_xor_sync(0xffffffffu, mx_a, 2));
    mx_b = fmaxf(mx_b, __shfl_xor_sync(0xffffffffu, mx_b, 1));
    mx_b = fmaxf(mx_b, __shfl_xor_sync(0xffffffffu, mx_b, 2));
    float mna = fmaxf(m_a, mx_a), mnb = fmaxf(m_b, mx_b);
    float ca = __expf(m_a - mna), cb = __expf(m_b - mnb);
    m_a = mna; m_b = mnb;
    l_a *= ca; l_b *= cb;
    #pragma unroll
    for (int j = 0; j < 8; j++) {
      oacc[j][0] *= ca; oacc[j][1] *= ca;
      oacc[j][2] *= cb; oacc[j][3] *= cb;
    }
    #pragma unroll
    for (int j = 0; j < 8; j++) {
      sacc[j][0] = __expf(sacc[j][0] - m_a); l_a += sacc[j][0];
      sacc[j][1] = __expf(sacc[j][1] - m_a); l_a += sacc[j][1];
      sacc[j][2] = __expf(sacc[j][2] - m_b); l_b += sacc[j][2];
      sacc[j][3] = __expf(sacc[j][3] - m_b); l_b += sacc[j][3];
    }

    #pragma unroll
    for (int jj = 0; jj < 4; jj++) {
      uint32_t a0 = packh2(sacc[2*jj  ][0], sacc[2*jj  ][1]);
      uint32_t a1 = packh2(sacc[2*jj  ][2], sacc[2*jj  ][3]);
      uint32_t a2 = packh2(sacc[2*jj+1][0], sacc[2*jj+1][1]);
      uint32_t a3 = packh2(sacc[2*jj+1][2], sacc[2*jj+1][3]);
      #pragma unroll
      for (int jd = 0; jd < 8; jd++) {
        uint32_t b0 = Vs[(jj*8 + c    )*VS_W + jd*8 + g];
        uint32_t b1 = Vs[(jj*8 + c + 4)*VS_W + jd*8 + g];
        asm volatile(
          "mma.sync.aligned.m16n8k16.row.col.f32.f16.f16.f32 "
          "{%0,%1,%2,%3},{%4,%5,%6,%7},{%8,%9},{%0,%1,%2,%3};"
          : "+f"(oacc[jd][0]), "+f"(oacc[jd][1]),
            "+f"(oacc[jd][2]), "+f"(oacc[jd][3])
          : "r"(a0), "r"(a1), "r"(a2), "r"(a3), "r"(b0), "r"(b1));
      }
    }
    __syncthreads();
  }

  l_a += __shfl_xor_sync(0xffffffffu, l_a, 1);
  l_a += __shfl_xor_sync(0xffffffffu, l_a, 2);
  l_b += __shfl_xor_sync(0xffffffffu, l_b, 1);
  l_b += __shfl_xor_sync(0xffffffffu, l_b, 2);
  float ia = 1.f / l_a, ib = 1.f / l_b;
  float* oa = g_AO + ((size_t)n*LQ + qa)*EMB + h*DH;
  float* ob = oa + 8*EMB;
  #pragma unroll
  for (int jd = 0; jd < 8; jd++) {
    *(float2*)(oa + jd*8 + 2*c) = make_float2(oacc[jd][0]*ia, oacc[jd][1]*ia);
    *(float2*)(ob + jd*8 + 2*c) = make_float2(oacc[jd][2]*ib, oacc[jd][3]*ib);
  }
}

// ---------------------------------------------------------------------------
extern "C" void kernel_launch(void* const* d_in, const int* in_sizes, int n_in,
                              void* d_out, int out_size) {
  (void)in_sizes; (void)n_in; (void)out_size;
  const float* values = (const float*)d_in[0];
  const float* keys   = (const float*)d_in[1];
  const float* query  = (const float*)d_in[2];
  const float* Wq   = (const float*)d_in[3];
  const float* bq   = (const float*)d_in[4];
  const float* Wk   = (const float*)d_in[5];
  const float* bk   = (const float*)d_in[6];
  const float* Wv   = (const float*)d_in[7];
  const float* bv   = (const float*)d_in[8];
  const float* Wo   = (const float*)d_in[9];
  const float* bo   = (const float*)d_in[10];
  const float* Wpos = (const float*)d_in[11];
  const float* bpos = (const float*)d_in[12];
  const float* rwb  = (const float*)d_in[13];
  const float* rrb  = (const float*)d_in[14];
  float* out = (float*)d_out;

  cudaFuncSetAttribute(gemm_h<0>, cudaFuncAttributeMaxDynamicSharedMemorySize,
                       GEMM_SMEM);
  cudaFuncSetAttribute(gemm_h<1>, cudaFuncAttributeMaxDynamicSharedMemorySize,
                       GEMM_SMEM);
  cudaFuncSetAttribute(gemm_h<2>, cudaFuncAttributeMaxDynamicSharedMemorySize,
                       GEMM_SMEM);
  cudaFuncSetAttribute(attn_mma, cudaFuncAttributeMaxDynamicSharedMemorySize,
                       ATTN_SMEM);

  // 1) sinusoid table
  pe_kernel<<<(NPOS*EMB + 255)/256, 256>>>();
  // 2) weight transpose+convert to fp16 [n][k]  (q,k,v,o,pos)
  wconv5<<<dim3(24, 24, 5), dim3(32, 8)>>>(Wq, Wk, Wv, Wo, Wpos);
  // 3) batched Q/K/V projections + R = pe@Wpos (fp16 out), one launch
  gemm_h<2><<<dim3(6, 32, 4), 256, GEMM_SMEM>>>(
      query, keys, values, bq, bk, bv, bpos, nullptr);
  // 4) BD gemm: batched over heads, direct scatter epilogue
  gemm_h<1><<<dim3(JPAD/128, 32, NH), 256, GEMM_SMEM>>>(
      nullptr, nullptr, nullptr, rrb, nullptr, nullptr, nullptr, nullptr);
  // 5) tensor-core fused attention
  attn_mma<<<NB*NH*(LQ/128), 256, ATTN_SMEM>>>(rwb);
  // 6) output projection
  gemm_h<0><<<dim3(6, 32), 256, GEMM_SMEM>>>(
      nullptr, nullptr, nullptr, bo, nullptr, nullptr, nullptr, out);
}

// round 10
// speedup vs baseline: 4.1218x; 1.1309x over previous
#include <cuda_runtime.h>
#include <cuda_fp16.h>
#include <math.h>
#include <stdint.h>
#include <stddef.h>

#define NB   8
#define LQ   512
#define EMB  768
#define NH   12
#define DH   64
#define NPOS 1023   // 2*MAXLEN-1
#define JPAD 1024
#define WSZ  (EMB*EMB)

// ---------------- scratch (__device__ globals: allocation-free rule) --------
__device__ __align__(16) float  g_pe[NPOS*EMB];
__device__ __align__(16) __half g_Wh[5*WSZ];              // weights transposed [n][k] fp16
__device__ __align__(16) __half g_Rh[(size_t)JPAD*EMB];   // R[j][e] fp16 (row 1023 unused)
__device__ __align__(16) __half g_Q [NB*LQ*EMB];
__device__ __align__(16) __half g_Qr[NB*LQ*EMB];          // Q + rrb, fp16
__device__ __align__(16) __half g_K [NB*LQ*EMB];
__device__ __align__(16) __half g_V [NB*LQ*EMB];
__device__ __align__(16) __half g_BD[(size_t)NB*NH*LQ*LQ];
__device__ __align__(16) __half g_AO[NB*LQ*EMB];

__device__ __forceinline__ uint32_t packh2(float lo, float hi) {
  __half2 h = __floats2half2_rn(lo, hi);
  return *(uint32_t*)&h;
}
__device__ __forceinline__ void mma_h(float* d, const uint32_t* a,
                                      uint32_t b0, uint32_t b1) {
  asm volatile(
    "mma.sync.aligned.m16n8k16.row.col.f32.f16.f16.f32 "
    "{%0,%1,%2,%3},{%4,%5,%6,%7},{%8,%9},{%0,%1,%2,%3};"
    : "+f"(d[0]), "+f"(d[1]), "+f"(d[2]), "+f"(d[3])
    : "r"(a[0]), "r"(a[1]), "r"(a[2]), "r"(a[3]), "r"(b0), "r"(b1));
}

// ---------------------------------------------------------------------------
__global__ void pe_kernel() {
  int idx = blockIdx.x * 256 + threadIdx.x;
  if (idx >= NPOS*EMB) return;
  int p = idx / EMB;
  int e = idx - p * EMB;
  int i2 = e & ~1;
  float div = expf(-(float)i2 * (9.210340371976184f / (float)EMB));
  float ang = (float)p * div;
  g_pe[idx] = (e & 1) ? cosf(ang) : sinf(ang);
}

// ---------------------------------------------------------------------------
__global__ void wconv5(const float* __restrict__ W0, const float* __restrict__ W1,
                       const float* __restrict__ W2, const float* __restrict__ W3,
                       const float* __restrict__ W4) {
  __shared__ float t[32][33];
  int z = blockIdx.z;
  const float* W = (z==0)?W0:(z==1)?W1:(z==2)?W2:(z==3)?W3:W4;
  __half* Wh = g_Wh + (size_t)z*WSZ;
  int k0 = blockIdx.x*32, n0 = blockIdx.y*32;
  int tx = threadIdx.x, ty = threadIdx.y;
  #pragma unroll
  for (int i = 0; i < 4; i++)
    t[ty+8*i][tx] = W[(size_t)(k0+ty+8*i)*EMB + n0+tx];
  __syncthreads();
  #pragma unroll
  for (int i = 0; i < 4; i++)
    Wh[(size_t)(n0+ty+8*i)*EMB + k0+tx] = __float2half(t[tx][ty+8*i]);
}

// ---------------------------------------------------------------------------
// Qr = Q + rrb (fp16)
// ---------------------------------------------------------------------------
__global__ void qradd(const float* __restrict__ rrb) {
  int i = blockIdx.x * 256 + threadIdx.x;   // over half2 words
  if (i >= NB*LQ*EMB/2) return;
  int e2 = i % (EMB/2);
  float2 r = *(const float2*)(rrb + 2*e2);
  float2 f = __half22float2(((const __half2*)g_Q)[i]);
  ((__half2*)g_Qr)[i] = __floats2half2_rn(f.x + r.x, f.y + r.y);
}

// ---------------------------------------------------------------------------
// fp16 MMA GEMM core (scalar frag loads + plain LDG/STS staging).
// MODE 0: out-proj  (A=g_AO fp16, B=Wh[3], bias=bo, C f32 -> Cout)
// MODE 1: BD gemm   (A=g_Qr+h*64, B=g_Rh+h*64, scatter fp16 -> g_BD)
// MODE 2: QKV+R over z (A f32; z<3 -> g_Q/K/V fp16; z=3 -> g_Rh fp16)
// ---------------------------------------------------------------------------
#define GA_W 20
#define GSZ  (128*GA_W)
#define GEMM_SMEM (4*GSZ*4)

template<int MODE>
__global__ __launch_bounds__(256, 2) void gemm_h(
    const float* __restrict__ Aq, const float* __restrict__ Ak,
    const float* __restrict__ Av,
    const float* __restrict__ b0p, const float* __restrict__ b1p,
    const float* __restrict__ b2p, const float* __restrict__ b3p,
    float* __restrict__ Cout)
{
  extern __shared__ uint32_t sm[];
  uint32_t* Asm = sm;            // [2][128][GA_W]
  uint32_t* Bsm = sm + 2*GSZ;    // [2][128][GA_W]

  int tid = threadIdx.x, lane = tid & 31, wid = tid >> 5;
  int g = lane >> 2, c = lane & 3;
  int wm0 = (wid >> 2) * 64, wn0 = (wid & 3) * 32;
  int bm = blockIdx.y * 128, bn = blockIdx.x * 128;

  const __half* Ah = nullptr; const float* Af = nullptr;
  const __half* Bh; const float* bias = nullptr;
  float* Cf = nullptr; __half* Chf = nullptr;
  int Mg = 1 << 30;
  constexpr int K = (MODE == 1) ? 64 : 768;
  constexpr int nsteps = K / 32;

  if (MODE == 0) {
    Ah = g_AO; Bh = g_Wh + 3*WSZ; bias = b0p; Cf = Cout;
  } else if (MODE == 1) {
    int h = blockIdx.z;
    Ah = g_Qr + h*DH; Bh = g_Rh + h*DH;
    int q0 = bm & (LQ - 1);
    if (bn > q0 + 638 || bn + 127 < q0) return;
  } else {
    int z = blockIdx.z;
    if (z == 0)      { Af = Aq; bias = b0p; Chf = g_Q; Bh = g_Wh; }
    else if (z == 1) { Af = Ak; bias = b1p; Chf = g_K; Bh = g_Wh + WSZ; }
    else if (z == 2) { Af = Av; bias = b2p; Chf = g_V; Bh = g_Wh + 2*WSZ; }
    else {
      if (blockIdx.y >= 8) return;
      Af = g_pe; bias = b3p; Bh = g_Wh + 4*WSZ; Mg = NPOS;
    }
  }

  int srow = tid >> 1;            // staging row 0..127
  int scol = (tid & 1) * 8;       // staging word offset (8 words = 16 halfs)
  bool arow_ok = (bm + srow) < Mg;

  float acc[4][4][4];
  #pragma unroll
  for (int i = 0; i < 4; i++)
    #pragma unroll
    for (int j = 0; j < 4; j++)
      #pragma unroll
      for (int r = 0; r < 4; r++) acc[i][j][r] = 0.f;

  uint4 au0, au1, bu0, bu1;

  auto ldg_step = [&](int k0) {
    const __half* Bp = Bh + (size_t)(bn + srow) * EMB + k0 + scol*2;
    bu0 = *(const uint4*)(Bp);
    bu1 = *(const uint4*)(Bp + 8);
    if (MODE != 2) {
      const __half* Ap = Ah + (size_t)(bm + srow) * EMB + k0 + scol*2;
      au0 = *(const uint4*)(Ap);
      au1 = *(const uint4*)(Ap + 8);
    } else {
      const float* Ap = Af + (size_t)(bm + srow) * EMB + k0 + scol*2;
      float4 v0 = arow_ok ? *(const float4*)(Ap)      : make_float4(0,0,0,0);
      float4 v1 = arow_ok ? *(const float4*)(Ap + 4)  : make_float4(0,0,0,0);
      float4 v2 = arow_ok ? *(const float4*)(Ap + 8)  : make_float4(0,0,0,0);
      float4 v3 = arow_ok ? *(const float4*)(Ap + 12) : make_float4(0,0,0,0);
      au0 = make_uint4(packh2(v0.x,v0.y), packh2(v0.z,v0.w),
                       packh2(v1.x,v1.y), packh2(v1.z,v1.w));
      au1 = make_uint4(packh2(v2.x,v2.y), packh2(v2.z,v2.w),
                       packh2(v3.x,v3.y), packh2(v3.z,v3.w));
    }
  };

  auto sts_step = [&](int buf) {
    uint32_t* Ab = Asm + buf*GSZ + srow*GA_W + scol;
    *(uint4*)(Ab)     = au0;
    *(uint4*)(Ab + 4) = au1;
    uint32_t* Bb = Bsm + buf*GSZ + srow*GA_W + scol;
    *(uint4*)(Bb)     = bu0;
    *(uint4*)(Bb + 4) = bu1;
  };

  ldg_step(0);
  sts_step(0);
  __syncthreads();

  for (int s = 0; s < nsteps; s++) {
    int buf = s & 1;
    if (s + 1 < nsteps) ldg_step((s + 1) * 32);

    const uint32_t* Ab = Asm + buf*GSZ;
    const uint32_t* Bb = Bsm + buf*GSZ;
    #pragma unroll
    for (int ks = 0; ks < 2; ks++) {
      uint32_t af[4][4], bf[4][2];
      #pragma unroll
      for (int i = 0; i < 4; i++) {
        int m0 = wm0 + i*16;
        af[i][0] = Ab[(m0 + g    )*GA_W + ks*8 + c    ];
        af[i][1] = Ab[(m0 + g + 8)*GA_W + ks*8 + c    ];
        af[i][2] = Ab[(m0 + g    )*GA_W + ks*8 + c + 4];
        af[i][3] = Ab[(m0 + g + 8)*GA_W + ks*8 + c + 4];
      }
      #pragma unroll
      for (int j = 0; j < 4; j++) {
        bf[j][0] = Bb[(wn0 + j*8 + g)*GA_W + ks*8 + c    ];
        bf[j][1] = Bb[(wn0 + j*8 + g)*GA_W + ks*8 + c + 4];
      }
      #pragma unroll
      for (int i = 0; i < 4; i++)
        #pragma unroll
        for (int j = 0; j < 4; j++)
          mma_h(acc[i][j], af[i], bf[j][0], bf[j][1]);
    }

    if (s + 1 < nsteps) sts_step(buf ^ 1);
    __syncthreads();
  }

  if (MODE == 1) {
    int h = blockIdx.z;
    #pragma unroll
    for (int j = 0; j < 4; j++) {
      int col = bn + wn0 + j*8 + 2*c;
      #pragma unroll
      for (int i = 0; i < 4; i++) {
        #pragma unroll
        for (int rr = 0; rr < 2; rr++) {
          int r = bm + wm0 + i*16 + g + rr*8;
          int n = r >> 9, q = r & (LQ - 1);
          __half* rowp = g_BD + (((size_t)(n*NH + h) * LQ) + q) * LQ;
          int k0c = q + 511 - col;
          if (k0c >= 0 && k0c < LQ)
            rowp[k0c] = __float2half(acc[i][j][rr*2+0]);
          if (k0c - 1 >= 0 && k0c - 1 < LQ)
            rowp[k0c - 1] = __float2half(acc[i][j][rr*2+1]);
        }
      }
    }
  } else if (MODE == 0) {
    #pragma unroll
    for (int j = 0; j < 4; j++) {
      int col = bn + wn0 + j*8 + 2*c;
      float b0 = bias[col], b1 = bias[col + 1];
      #pragma unroll
      for (int i = 0; i < 4; i++) {
        int r0 = bm + wm0 + i*16 + g;
        *(float2*)(Cf + (size_t)r0 * EMB + col) =
            make_float2(acc[i][j][0] + b0, acc[i][j][1] + b1);
        int r1 = r0 + 8;
        *(float2*)(Cf + (size_t)r1 * EMB + col) =
            make_float2(acc[i][j][2] + b0, acc[i][j][3] + b1);
      }
    }
  } else {
    bool toR = (blockIdx.z == 3);
    #pragma unroll
    for (int j = 0; j < 4; j++) {
      int col = bn + wn0 + j*8 + 2*c;
      float b0 = bias[col], b1 = bias[col + 1];
      #pragma unroll
      for (int i = 0; i < 4; i++) {
        #pragma unroll
        for (int rr = 0; rr < 2; rr++) {
          int r = bm + wm0 + i*16 + g + rr*8;
          uint32_t w = packh2(acc[i][j][rr*2+0] + b0, acc[i][j][rr*2+1] + b1);
          if (toR) {
            if (r < NPOS) *(uint32_t*)(g_Rh + (size_t)r*EMB + col) = w;
          } else {
            *(uint32_t*)(Chf + (size_t)r*EMB + col) = w;
          }
        }
      }
    }
  }
}

// ---------------------------------------------------------------------------
// Tensor-core fused attention: fp16 operands, fp16 m16n8k16 S-mma.
// FIX R9: Q/K staging now covers the FULL 64-half row (8 uint4 chunks, not 4).
// ---------------------------------------------------------------------------
#define QH_W 36     // Qs/Ks row stride in words (32 data + 4 pad)
#define VS_W 72
#define ATTN_SMEM ((128*QH_W + 64*QH_W + 32*VS_W + 32) * 4)

__global__ __launch_bounds__(256) void attn_mma(const float* __restrict__ rwb)
{
  extern __shared__ uint32_t sm[];
  uint32_t* Qs   = sm;                   // [128][QH_W] fp16 pairs (rwb folded)
  uint32_t* Ks   = Qs + 128*QH_W;        // [64][QH_W]
  uint32_t* Vs   = Ks + 64*QH_W;         // [32][VS_W] h2 k-pairs
  uint32_t* rwbh = Vs + 32*VS_W;         // [32] h2

  int tid = threadIdx.x, lane = tid & 31, wid = tid >> 5;
  int g = lane >> 2, c = lane & 3;
  int b = blockIdx.x;
  int qt = b & 3; b >>= 2;
  int h = b % NH, n = b / NH;
  int q0 = qt * 128;
  int wm = wid * 16;

  if (tid < 32) {
    float2 r = *(const float2*)(rwb + h*DH + 2*tid);
    rwbh[tid] = packh2(r.x, r.y);
  }
  __syncthreads();

  // stage Q (fp16) + rwb : 128 rows x 8 chunks of 8 halfs
  const __half* Qg = g_Q + ((size_t)n*LQ + q0)*EMB + h*DH;
  for (int u = tid; u < 128*8; u += 256) {
    int r = u >> 3, ch = u & 7;
    uint4 v = *(const uint4*)(Qg + (size_t)r*EMB + ch*8);
    __half2 w0 = *(__half2*)&rwbh[ch*4+0];
    __half2 w1 = *(__half2*)&rwbh[ch*4+1];
    __half2 w2 = *(__half2*)&rwbh[ch*4+2];
    __half2 w3 = *(__half2*)&rwbh[ch*4+3];
    __half2 q0h = __hadd2(*(__half2*)&v.x, w0);
    __half2 q1h = __hadd2(*(__half2*)&v.y, w1);
    __half2 q2h = __hadd2(*(__half2*)&v.z, w2);
    __half2 q3h = __hadd2(*(__half2*)&v.w, w3);
    uint32_t* dst = Qs + r*QH_W + ch*4;
    dst[0] = *(uint32_t*)&q0h; dst[1] = *(uint32_t*)&q1h;
    dst[2] = *(uint32_t*)&q2h; dst[3] = *(uint32_t*)&q3h;
  }

  float oacc[8][4];
  #pragma unroll
  for (int j = 0; j < 8; j++)
    #pragma unroll
    for (int r = 0; r < 4; r++) oacc[j][r] = 0.f;
  float m_a = -1e30f, m_b = -1e30f, l_a = 0.f, l_b = 0.f;

  int qa = q0 + wm + g;
  const __half* bdra = g_BD + ((size_t)(n*NH + h)*LQ + qa)*LQ;
  const __half* bdrb = bdra + 8*LQ;

  for (int k0 = 0; k0 < LQ; k0 += 64) {
    const __half* Kg = g_K + ((size_t)n*LQ + k0)*EMB + h*DH;
    const __half* Vg = g_V + ((size_t)n*LQ + k0)*EMB + h*DH;
    // K tile: 64 rows x 8 chunks of 8 halfs (FULL row)
    for (int u = tid; u < 64*8; u += 256) {
      int r = u >> 3, ch = u & 7;
      uint4 v = *(const uint4*)(Kg + (size_t)r*EMB + ch*8);
      uint32_t* dst = Ks + r*QH_W + ch*4;
      dst[0] = v.x; dst[1] = v.y; dst[2] = v.z; dst[3] = v.w;
    }
    // V interleave: Vs[kpair][d] = h2(V[2k][d], V[2k+1][d])
    for (int u = tid; u < 32*16; u += 256) {
      int kk = u >> 4, dc = (u & 15) * 4;
      uint2 a  = *(const uint2*)(Vg + (size_t)(2*kk  )*EMB + dc);
      uint2 bb = *(const uint2*)(Vg + (size_t)(2*kk+1)*EMB + dc);
      uint32_t* dst = Vs + kk*VS_W + dc;
      dst[0] = __byte_perm(a.x, bb.x, 0x5410);
      dst[1] = __byte_perm(a.x, bb.x, 0x7632);
      dst[2] = __byte_perm(a.y, bb.y, 0x5410);
      dst[3] = __byte_perm(a.y, bb.y, 0x7632);
    }
    __syncthreads();

    // init S from BD (fp16)
    float sacc[8][4];
    #pragma unroll
    for (int j = 0; j < 8; j++) {
      uint32_t w0 = *(const uint32_t*)(bdra + k0 + j*8 + 2*c);
      uint32_t w1 = *(const uint32_t*)(bdrb + k0 + j*8 + 2*c);
      float2 f0 = __half22float2(*(__half2*)&w0);
      float2 f1 = __half22float2(*(__half2*)&w1);
      sacc[j][0] = f0.x; sacc[j][1] = f0.y;
      sacc[j][2] = f1.x; sacc[j][3] = f1.y;
    }

    // S += (Q+rwb) . K^T   (fp16 m16n8k16, scalar frag loads)
    #pragma unroll
    for (int ks = 0; ks < 4; ks++) {
      uint32_t af[4];
      af[0] = Qs[(wm + g    )*QH_W + ks*8 + c    ];
      af[1] = Qs[(wm + g + 8)*QH_W + ks*8 + c    ];
      af[2] = Qs[(wm + g    )*QH_W + ks*8 + c + 4];
      af[3] = Qs[(wm + g + 8)*QH_W + ks*8 + c + 4];
      #pragma unroll
      for (int j = 0; j < 8; j++) {
        uint32_t b0 = Ks[(j*8 + g)*QH_W + ks*8 + c    ];
        uint32_t b1 = Ks[(j*8 + g)*QH_W + ks*8 + c + 4];
        mma_h(sacc[j], af, b0, b1);
      }
    }

    // online softmax
    float mx_a = -1e30f, mx_b = -1e30f;
    #pragma unroll
    for (int j = 0; j < 8; j++) {
      sacc[j][0] *= 0.125f; sacc[j][1] *= 0.125f;
      sacc[j][2] *= 0.125f; sacc[j][3] *= 0.125f;
      mx_a = fmaxf(mx_a, fmaxf(sacc[j][0], sacc[j][1]));
      mx_b = fmaxf(mx_b, fmaxf(sacc[j][2], sacc[j][3]));
    }
    mx_a = fmaxf(mx_a, __shfl_xor_sync(0xffffffffu, mx_a, 1));
    mx_a = fmaxf(mx_a, __shfl_xor_sync(0xffffffffu, mx_a, 2));
    mx_b = fmaxf(mx_b, __shfl_xor_sync(0xffffffffu, mx_b, 1));
    mx_b = fmaxf(mx_b, __shfl_xor_sync(0xffffffffu, mx_b, 2));
    float mna = fmaxf(m_a, mx_a), mnb = fmaxf(m_b, mx_b);
    float ca = __expf(m_a - mna), cb = __expf(m_b - mnb);
    m_a = mna; m_b = mnb;
    l_a *= ca; l_b *= cb;
    #pragma unroll
    for (int j = 0; j < 8; j++) {
      oacc[j][0] *= ca; oacc[j][1] *= ca;
      oacc[j][2] *= cb; oacc[j][3] *= cb;
    }
    #pragma unroll
    for (int j = 0; j < 8; j++) {
      sacc[j][0] = __expf(sacc[j][0] - m_a); l_a += sacc[j][0];
      sacc[j][1] = __expf(sacc[j][1] - m_a); l_a += sacc[j][1];
      sacc[j][2] = __expf(sacc[j][2] - m_b); l_b += sacc[j][2];
      sacc[j][3] = __expf(sacc[j][3] - m_b); l_b += sacc[j][3];
    }

    // O += P . V
    #pragma unroll
    for (int jj = 0; jj < 4; jj++) {
      uint32_t pa[4];
      pa[0] = packh2(sacc[2*jj  ][0], sacc[2*jj  ][1]);
      pa[1] = packh2(sacc[2*jj  ][2], sacc[2*jj  ][3]);
      pa[2] = packh2(sacc[2*jj+1][0], sacc[2*jj+1][1]);
      pa[3] = packh2(sacc[2*jj+1][2], sacc[2*jj+1][3]);
      #pragma unroll
      for (int jd = 0; jd < 8; jd++) {
        uint32_t b0 = Vs[(jj*8 + c    )*VS_W + jd*8 + g];
        uint32_t b1 = Vs[(jj*8 + c + 4)*VS_W + jd*8 + g];
        mma_h(oacc[jd], pa, b0, b1);
      }
    }
    __syncthreads();
  }

  l_a += __shfl_xor_sync(0xffffffffu, l_a, 1);
  l_a += __shfl_xor_sync(0xffffffffu, l_a, 2);
  l_b += __shfl_xor_sync(0xffffffffu, l_b, 1);
  l_b += __shfl_xor_sync(0xffffffffu, l_b, 2);
  float ia = 1.f / l_a, ib = 1.f / l_b;
  __half* oa = g_AO + ((size_t)n*LQ + qa)*EMB + h*DH;
  __half* ob = oa + 8*EMB;
  #pragma unroll
  for (int jd = 0; jd < 8; jd++) {
    *(uint32_t*)(oa + jd*8 + 2*c) = packh2(oacc[jd][0]*ia, oacc[jd][1]*ia);
    *(uint32_t*)(ob + jd*8 + 2*c) = packh2(oacc[jd][2]*ib, oacc[jd][3]*ib);
  }
}

// ---------------------------------------------------------------------------
extern "C" void kernel_launch(void* const* d_in, const int* in_sizes, int n_in,
                              void* d_out, int out_size) {
  (void)in_sizes; (void)n_in; (void)out_size;
  const float* values = (const float*)d_in[0];
  const float* keys   = (const float*)d_in[1];
  const float* query  = (const float*)d_in[2];
  const float* Wq   = (const float*)d_in[3];
  const float* bq   = (const float*)d_in[4];
  const float* Wk   = (const float*)d_in[5];
  const float* bk   = (const float*)d_in[6];
  const float* Wv   = (const float*)d_in[7];
  const float* bv   = (const float*)d_in[8];
  const float* Wo   = (const float*)d_in[9];
  const float* bo   = (const float*)d_in[10];
  const float* Wpos = (const float*)d_in[11];
  const float* bpos = (const float*)d_in[12];
  const float* rwb  = (const float*)d_in[13];
  const float* rrb  = (const float*)d_in[14];
  float* out = (float*)d_out;

  cudaFuncSetAttribute(gemm_h<0>, cudaFuncAttributeMaxDynamicSharedMemorySize,
                       GEMM_SMEM);
  cudaFuncSetAttribute(gemm_h<1>, cudaFuncAttributeMaxDynamicSharedMemorySize,
                       GEMM_SMEM);
  cudaFuncSetAttribute(gemm_h<2>, cudaFuncAttributeMaxDynamicSharedMemorySize,
                       GEMM_SMEM);
  cudaFuncSetAttribute(attn_mma, cudaFuncAttributeMaxDynamicSharedMemorySize,
                       ATTN_SMEM);

  // 1) sinusoid table
  pe_kernel<<<(NPOS*EMB + 255)/256, 256>>>();
  // 2) weight transpose+convert to fp16 [n][k]
  wconv5<<<dim3(24, 24, 5), dim3(32, 8)>>>(Wq, Wk, Wv, Wo, Wpos);
  // 3) batched Q/K/V projections + R = pe@Wpos, fp16 outputs
  gemm_h<2><<<dim3(6, 32, 4), 256, GEMM_SMEM>>>(
      query, keys, values, bq, bk, bv, bpos, nullptr);
  // 4) Qr = Q + rrb
  qradd<<<(NB*LQ*EMB/2 + 255)/256, 256>>>(rrb);
  // 5) BD gemm: batched over heads, fp16 scatter epilogue
  gemm_h<1><<<dim3(JPAD/128, 32, NH), 256, GEMM_SMEM>>>(
      nullptr, nullptr, nullptr, nullptr, nullptr, nullptr, nullptr, nullptr);
  // 6) tensor-core fused attention (all fp16 operands)
  attn_mma<<<NB*NH*(LQ/128), 256, ATTN_SMEM>>>(rwb);
  // 7) output projection (f32 out)
  gemm_h<0><<<dim3(6, 32), 256, GEMM_SMEM>>>(
      nullptr, nullptr, nullptr, bo, nullptr, nullptr, nullptr, out);
}

// round 12
// speedup vs baseline: 4.7476x; 1.1518x over previous
#include <cuda_runtime.h>
#include <cuda_fp16.h>
#include <math.h>
#include <stdint.h>
#include <stddef.h>

#define NB   8
#define LQ   512
#define EMB  768
#define NH   12
#define DH   64
#define NPOS 1023   // 2*MAXLEN-1
#define JPAD 1024
#define WSZ  (EMB*EMB)

// ---------------- scratch (__device__ globals: allocation-free rule) --------
__device__ __align__(16) float  g_pe[NPOS*EMB];
__device__ __align__(16) __half g_Wh[5*WSZ];              // weights transposed [n][k] fp16
__device__ __align__(16) __half g_Rh[(size_t)JPAD*EMB];   // R[j][e] fp16 (row 1023 unused)
__device__ __align__(16) __half g_Q [NB*LQ*EMB];
__device__ __align__(16) __half g_K [NB*LQ*EMB];
__device__ __align__(16) __half g_V [NB*LQ*EMB];
__device__ __align__(16) __half g_BD[(size_t)NB*NH*LQ*LQ];
__device__ __align__(16) __half g_AO[NB*LQ*EMB];

__device__ __forceinline__ uint32_t packh2(float lo, float hi) {
  __half2 h = __floats2half2_rn(lo, hi);
  return *(uint32_t*)&h;
}
__device__ __forceinline__ uint32_t hadd2u(uint32_t a, uint32_t b) {
  __half2 r = __hadd2(*(__half2*)&a, *(__half2*)&b);
  return *(uint32_t*)&r;
}
__device__ __forceinline__ void ldsm_x4(uint32_t* r, uint32_t addr) {
  asm volatile("ldmatrix.sync.aligned.m8n8.x4.shared.b16 {%0,%1,%2,%3}, [%4];"
    : "=r"(r[0]), "=r"(r[1]), "=r"(r[2]), "=r"(r[3]) : "r"(addr));
}
__device__ __forceinline__ void cpa16(uint32_t dst, const void* src) {
  asm volatile("cp.async.cg.shared.global [%0], [%1], 16;" :: "r"(dst), "l"(src));
}
__device__ __forceinline__ void cpa_wait_all() {
  asm volatile("cp.async.wait_all;" ::: "memory");
}
__device__ __forceinline__ void mma_h(float* d, const uint32_t* a,
                                      uint32_t b0, uint32_t b1) {
  asm volatile(
    "mma.sync.aligned.m16n8k16.row.col.f32.f16.f16.f32 "
    "{%0,%1,%2,%3},{%4,%5,%6,%7},{%8,%9},{%0,%1,%2,%3};"
    : "+f"(d[0]), "+f"(d[1]), "+f"(d[2]), "+f"(d[3])
    : "r"(a[0]), "r"(a[1]), "r"(a[2]), "r"(a[3]), "r"(b0), "r"(b1));
}

// ---------------------------------------------------------------------------
__global__ void pe_kernel() {
  int idx = blockIdx.x * 256 + threadIdx.x;
  if (idx >= NPOS*EMB) return;
  int p = idx / EMB;
  int e = idx - p * EMB;
  int i2 = e & ~1;
  float div = expf(-(float)i2 * (9.210340371976184f / (float)EMB));
  float ang = (float)p * div;
  g_pe[idx] = (e & 1) ? cosf(ang) : sinf(ang);
}

// ---------------------------------------------------------------------------
__global__ void wconv5(const float* __restrict__ W0, const float* __restrict__ W1,
                       const float* __restrict__ W2, const float* __restrict__ W3,
                       const float* __restrict__ W4) {
  __shared__ float t[32][33];
  int z = blockIdx.z;
  const float* W = (z==0)?W0:(z==1)?W1:(z==2)?W2:(z==3)?W3:W4;
  __half* Wh = g_Wh + (size_t)z*WSZ;
  int k0 = blockIdx.x*32, n0 = blockIdx.y*32;
  int tx = threadIdx.x, ty = threadIdx.y;
  #pragma unroll
  for (int i = 0; i < 4; i++)
    t[ty+8*i][tx] = W[(size_t)(k0+ty+8*i)*EMB + n0+tx];
  __syncthreads();
  #pragma unroll
  for (int i = 0; i < 4; i++)
    Wh[(size_t)(n0+ty+8*i)*EMB + k0+tx] = __float2half(t[tx][ty+8*i]);
}

// ---------------------------------------------------------------------------
// fp16 MMA GEMM core, ldmatrix frag loads + cp.async staging.
// MODE 0: out-proj  (A=g_AO fp16, B=Wh[3], bias=bo, C f32 -> Cout)
// MODE 1: BD gemm   (A=g_Q+h*64 with rrb folded at staging, B=g_Rh+h*64,
//                    scatter fp16 -> g_BD; b0p carries rrb)
// MODE 2: QKV+R over z (A f32; z<3 -> g_Q/K/V fp16; z=3 -> g_Rh fp16)
// ---------------------------------------------------------------------------
#define GA_W 20
#define GSZ  (128*GA_W)
#define GEMM_SMEM (4*GSZ*4)

template<int MODE>
__global__ __launch_bounds__(256, 2) void gemm_h(
    const float* __restrict__ Aq, const float* __restrict__ Ak,
    const float* __restrict__ Av,
    const float* __restrict__ b0p, const float* __restrict__ b1p,
    const float* __restrict__ b2p, const float* __restrict__ b3p,
    float* __restrict__ Cout)
{
  extern __shared__ uint32_t sm[];
  uint32_t* Asm = sm;            // [2][128][GA_W]
  uint32_t* Bsm = sm + 2*GSZ;    // [2][128][GA_W]
  uint32_t Asm_sa = (uint32_t)__cvta_generic_to_shared(Asm);
  uint32_t Bsm_sa = (uint32_t)__cvta_generic_to_shared(Bsm);

  int tid = threadIdx.x, lane = tid & 31, wid = tid >> 5;
  int g = lane >> 2, c = lane & 3;
  int lane7 = lane & 7, mat = lane >> 3;
  int rsel = (mat & 1) * 8 + lane7;       // A-frag row select
  int akw  = (mat >> 1) * 4;              // A-frag k-word offset
  int bkw  = mat * 4;                     // B-frag k-word offset
  int wm0 = (wid >> 2) * 64, wn0 = (wid & 3) * 32;
  int bm = blockIdx.y * 128, bn = blockIdx.x * 128;

  const __half* Ah = nullptr; const float* Af = nullptr;
  const __half* Bh; const float* bias = nullptr;
  const float* rrbp = nullptr;
  float* Cf = nullptr; __half* Chf = nullptr;
  int Mg = 1 << 30;
  constexpr int K = (MODE == 1) ? 64 : 768;
  constexpr int nsteps = K / 32;

  if (MODE == 0) {
    Ah = g_AO; Bh = g_Wh + 3*WSZ; bias = b0p; Cf = Cout;
  } else if (MODE == 1) {
    int h = blockIdx.z;
    Ah = g_Q + h*DH; Bh = g_Rh + h*DH; rrbp = b0p + h*DH;
    int q0 = bm & (LQ - 1);
    if (bn > q0 + 638 || bn + 127 < q0) return;
  } else {
    int z = blockIdx.z;
    if (z == 0)      { Af = Aq; bias = b0p; Chf = g_Q; Bh = g_Wh; }
    else if (z == 1) { Af = Ak; bias = b1p; Chf = g_K; Bh = g_Wh + WSZ; }
    else if (z == 2) { Af = Av; bias = b2p; Chf = g_V; Bh = g_Wh + 2*WSZ; }
    else {
      if (blockIdx.y >= 8) return;
      Af = g_pe; bias = b3p; Bh = g_Wh + 4*WSZ; Mg = NPOS;
    }
  }

  int srow = tid >> 1;            // staging row 0..127
  int scol = (tid & 1) * 8;       // staging word offset (8 words = 16 halfs)
  bool arow_ok = (bm + srow) < Mg;

  float acc[4][4][4];
  #pragma unroll
  for (int i = 0; i < 4; i++)
    #pragma unroll
    for (int j = 0; j < 4; j++)
      #pragma unroll
      for (int r = 0; r < 4; r++) acc[i][j][r] = 0.f;

  uint4 au0, au1;   // MODE 1/2: staged A words

  auto issue_step = [&](int buf, int k0) {
    // B via cp.async (2 chunks of 16B per thread; 2 threads cover the 64B row)
    #pragma unroll
    for (int it = 0; it < 2; it++) {
      int ch = (tid & 1) * 2 + it;
      cpa16(Bsm_sa + (buf*GSZ + srow*GA_W + ch*4)*4,
            Bh + (size_t)(bn + srow) * EMB + k0 + ch*8);
    }
    if (MODE == 0) {
      #pragma unroll
      for (int it = 0; it < 2; it++) {
        int ch = (tid & 1) * 2 + it;
        cpa16(Asm_sa + (buf*GSZ + srow*GA_W + ch*4)*4,
              Ah + (size_t)(bm + srow) * EMB + k0 + ch*8);
      }
    } else if (MODE == 1) {
      const __half* Ap = Ah + (size_t)(bm + srow) * EMB + k0 + scol*2;
      au0 = *(const uint4*)(Ap);
      au1 = *(const uint4*)(Ap + 8);
      const float* rp = rrbp + k0 + scol*2;
      float4 r0 = *(const float4*)(rp);
      float4 r1 = *(const float4*)(rp + 4);
      float4 r2 = *(const float4*)(rp + 8);
      float4 r3 = *(const float4*)(rp + 12);
      au0.x = hadd2u(au0.x, packh2(r0.x, r0.y));
      au0.y = hadd2u(au0.y, packh2(r0.z, r0.w));
      au0.z = hadd2u(au0.z, packh2(r1.x, r1.y));
      au0.w = hadd2u(au0.w, packh2(r1.z, r1.w));
      au1.x = hadd2u(au1.x, packh2(r2.x, r2.y));
      au1.y = hadd2u(au1.y, packh2(r2.z, r2.w));
      au1.z = hadd2u(au1.z, packh2(r3.x, r3.y));
      au1.w = hadd2u(au1.w, packh2(r3.z, r3.w));
    } else {
      const float* Ap = Af + (size_t)(bm + srow) * EMB + k0 + scol*2;
      float4 v0 = arow_ok ? *(const float4*)(Ap)      : make_float4(0,0,0,0);
      float4 v1 = arow_ok ? *(const float4*)(Ap + 4)  : make_float4(0,0,0,0);
      float4 v2 = arow_ok ? *(const float4*)(Ap + 8)  : make_float4(0,0,0,0);
      float4 v3 = arow_ok ? *(const float4*)(Ap + 12) : make_float4(0,0,0,0);
      au0 = make_uint4(packh2(v0.x,v0.y), packh2(v0.z,v0.w),
                       packh2(v1.x,v1.y), packh2(v1.z,v1.w));
      au1 = make_uint4(packh2(v2.x,v2.y), packh2(v2.z,v2.w),
                       packh2(v3.x,v3.y), packh2(v3.z,v3.w));
    }
  };

  auto sts_step = [&](int buf) {
    if (MODE != 0) {
      uint32_t* Ab = Asm + buf*GSZ + srow*GA_W + scol;
      *(uint4*)(Ab)     = au0;
      *(uint4*)(Ab + 4) = au1;
    }
  };

  issue_step(0, 0);
  sts_step(0);
  cpa_wait_all();
  __syncthreads();

  for (int s = 0; s < nsteps; s++) {
    int buf = s & 1;
    if (s + 1 < nsteps) issue_step(buf ^ 1, (s + 1) * 32);

    uint32_t Ab = Asm_sa + buf*GSZ*4;
    uint32_t Bb = Bsm_sa + buf*GSZ*4;
    uint32_t bf[4][4];
    #pragma unroll
    for (int j = 0; j < 4; j++)
      ldsm_x4(bf[j], Bb + ((wn0 + j*8 + lane7)*GA_W + bkw)*4);
    #pragma unroll
    for (int ks = 0; ks < 2; ks++) {
      uint32_t af[4][4];
      #pragma unroll
      for (int i = 0; i < 4; i++)
        ldsm_x4(af[i], Ab + ((wm0 + i*16 + rsel)*GA_W + akw + ks*8)*4);
      #pragma unroll
      for (int i = 0; i < 4; i++)
        #pragma unroll
        for (int j = 0; j < 4; j++)
          mma_h(acc[i][j], af[i], bf[j][ks*2], bf[j][ks*2+1]);
    }

    if (s + 1 < nsteps) {
      sts_step(buf ^ 1);
      cpa_wait_all();
    }
    __syncthreads();
  }

  if (MODE == 1) {
    int h = blockIdx.z;
    #pragma unroll
    for (int j = 0; j < 4; j++) {
      int col = bn + wn0 + j*8 + 2*c;
      #pragma unroll
      for (int i = 0; i < 4; i++) {
        #pragma unroll
        for (int rr = 0; rr < 2; rr++) {
          int r = bm + wm0 + i*16 + g + rr*8;
          int n = r >> 9, q = r & (LQ - 1);
          __half* rowp = g_BD + (((size_t)(n*NH + h) * LQ) + q) * LQ;
          int k0c = q + 511 - col;
          if (k0c >= 0 && k0c < LQ)
            rowp[k0c] = __float2half(acc[i][j][rr*2+0]);
          if (k0c - 1 >= 0 && k0c - 1 < LQ)
            rowp[k0c - 1] = __float2half(acc[i][j][rr*2+1]);
        }
      }
    }
  } else if (MODE == 0) {
    #pragma unroll
    for (int j = 0; j < 4; j++) {
      int col = bn + wn0 + j*8 + 2*c;
      float b0 = bias[col], b1 = bias[col + 1];
      #pragma unroll
      for (int i = 0; i < 4; i++) {
        int r0 = bm + wm0 + i*16 + g;
        *(float2*)(Cf + (size_t)r0 * EMB + col) =
            make_float2(acc[i][j][0] + b0, acc[i][j][1] + b1);
        int r1 = r0 + 8;
        *(float2*)(Cf + (size_t)r1 * EMB + col) =
            make_float2(acc[i][j][2] + b0, acc[i][j][3] + b1);
      }
    }
  } else {
    bool toR = (blockIdx.z == 3);
    #pragma unroll
    for (int j = 0; j < 4; j++) {
      int col = bn + wn0 + j*8 + 2*c;
      float b0 = bias[col], b1 = bias[col + 1];
      #pragma unroll
      for (int i = 0; i < 4; i++) {
        #pragma unroll
        for (int rr = 0; rr < 2; rr++) {
          int r = bm + wm0 + i*16 + g + rr*8;
          uint32_t w = packh2(acc[i][j][rr*2+0] + b0, acc[i][j][rr*2+1] + b1);
          if (toR) {
            if (r < NPOS) *(uint32_t*)(g_Rh + (size_t)r*EMB + col) = w;
          } else {
            *(uint32_t*)(Chf + (size_t)r*EMB + col) = w;
          }
        }
      }
    }
  }
}

// ---------------------------------------------------------------------------
// Tensor-core fused attention: fp16 operands, ldmatrix frag loads,
// cp.async K staging (FULL 8-chunk rows).
// ---------------------------------------------------------------------------
#define QH_W 36     // Qs/Ks row stride in words (32 data + 4 pad)
#define VS_W 72
#define ATTN_SMEM ((128*QH_W + 64*QH_W + 32*VS_W + 32) * 4)

__global__ __launch_bounds__(256) void attn_mma(const float* __restrict__ rwb)
{
  extern __shared__ uint32_t sm[];
  uint32_t* Qs   = sm;                   // [128][QH_W] fp16 pairs (rwb folded)
  uint32_t* Ks   = Qs + 128*QH_W;        // [64][QH_W]
  uint32_t* Vs   = Ks + 64*QH_W;         // [32][VS_W] h2 k-pairs
  uint32_t* rwbh = Vs + 32*VS_W;         // [32] h2
  uint32_t Qs_sa = (uint32_t)__cvta_generic_to_shared(Qs);
  uint32_t Ks_sa = (uint32_t)__cvta_generic_to_shared(Ks);

  int tid = threadIdx.x, lane = tid & 31, wid = tid >> 5;
  int g = lane >> 2, c = lane & 3;
  int lane7 = lane & 7, mat = lane >> 3;
  int rsel = (mat & 1) * 8 + lane7;
  int akw  = (mat >> 1) * 4;
  int bkw  = mat * 4;
  int b = blockIdx.x;
  int qt = b & 3; b >>= 2;
  int h = b % NH, n = b / NH;
  int q0 = qt * 128;
  int wm = wid * 16;

  if (tid < 32) {
    float2 r = *(const float2*)(rwb + h*DH + 2*tid);
    rwbh[tid] = packh2(r.x, r.y);
  }
  __syncthreads();

  // stage Q (fp16) + rwb : 128 rows x 8 chunks of 8 halfs (FULL row)
  const __half* Qg = g_Q + ((size_t)n*LQ + q0)*EMB + h*DH;
  for (int u = tid; u < 128*8; u += 256) {
    int r = u >> 3, ch = u & 7;
    uint4 v = *(const uint4*)(Qg + (size_t)r*EMB + ch*8);
    uint32_t* dst = Qs + r*QH_W + ch*4;
    dst[0] = hadd2u(v.x, rwbh[ch*4+0]);
    dst[1] = hadd2u(v.y, rwbh[ch*4+1]);
    dst[2] = hadd2u(v.z, rwbh[ch*4+2]);
    dst[3] = hadd2u(v.w, rwbh[ch*4+3]);
  }

  float oacc[8][4];
  #pragma unroll
  for (int j = 0; j < 8; j++)
    #pragma unroll
    for (int r = 0; r < 4; r++) oacc[j][r] = 0.f;
  float m_a = -1e30f, m_b = -1e30f, l_a = 0.f, l_b = 0.f;

  int qa = q0 + wm + g;
  const __half* bdra = g_BD + ((size_t)(n*NH + h)*LQ + qa)*LQ;
  const __half* bdrb = bdra + 8*LQ;

  for (int k0 = 0; k0 < LQ; k0 += 64) {
    const __half* Kg = g_K + ((size_t)n*LQ + k0)*EMB + h*DH;
    const __half* Vg = g_V + ((size_t)n*LQ + k0)*EMB + h*DH;
    // K tile via cp.async: 64 rows x 8 chunks of 16B (FULL row)
    for (int u = tid; u < 64*8; u += 256) {
      int r = u >> 3, ch = u & 7;
      cpa16(Ks_sa + (r*QH_W + ch*4)*4, Kg + (size_t)r*EMB + ch*8);
    }
    // V interleave: Vs[kpair][d] = h2(V[2k][d], V[2k+1][d])
    for (int u = tid; u < 32*16; u += 256) {
      int kk = u >> 4, dc = (u & 15) * 4;
      uint2 a  = *(const uint2*)(Vg + (size_t)(2*kk  )*EMB + dc);
      uint2 bb = *(const uint2*)(Vg + (size_t)(2*kk+1)*EMB + dc);
      uint32_t* dst = Vs + kk*VS_W + dc;
      dst[0] = __byte_perm(a.x, bb.x, 0x5410);
      dst[1] = __byte_perm(a.x, bb.x, 0x7632);
      dst[2] = __byte_perm(a.y, bb.y, 0x5410);
      dst[3] = __byte_perm(a.y, bb.y, 0x7632);
    }
    cpa_wait_all();
    __syncthreads();

    // init S from BD (fp16)
    float sacc[8][4];
    #pragma unroll
    for (int j = 0; j < 8; j++) {
      uint32_t w0 = *(const uint32_t*)(bdra + k0 + j*8 + 2*c);
      uint32_t w1 = *(const uint32_t*)(bdrb + k0 + j*8 + 2*c);
      float2 f0 = __half22float2(*(__half2*)&w0);
      float2 f1 = __half22float2(*(__half2*)&w1);
      sacc[j][0] = f0.x; sacc[j][1] = f0.y;
      sacc[j][2] = f1.x; sacc[j][3] = f1.y;
    }

    // S += (Q+rwb) . K^T   (fp16 m16n8k16, ldmatrix frags)
    uint32_t af[4][4];
    #pragma unroll
    for (int ks = 0; ks < 4; ks++)
      ldsm_x4(af[ks], Qs_sa + ((wm + rsel)*QH_W + akw + ks*8)*4);
    #pragma unroll
    for (int j = 0; j < 8; j++) {
      uint32_t bf[8];
      ldsm_x4(bf+0, Ks_sa + ((j*8 + lane7)*QH_W + bkw +  0)*4);
      ldsm_x4(bf+4, Ks_sa + ((j*8 + lane7)*QH_W + bkw + 16)*4);
      #pragma unroll
      for (int ks = 0; ks < 4; ks++)
        mma_h(sacc[j], af[ks], bf[ks*2], bf[ks*2+1]);
    }

    // online softmax
    float mx_a = -1e30f, mx_b = -1e30f;
    #pragma unroll
    for (int j = 0; j < 8; j++) {
      sacc[j][0] *= 0.125f; sacc[j][1] *= 0.125f;
      sacc[j][2] *= 0.125f; sacc[j][3] *= 0.125f;
      mx_a = fmaxf(mx_a, fmaxf(sacc[j][0], sacc[j][1]));
      mx_b = fmaxf(mx_b, fmaxf(sacc[j][2], sacc[j][3]));
    }
    mx_a = fmaxf(mx_a, __shfl_xor_sync(0xffffffffu, mx_a, 1));
    mx_a = fmaxf(mx_a, __shfl_xor_sync(0xffffffffu, mx_a, 2));
    mx_b = fmaxf(mx_b, __shfl_xor_sync(0xffffffffu, mx_b, 1));
    mx_b = fmaxf(mx_b, __shfl_xor_sync(0xffffffffu, mx_b, 2));
    float mna = fmaxf(m_a, mx_a), mnb = fmaxf(m_b, mx_b);
    float ca = __expf(m_a - mna), cb = __expf(m_b - mnb);
    m_a = mna; m_b = mnb;
    l_a *= ca; l_b *= cb;
    #pragma unroll
    for (int j = 0; j < 8; j++) {
      oacc[j][0] *= ca; oacc[j][1] *= ca;
      oacc[j][2] *= cb; oacc[j][3] *= cb;
    }
    #pragma unroll
    for (int j = 0; j < 8; j++) {
      sacc[j][0] = __expf(sacc[j][0] - m_a); l_a += sacc[j][0];
      sacc[j][1] = __expf(sacc[j][1] - m_a); l_a += sacc[j][1];
      sacc[j][2] = __expf(sacc[j][2] - m_b); l_b += sacc[j][2];
      sacc[j][3] = __expf(sacc[j][3] - m_b); l_b += sacc[j][3];
    }

    // O += P . V
    #pragma unroll
    for (int jj = 0; jj < 4; jj++) {
      uint32_t pa[4];
      pa[0] = packh2(sacc[2*jj  ][0], sacc[2*jj  ][1]);
      pa[1] = packh2(sacc[2*jj  ][2], sacc[2*jj  ][3]);
      pa[2] = packh2(sacc[2*jj+1][0], sacc[2*jj+1][1]);
      pa[3] = packh2(sacc[2*jj+1][2], sacc[2*jj+1][3]);
      #pragma unroll
      for (int jd = 0; jd < 8; jd++) {
        uint32_t b0 = Vs[(jj*8 + c    )*VS_W + jd*8 + g];
        uint32_t b1 = Vs[(jj*8 + c + 4)*VS_W + jd*8 + g];
        mma_h(oacc[jd], pa, b0, b1);
      }
    }
    __syncthreads();
  }

  l_a += __shfl_xor_sync(0xffffffffu, l_a, 1);
  l_a += __shfl_xor_sync(0xffffffffu, l_a, 2);
  l_b += __shfl_xor_sync(0xffffffffu, l_b, 1);
  l_b += __shfl_xor_sync(0xffffffffu, l_b, 2);
  float ia = 1.f / l_a, ib = 1.f / l_b;
  __half* oa = g_AO + ((size_t)n*LQ + qa)*EMB + h*DH;
  __half* ob = oa + 8*EMB;
  #pragma unroll
  for (int jd = 0; jd < 8; jd++) {
    *(uint32_t*)(oa + jd*8 + 2*c) = packh2(oacc[jd][0]*ia, oacc[jd][1]*ia);
    *(uint32_t*)(ob + jd*8 + 2*c) = packh2(oacc[jd][2]*ib, oacc[jd][3]*ib);
  }
}

// ---------------------------------------------------------------------------
extern "C" void kernel_launch(void* const* d_in, const int* in_sizes, int n_in,
                              void* d_out, int out_size) {
  (void)in_sizes; (void)n_in; (void)out_size;
  const float* values = (const float*)d_in[0];
  const float* keys   = (const float*)d_in[1];
  const float* query  = (const float*)d_in[2];
  const float* Wq   = (const float*)d_in[3];
  const float* bq   = (const float*)d_in[4];
  const float* Wk   = (const float*)d_in[5];
  const float* bk   = (const float*)d_in[6];
  const float* Wv   = (const float*)d_in[7];
  const float* bv   = (const float*)d_in[8];
  const float* Wo   = (const float*)d_in[9];
  const float* bo   = (const float*)d_in[10];
  const float* Wpos = (const float*)d_in[11];
  const float* bpos = (const float*)d_in[12];
  const float* rwb  = (const float*)d_in[13];
  const float* rrb  = (const float*)d_in[14];
  float* out = (float*)d_out;

  cudaFuncSetAttribute(gemm_h<0>, cudaFuncAttributeMaxDynamicSharedMemorySize,
                       GEMM_SMEM);
  cudaFuncSetAttribute(gemm_h<1>, cudaFuncAttributeMaxDynamicSharedMemorySize,
                       GEMM_SMEM);
  cudaFuncSetAttribute(gemm_h<2>, cudaFuncAttributeMaxDynamicSharedMemorySize,
                       GEMM_SMEM);
  cudaFuncSetAttribute(attn_mma, cudaFuncAttributeMaxDynamicSharedMemorySize,
                       ATTN_SMEM);

  // 1) sinusoid table
  pe_kernel<<<(NPOS*EMB + 255)/256, 256>>>();
  // 2) weight transpose+convert to fp16 [n][k]
  wconv5<<<dim3(24, 24, 5), dim3(32, 8)>>>(Wq, Wk, Wv, Wo, Wpos);
  // 3) batched Q/K/V projections + R = pe@Wpos, fp16 outputs
  gemm_h<2><<<dim3(6, 32, 4), 256, GEMM_SMEM>>>(
      query, keys, values, bq, bk, bv, bpos, nullptr);
  // 4) BD gemm: batched over heads, rrb folded at staging, fp16 scatter
  gemm_h<1><<<dim3(JPAD/128, 32, NH), 256, GEMM_SMEM>>>(
      nullptr, nullptr, nullptr, rrb, nullptr, nullptr, nullptr, nullptr);
  // 5) tensor-core fused attention (all fp16 operands)
  attn_mma<<<NB*NH*(LQ/128), 256, ATTN_SMEM>>>(rwb);
  // 6) output projection (f32 out)
  gemm_h<0><<<dim3(6, 32), 256, GEMM_SMEM>>>(
      nullptr, nullptr, nullptr, bo, nullptr, nullptr, nullptr, out);
}

// round 13
// speedup vs baseline: 5.3633x; 1.1297x over previous
#include <cuda_runtime.h>
#include <cuda_fp16.h>
#include <math.h>
#include <stdint.h>
#include <stddef.h>

#define NB   8
#define LQ   512
#define EMB  768
#define NH   12
#define DH   64
#define NPOS 1023   // 2*MAXLEN-1
#define JPAD 1024
#define WSZ  (EMB*EMB)

// ---------------- scratch (__device__ globals: allocation-free rule) --------
__device__ __align__(16) float  g_pe[NPOS*EMB];
__device__ __align__(16) __half g_Wh[5*WSZ];              // weights transposed [n][k] fp16
__device__ __align__(16) __half g_Rh[(size_t)JPAD*EMB];   // R[j][e] fp16 (row 1023 unused)
__device__ __align__(16) __half g_Q [NB*LQ*EMB];
__device__ __align__(16) __half g_K [NB*LQ*EMB];
__device__ __align__(16) __half g_V [NB*LQ*EMB];
__device__ __align__(16) __half g_BD[(size_t)NB*NH*LQ*LQ];
__device__ __align__(16) __half g_AO[NB*LQ*EMB];

__device__ __forceinline__ uint32_t packh2(float lo, float hi) {
  __half2 h = __floats2half2_rn(lo, hi);
  return *(uint32_t*)&h;
}
__device__ __forceinline__ uint32_t hadd2u(uint32_t a, uint32_t b) {
  __half2 r = __hadd2(*(__half2*)&a, *(__half2*)&b);
  return *(uint32_t*)&r;
}
__device__ __forceinline__ void ldsm_x4(uint32_t* r, uint32_t addr) {
  asm volatile("ldmatrix.sync.aligned.m8n8.x4.shared.b16 {%0,%1,%2,%3}, [%4];"
    : "=r"(r[0]), "=r"(r[1]), "=r"(r[2]), "=r"(r[3]) : "r"(addr));
}
__device__ __forceinline__ void cpa16(uint32_t dst, const void* src) {
  asm volatile("cp.async.cg.shared.global [%0], [%1], 16;" :: "r"(dst), "l"(src));
}
__device__ __forceinline__ void cpa_wait_all() {
  asm volatile("cp.async.wait_all;" ::: "memory");
}
__device__ __forceinline__ void mma_h(float* d, const uint32_t* a,
                                      uint32_t b0, uint32_t b1) {
  asm volatile(
    "mma.sync.aligned.m16n8k16.row.col.f32.f16.f16.f32 "
    "{%0,%1,%2,%3},{%4,%5,%6,%7},{%8,%9},{%0,%1,%2,%3};"
    : "+f"(d[0]), "+f"(d[1]), "+f"(d[2]), "+f"(d[3])
    : "r"(a[0]), "r"(a[1]), "r"(a[2]), "r"(a[3]), "r"(b0), "r"(b1));
}

// ---------------------------------------------------------------------------
__global__ void pe_kernel() {
  int idx = blockIdx.x * 256 + threadIdx.x;
  if (idx >= NPOS*EMB) return;
  int p = idx / EMB;
  int e = idx - p * EMB;
  int i2 = e & ~1;
  float div = expf(-(float)i2 * (9.210340371976184f / (float)EMB));
  float ang = (float)p * div;
  g_pe[idx] = (e & 1) ? cosf(ang) : sinf(ang);
}

// ---------------------------------------------------------------------------
__global__ void wconv5(const float* __restrict__ W0, const float* __restrict__ W1,
                       const float* __restrict__ W2, const float* __restrict__ W3,
                       const float* __restrict__ W4) {
  __shared__ float t[32][33];
  int z = blockIdx.z;
  const float* W = (z==0)?W0:(z==1)?W1:(z==2)?W2:(z==3)?W3:W4;
  __half* Wh = g_Wh + (size_t)z*WSZ;
  int k0 = blockIdx.x*32, n0 = blockIdx.y*32;
  int tx = threadIdx.x, ty = threadIdx.y;
  #pragma unroll
  for (int i = 0; i < 4; i++)
    t[ty+8*i][tx] = W[(size_t)(k0+ty+8*i)*EMB + n0+tx];
  __syncthreads();
  #pragma unroll
  for (int i = 0; i < 4; i++)
    Wh[(size_t)(n0+ty+8*i)*EMB + k0+tx] = __float2half(t[tx][ty+8*i]);
}

// ---------------------------------------------------------------------------
// fp16 MMA GEMM core, ldmatrix frag loads + cp.async staging.
// MODE 0: out-proj  (A=g_AO fp16, B=Wh[3], bias=bo, C f32 -> Cout)
// MODE 1: BD gemm   (A=g_Q+h*64 with rrb folded at staging, B=g_Rh+h*64,
//                    coalesced smem-staged scatter -> g_BD; b0p carries rrb)
// MODE 2: QKV+R over z (A f32; z<3 -> g_Q/K/V fp16; z=3 -> g_Rh fp16)
// ---------------------------------------------------------------------------
#define GA_W 20
#define GSZ  (128*GA_W)
#define GEMM_SMEM (4*GSZ*4)
#define CS_W 132   // epilogue smem row stride in halfs

template<int MODE>
__global__ __launch_bounds__(256, 2) void gemm_h(
    const float* __restrict__ Aq, const float* __restrict__ Ak,
    const float* __restrict__ Av,
    const float* __restrict__ b0p, const float* __restrict__ b1p,
    const float* __restrict__ b2p, const float* __restrict__ b3p,
    float* __restrict__ Cout)
{
  extern __shared__ uint32_t sm[];
  uint32_t* Asm = sm;            // [2][128][GA_W]
  uint32_t* Bsm = sm + 2*GSZ;    // [2][128][GA_W]
  uint32_t Asm_sa = (uint32_t)__cvta_generic_to_shared(Asm);
  uint32_t Bsm_sa = (uint32_t)__cvta_generic_to_shared(Bsm);

  int tid = threadIdx.x, lane = tid & 31, wid = tid >> 5;
  int g = lane >> 2, c = lane & 3;
  int lane7 = lane & 7, mat = lane >> 3;
  int rsel = (mat & 1) * 8 + lane7;       // A-frag row select
  int akw  = (mat >> 1) * 4;              // A-frag k-word offset
  int bkw  = mat * 4;                     // B-frag k-word offset
  int wm0 = (wid >> 2) * 64, wn0 = (wid & 3) * 32;
  int bm = blockIdx.y * 128, bn = blockIdx.x * 128;

  const __half* Ah = nullptr; const float* Af = nullptr;
  const __half* Bh; const float* bias = nullptr;
  const float* rrbp = nullptr;
  float* Cf = nullptr; __half* Chf = nullptr;
  int Mg = 1 << 30;
  constexpr int K = (MODE == 1) ? 64 : 768;
  constexpr int nsteps = K / 32;

  if (MODE == 0) {
    Ah = g_AO; Bh = g_Wh + 3*WSZ; bias = b0p; Cf = Cout;
  } else if (MODE == 1) {
    int h = blockIdx.z;
    Ah = g_Q + h*DH; Bh = g_Rh + h*DH; rrbp = b0p + h*DH;
    int q0 = bm & (LQ - 1);
    if (bn > q0 + 638 || bn + 127 < q0) return;
  } else {
    int z = blockIdx.z;
    if (z == 0)      { Af = Aq; bias = b0p; Chf = g_Q; Bh = g_Wh; }
    else if (z == 1) { Af = Ak; bias = b1p; Chf = g_K; Bh = g_Wh + WSZ; }
    else if (z == 2) { Af = Av; bias = b2p; Chf = g_V; Bh = g_Wh + 2*WSZ; }
    else {
      if (blockIdx.y >= 8) return;
      Af = g_pe; bias = b3p; Bh = g_Wh + 4*WSZ; Mg = NPOS;
    }
  }

  int srow = tid >> 1;            // staging row 0..127
  int scol = (tid & 1) * 8;       // staging word offset (8 words = 16 halfs)
  bool arow_ok = (bm + srow) < Mg;

  float acc[4][4][4];
  #pragma unroll
  for (int i = 0; i < 4; i++)
    #pragma unroll
    for (int j = 0; j < 4; j++)
      #pragma unroll
      for (int r = 0; r < 4; r++) acc[i][j][r] = 0.f;

  uint4 au0, au1;   // MODE 1/2: staged A words

  auto issue_step = [&](int buf, int k0) {
    #pragma unroll
    for (int it = 0; it < 2; it++) {
      int ch = (tid & 1) * 2 + it;
      cpa16(Bsm_sa + (buf*GSZ + srow*GA_W + ch*4)*4,
            Bh + (size_t)(bn + srow) * EMB + k0 + ch*8);
    }
    if (MODE == 0) {
      #pragma unroll
      for (int it = 0; it < 2; it++) {
        int ch = (tid & 1) * 2 + it;
        cpa16(Asm_sa + (buf*GSZ + srow*GA_W + ch*4)*4,
              Ah + (size_t)(bm + srow) * EMB + k0 + ch*8);
      }
    } else if (MODE == 1) {
      const __half* Ap = Ah + (size_t)(bm + srow) * EMB + k0 + scol*2;
      au0 = *(const uint4*)(Ap);
      au1 = *(const uint4*)(Ap + 8);
      const float* rp = rrbp + k0 + scol*2;
      float4 r0 = *(const float4*)(rp);
      float4 r1 = *(const float4*)(rp + 4);
      float4 r2 = *(const float4*)(rp + 8);
      float4 r3 = *(const float4*)(rp + 12);
      au0.x = hadd2u(au0.x, packh2(r0.x, r0.y));
      au0.y = hadd2u(au0.y, packh2(r0.z, r0.w));
      au0.z = hadd2u(au0.z, packh2(r1.x, r1.y));
      au0.w = hadd2u(au0.w, packh2(r1.z, r1.w));
      au1.x = hadd2u(au1.x, packh2(r2.x, r2.y));
      au1.y = hadd2u(au1.y, packh2(r2.z, r2.w));
      au1.z = hadd2u(au1.z, packh2(r3.x, r3.y));
      au1.w = hadd2u(au1.w, packh2(r3.z, r3.w));
    } else {
      const float* Ap = Af + (size_t)(bm + srow) * EMB + k0 + scol*2;
      float4 v0 = arow_ok ? *(const float4*)(Ap)      : make_float4(0,0,0,0);
      float4 v1 = arow_ok ? *(const float4*)(Ap + 4)  : make_float4(0,0,0,0);
      float4 v2 = arow_ok ? *(const float4*)(Ap + 8)  : make_float4(0,0,0,0);
      float4 v3 = arow_ok ? *(const float4*)(Ap + 12) : make_float4(0,0,0,0);
      au0 = make_uint4(packh2(v0.x,v0.y), packh2(v0.z,v0.w),
                       packh2(v1.x,v1.y), packh2(v1.z,v1.w));
      au1 = make_uint4(packh2(v2.x,v2.y), packh2(v2.z,v2.w),
                       packh2(v3.x,v3.y), packh2(v3.z,v3.w));
    }
  };

  auto sts_step = [&](int buf) {
    if (MODE != 0) {
      uint32_t* Ab = Asm + buf*GSZ + srow*GA_W + scol;
      *(uint4*)(Ab)     = au0;
      *(uint4*)(Ab + 4) = au1;
    }
  };

  issue_step(0, 0);
  sts_step(0);
  cpa_wait_all();
  __syncthreads();

  for (int s = 0; s < nsteps; s++) {
    int buf = s & 1;
    if (s + 1 < nsteps) issue_step(buf ^ 1, (s + 1) * 32);

    uint32_t Ab = Asm_sa + buf*GSZ*4;
    uint32_t Bb = Bsm_sa + buf*GSZ*4;
    uint32_t bf[4][4];
    #pragma unroll
    for (int j = 0; j < 4; j++)
      ldsm_x4(bf[j], Bb + ((wn0 + j*8 + lane7)*GA_W + bkw)*4);
    #pragma unroll
    for (int ks = 0; ks < 2; ks++) {
      uint32_t af[4][4];
      #pragma unroll
      for (int i = 0; i < 4; i++)
        ldsm_x4(af[i], Ab + ((wm0 + i*16 + rsel)*GA_W + akw + ks*8)*4);
      #pragma unroll
      for (int i = 0; i < 4; i++)
        #pragma unroll
        for (int j = 0; j < 4; j++)
          mma_h(acc[i][j], af[i], bf[j][ks*2], bf[j][ks*2+1]);
    }

    if (s + 1 < nsteps) {
      sts_step(buf ^ 1);
      cpa_wait_all();
    }
    __syncthreads();
  }

  if (MODE == 1) {
    // --- coalesced BD scatter: stage C tile in smem, then aligned STG.128 ---
    int h = blockIdx.z;
    __half* Csm = (__half*)sm;   // [128][CS_W], 33.8 KB (reuses staging smem)
    #pragma unroll
    for (int j = 0; j < 4; j++) {
      int colp = wn0 + j*8 + 2*c;
      #pragma unroll
      for (int i = 0; i < 4; i++) {
        #pragma unroll
        for (int rr = 0; rr < 2; rr++) {
          int rloc = wm0 + i*16 + g + rr*8;
          *(uint32_t*)(Csm + rloc*CS_W + colp) =
              packh2(acc[i][j][rr*2+0], acc[i][j][rr*2+1]);
        }
      }
    }
    __syncthreads();
    // writeback: 8 threads per row along k, 32 rows per pass, 4 passes
    int tsub = tid & 7;          // 0..7 (chunk lane within row)
    int rbase = tid >> 3;        // 0..31
    #pragma unroll
    for (int ps = 0; ps < 4; ps++) {
      int r = ps*32 + rbase;
      int q = (bm + r) & (LQ - 1);
      int n = (bm + r) >> 9;
      __half* rowp = g_BD + (((size_t)(n*NH + h) * LQ) + q) * LQ;
      const __half* srowp = Csm + r*CS_W;
      int kbase = q + 511 - bn;                  // k at colp=0 ; colp = kbase - k
      int klo = max(0, kbase - 127);
      int khi = min(LQ - 1, kbase);
      for (int k8 = (klo & ~7) + tsub*8; k8 <= khi; k8 += 64) {
        if (k8 >= klo && k8 + 7 <= khi) {
          __half tmp[8];
          #pragma unroll
          for (int t = 0; t < 8; t++) tmp[t] = srowp[kbase - (k8 + t)];
          *(uint4*)(rowp + k8) = *(uint4*)tmp;
        } else {
          #pragma unroll
          for (int t = 0; t < 8; t++) {
            int k = k8 + t;
            if (k >= klo && k <= khi) rowp[k] = srowp[kbase - k];
          }
        }
      }
    }
  } else if (MODE == 0) {
    #pragma unroll
    for (int j = 0; j < 4; j++) {
      int col = bn + wn0 + j*8 + 2*c;
      float b0 = bias[col], b1 = bias[col + 1];
      #pragma unroll
      for (int i = 0; i < 4; i++) {
        int r0 = bm + wm0 + i*16 + g;
        *(float2*)(Cf + (size_t)r0 * EMB + col) =
            make_float2(acc[i][j][0] + b0, acc[i][j][1] + b1);
        int r1 = r0 + 8;
        *(float2*)(Cf + (size_t)r1 * EMB + col) =
            make_float2(acc[i][j][2] + b0, acc[i][j][3] + b1);
      }
    }
  } else {
    bool toR = (blockIdx.z == 3);
    #pragma unroll
    for (int j = 0; j < 4; j++) {
      int col = bn + wn0 + j*8 + 2*c;
      float b0 = bias[col], b1 = bias[col + 1];
      #pragma unroll
      for (int i = 0; i < 4; i++) {
        #pragma unroll
        for (int rr = 0; rr < 2; rr++) {
          int r = bm + wm0 + i*16 + g + rr*8;
          uint32_t w = packh2(acc[i][j][rr*2+0] + b0, acc[i][j][rr*2+1] + b1);
          if (toR) {
            if (r < NPOS) *(uint32_t*)(g_Rh + (size_t)r*EMB + col) = w;
          } else {
            *(uint32_t*)(Chf + (size_t)r*EMB + col) = w;
          }
        }
      }
    }
  }
}

// ---------------------------------------------------------------------------
// Tensor-core fused attention: fp16 operands, ldmatrix frag loads,
// cp.async K staging (FULL 8-chunk rows).
// ---------------------------------------------------------------------------
#define QH_W 36     // Qs/Ks row stride in words (32 data + 4 pad)
#define VS_W 72
#define ATTN_SMEM ((128*QH_W + 64*QH_W + 32*VS_W + 32) * 4)

__global__ __launch_bounds__(256) void attn_mma(const float* __restrict__ rwb)
{
  extern __shared__ uint32_t sm[];
  uint32_t* Qs   = sm;                   // [128][QH_W] fp16 pairs (rwb folded)
  uint32_t* Ks   = Qs + 128*QH_W;        // [64][QH_W]
  uint32_t* Vs   = Ks + 64*QH_W;         // [32][VS_W] h2 k-pairs
  uint32_t* rwbh = Vs + 32*VS_W;         // [32] h2
  uint32_t Qs_sa = (uint32_t)__cvta_generic_to_shared(Qs);
  uint32_t Ks_sa = (uint32_t)__cvta_generic_to_shared(Ks);

  int tid = threadIdx.x, lane = tid & 31, wid = tid >> 5;
  int g = lane >> 2, c = lane & 3;
  int lane7 = lane & 7, mat = lane >> 3;
  int rsel = (mat & 1) * 8 + lane7;
  int akw  = (mat >> 1) * 4;
  int bkw  = mat * 4;
  int b = blockIdx.x;
  int qt = b & 3; b >>= 2;
  int h = b % NH, n = b / NH;
  int q0 = qt * 128;
  int wm = wid * 16;

  if (tid < 32) {
    float2 r = *(const float2*)(rwb + h*DH + 2*tid);
    rwbh[tid] = packh2(r.x, r.y);
  }
  __syncthreads();

  // stage Q (fp16) + rwb : 128 rows x 8 chunks of 8 halfs (FULL row)
  const __half* Qg = g_Q + ((size_t)n*LQ + q0)*EMB + h*DH;
  for (int u = tid; u < 128*8; u += 256) {
    int r = u >> 3, ch = u & 7;
    uint4 v = *(const uint4*)(Qg + (size_t)r*EMB + ch*8);
    uint32_t* dst = Qs + r*QH_W + ch*4;
    dst[0] = hadd2u(v.x, rwbh[ch*4+0]);
    dst[1] = hadd2u(v.y, rwbh[ch*4+1]);
    dst[2] = hadd2u(v.z, rwbh[ch*4+2]);
    dst[3] = hadd2u(v.w, rwbh[ch*4+3]);
  }

  float oacc[8][4];
  #pragma unroll
  for (int j = 0; j < 8; j++)
    #pragma unroll
    for (int r = 0; r < 4; r++) oacc[j][r] = 0.f;
  float m_a = -1e30f, m_b = -1e30f, l_a = 0.f, l_b = 0.f;

  int qa = q0 + wm + g;
  const __half* bdra = g_BD + ((size_t)(n*NH + h)*LQ + qa)*LQ;
  const __half* bdrb = bdra + 8*LQ;

  for (int k0 = 0; k0 < LQ; k0 += 64) {
    const __half* Kg = g_K + ((size_t)n*LQ + k0)*EMB + h*DH;
    const __half* Vg = g_V + ((size_t)n*LQ + k0)*EMB + h*DH;
    // K tile via cp.async: 64 rows x 8 chunks of 16B (FULL row)
    for (int u = tid; u < 64*8; u += 256) {
      int r = u >> 3, ch = u & 7;
      cpa16(Ks_sa + (r*QH_W + ch*4)*4, Kg + (size_t)r*EMB + ch*8);
    }
    // V interleave: Vs[kpair][d] = h2(V[2k][d], V[2k+1][d])
    for (int u = tid; u < 32*16; u += 256) {
      int kk = u >> 4, dc = (u & 15) * 4;
      uint2 a  = *(const uint2*)(Vg + (size_t)(2*kk  )*EMB + dc);
      uint2 bb = *(const uint2*)(Vg + (size_t)(2*kk+1)*EMB + dc);
      uint32_t* dst = Vs + kk*VS_W + dc;
      dst[0] = __byte_perm(a.x, bb.x, 0x5410);
      dst[1] = __byte_perm(a.x, bb.x, 0x7632);
      dst[2] = __byte_perm(a.y, bb.y, 0x5410);
      dst[3] = __byte_perm(a.y, bb.y, 0x7632);
    }
    cpa_wait_all();
    __syncthreads();

    // init S from BD (fp16)
    float sacc[8][4];
    #pragma unroll
    for (int j = 0; j < 8; j++) {
      uint32_t w0 = *(const uint32_t*)(bdra + k0 + j*8 + 2*c);
      uint32_t w1 = *(const uint32_t*)(bdrb + k0 + j*8 + 2*c);
      float2 f0 = __half22float2(*(__half2*)&w0);
      float2 f1 = __half22float2(*(__half2*)&w1);
      sacc[j][0] = f0.x; sacc[j][1] = f0.y;
      sacc[j][2] = f1.x; sacc[j][3] = f1.y;
    }

    // S += (Q+rwb) . K^T   (fp16 m16n8k16, ldmatrix frags)
    uint32_t af[4][4];
    #pragma unroll
    for (int ks = 0; ks < 4; ks++)
      ldsm_x4(af[ks], Qs_sa + ((wm + rsel)*QH_W + akw + ks*8)*4);
    #pragma unroll
    for (int j = 0; j < 8; j++) {
      uint32_t bf[8];
      ldsm_x4(bf+0, Ks_sa + ((j*8 + lane7)*QH_W + bkw +  0)*4);
      ldsm_x4(bf+4, Ks_sa + ((j*8 + lane7)*QH_W + bkw + 16)*4);
      #pragma unroll
      for (int ks = 0; ks < 4; ks++)
        mma_h(sacc[j], af[ks], bf[ks*2], bf[ks*2+1]);
    }

    // online softmax
    float mx_a = -1e30f, mx_b = -1e30f;
    #pragma unroll
    for (int j = 0; j < 8; j++) {
      sacc[j][0] *= 0.125f; sacc[j][1] *= 0.125f;
      sacc[j][2] *= 0.125f; sacc[j][3] *= 0.125f;
      mx_a = fmaxf(mx_a, fmaxf(sacc[j][0], sacc[j][1]));
      mx_b = fmaxf(mx_b, fmaxf(sacc[j][2], sacc[j][3]));
    }
    mx_a = fmaxf(mx_a, __shfl_xor_sync(0xffffffffu, mx_a, 1));
    mx_a = fmaxf(mx_a, __shfl_xor_sync(0xffffffffu, mx_a, 2));
    mx_b = fmaxf(mx_b, __shfl_xor_sync(0xffffffffu, mx_b, 1));
    mx_b = fmaxf(mx_b, __shfl_xor_sync(0xffffffffu, mx_b, 2));
    float mna = fmaxf(m_a, mx_a), mnb = fmaxf(m_b, mx_b);
    float ca = __expf(m_a - mna), cb = __expf(m_b - mnb);
    m_a = mna; m_b = mnb;
    l_a *= ca; l_b *= cb;
    #pragma unroll
    for (int j = 0; j < 8; j++) {
      oacc[j][0] *= ca; oacc[j][1] *= ca;
      oacc[j][2] *= cb; oacc[j][3] *= cb;
    }
    #pragma unroll
    for (int j = 0; j < 8; j++) {
      sacc[j][0] = __expf(sacc[j][0] - m_a); l_a += sacc[j][0];
      sacc[j][1] = __expf(sacc[j][1] - m_a); l_a += sacc[j][1];
      sacc[j][2] = __expf(sacc[j][2] - m_b); l_b += sacc[j][2];
      sacc[j][3] = __expf(sacc[j][3] - m_b); l_b += sacc[j][3];
    }

    // O += P . V
    #pragma unroll
    for (int jj = 0; jj < 4; jj++) {
      uint32_t pa[4];
      pa[0] = packh2(sacc[2*jj  ][0], sacc[2*jj  ][1]);
      pa[1] = packh2(sacc[2*jj  ][2], sacc[2*jj  ][3]);
      pa[2] = packh2(sacc[2*jj+1][0], sacc[2*jj+1][1]);
      pa[3] = packh2(sacc[2*jj+1][2], sacc[2*jj+1][3]);
      #pragma unroll
      for (int jd = 0; jd < 8; jd++) {
        uint32_t b0 = Vs[(jj*8 + c    )*VS_W + jd*8 + g];
        uint32_t b1 = Vs[(jj*8 + c + 4)*VS_W + jd*8 + g];
        mma_h(oacc[jd], pa, b0, b1);
      }
    }
    __syncthreads();
  }

  l_a += __shfl_xor_sync(0xffffffffu, l_a, 1);
  l_a += __shfl_xor_sync(0xffffffffu, l_a, 2);
  l_b += __shfl_xor_sync(0xffffffffu, l_b, 1);
  l_b += __shfl_xor_sync(0xffffffffu, l_b, 2);
  float ia = 1.f / l_a, ib = 1.f / l_b;
  __half* oa = g_AO + ((size_t)n*LQ + qa)*EMB + h*DH;
  __half* ob = oa + 8*EMB;
  #pragma unroll
  for (int jd = 0; jd < 8; jd++) {
    *(uint32_t*)(oa + jd*8 + 2*c) = packh2(oacc[jd][0]*ia, oacc[jd][1]*ia);
    *(uint32_t*)(ob + jd*8 + 2*c) = packh2(oacc[jd][2]*ib, oacc[jd][3]*ib);
  }
}

// ---------------------------------------------------------------------------
extern "C" void kernel_launch(void* const* d_in, const int* in_sizes, int n_in,
                              void* d_out, int out_size) {
  (void)in_sizes; (void)n_in; (void)out_size;
  const float* values = (const float*)d_in[0];
  const float* keys   = (const float*)d_in[1];
  const float* query  = (const float*)d_in[2];
  const float* Wq   = (const float*)d_in[3];
  const float* bq   = (const float*)d_in[4];
  const float* Wk   = (const float*)d_in[5];
  const float* bk   = (const float*)d_in[6];
  const float* Wv   = (const float*)d_in[7];
  const float* bv   = (const float*)d_in[8];
  const float* Wo   = (const float*)d_in[9];
  const float* bo   = (const float*)d_in[10];
  const float* Wpos = (const float*)d_in[11];
  const float* bpos = (const float*)d_in[12];
  const float* rwb  = (const float*)d_in[13];
  const float* rrb  = (const float*)d_in[14];
  float* out = (float*)d_out;

  cudaFuncSetAttribute(gemm_h<0>, cudaFuncAttributeMaxDynamicSharedMemorySize,
                       GEMM_SMEM);
  cudaFuncSetAttribute(gemm_h<1>, cudaFuncAttributeMaxDynamicSharedMemorySize,
                       GEMM_SMEM);
  cudaFuncSetAttribute(gemm_h<2>, cudaFuncAttributeMaxDynamicSharedMemorySize,
                       GEMM_SMEM);
  cudaFuncSetAttribute(attn_mma, cudaFuncAttributeMaxDynamicSharedMemorySize,
                       ATTN_SMEM);

  // 1) sinusoid table
  pe_kernel<<<(NPOS*EMB + 255)/256, 256>>>();
  // 2) weight transpose+convert to fp16 [n][k]
  wconv5<<<dim3(24, 24, 5), dim3(32, 8)>>>(Wq, Wk, Wv, Wo, Wpos);
  // 3) batched Q/K/V projections + R = pe@Wpos, fp16 outputs
  gemm_h<2><<<dim3(6, 32, 4), 256, GEMM_SMEM>>>(
      query, keys, values, bq, bk, bv, bpos, nullptr);
  // 4) BD gemm: batched over heads, rrb folded at staging, coalesced scatter
  gemm_h<1><<<dim3(JPAD/128, 32, NH), 256, GEMM_SMEM>>>(
      nullptr, nullptr, nullptr, rrb, nullptr, nullptr, nullptr, nullptr);
  // 5) tensor-core fused attention (all fp16 operands)
  attn_mma<<<NB*NH*(LQ/128), 256, ATTN_SMEM>>>(rwb);
  // 6) output projection (f32 out)
  gemm_h<0><<<dim3(6, 32), 256, GEMM_SMEM>>>(
      nullptr, nullptr, nullptr, bo, nullptr, nullptr, nullptr, out);
}

// round 15
// speedup vs baseline: 5.3640x; 1.0001x over previous
#include <cuda_runtime.h>
#include <cuda_fp16.h>
#include <math.h>
#include <stdint.h>
#include <stddef.h>

#define NB   8
#define LQ   512
#define EMB  768
#define NH   12
#define DH   64
#define NPOS 1023   // 2*MAXLEN-1
#define JPAD 1024
#define WSZ  (EMB*EMB)

// ---------------- scratch (__device__ globals: allocation-free rule) --------
__device__ __align__(16) float  g_pe[NPOS*EMB];
__device__ __align__(16) __half g_Wh[5*WSZ];              // weights transposed [n][k] fp16
__device__ __align__(16) __half g_Rh[(size_t)JPAD*EMB];   // R[j][e] fp16 (row 1023 zeroed)
__device__ __align__(16) __half g_Q [NB*LQ*EMB];
__device__ __align__(16) __half g_K [NB*LQ*EMB];
__device__ __align__(16) __half g_V [NB*LQ*EMB];
__device__ __align__(16) __half g_BD[(size_t)NB*NH*LQ*LQ];
__device__ __align__(16) __half g_AO[NB*LQ*EMB];

__device__ __forceinline__ uint32_t packh2(float lo, float hi) {
  __half2 h = __floats2half2_rn(lo, hi);
  return *(uint32_t*)&h;
}
__device__ __forceinline__ uint32_t hadd2u(uint32_t a, uint32_t b) {
  __half2 r = __hadd2(*(__half2*)&a, *(__half2*)&b);
  return *(uint32_t*)&r;
}
__device__ __forceinline__ void ldsm_x4(uint32_t* r, uint32_t addr) {
  asm volatile("ldmatrix.sync.aligned.m8n8.x4.shared.b16 {%0,%1,%2,%3}, [%4];"
    : "=r"(r[0]), "=r"(r[1]), "=r"(r[2]), "=r"(r[3]) : "r"(addr));
}
__device__ __forceinline__ void cpa16(uint32_t dst, const void* src) {
  asm volatile("cp.async.cg.shared.global [%0], [%1], 16;" :: "r"(dst), "l"(src));
}
__device__ __forceinline__ void cpa_wait_all() {
  asm volatile("cp.async.wait_all;" ::: "memory");
}
__device__ __forceinline__ void mma_h(float* d, const uint32_t* a,
                                      uint32_t b0, uint32_t b1) {
  asm volatile(
    "mma.sync.aligned.m16n8k16.row.col.f32.f16.f16.f32 "
    "{%0,%1,%2,%3},{%4,%5,%6,%7},{%8,%9},{%0,%1,%2,%3};"
    : "+f"(d[0]), "+f"(d[1]), "+f"(d[2]), "+f"(d[3])
    : "r"(a[0]), "r"(a[1]), "r"(a[2]), "r"(a[3]), "r"(b0), "r"(b1));
}

// ---------------------------------------------------------------------------
__global__ void pe_kernel() {
  int idx = blockIdx.x * 256 + threadIdx.x;
  if (idx >= NPOS*EMB) return;
  int p = idx / EMB;
  int e = idx - p * EMB;
  int i2 = e & ~1;
  float div = expf(-(float)i2 * (9.210340371976184f / (float)EMB));
  float ang = (float)p * div;
  g_pe[idx] = (e & 1) ? cosf(ang) : sinf(ang);
}

// ---------------------------------------------------------------------------
__global__ void wconv5(const float* __restrict__ W0, const float* __restrict__ W1,
                       const float* __restrict__ W2, const float* __restrict__ W3,
                       const float* __restrict__ W4) {
  __shared__ float t[32][33];
  int z = blockIdx.z;
  const float* W = (z==0)?W0:(z==1)?W1:(z==2)?W2:(z==3)?W3:W4;
  __half* Wh = g_Wh + (size_t)z*WSZ;
  int k0 = blockIdx.x*32, n0 = blockIdx.y*32;
  int tx = threadIdx.x, ty = threadIdx.y;
  #pragma unroll
  for (int i = 0; i < 4; i++)
    t[ty+8*i][tx] = W[(size_t)(k0+ty+8*i)*EMB + n0+tx];
  __syncthreads();
  #pragma unroll
  for (int i = 0; i < 4; i++)
    Wh[(size_t)(n0+ty+8*i)*EMB + k0+tx] = __float2half(t[tx][ty+8*i]);
}

// ---------------------------------------------------------------------------
// fp16 MMA GEMM core, ldmatrix frag loads + cp.async staging.
// MODE 0: out-proj  (A=g_AO fp16, B=Wh[3], bias=bo, C f32 -> Cout)
// MODE 2: QKV+R over z (A f32; z<3 -> g_Q/K/V fp16; z=3 -> g_Rh fp16)
// ---------------------------------------------------------------------------
#define GA_W 20
#define GSZ  (128*GA_W)
#define GEMM_SMEM (4*GSZ*4)

template<int MODE>
__global__ __launch_bounds__(256, 2) void gemm_h(
    const float* __restrict__ Aq, const float* __restrict__ Ak,
    const float* __restrict__ Av,
    const float* __restrict__ b0p, const float* __restrict__ b1p,
    const float* __restrict__ b2p, const float* __restrict__ b3p,
    float* __restrict__ Cout)
{
  extern __shared__ uint32_t sm[];
  uint32_t* Asm = sm;            // [2][128][GA_W]
  uint32_t* Bsm = sm + 2*GSZ;    // [2][128][GA_W]
  uint32_t Asm_sa = (uint32_t)__cvta_generic_to_shared(Asm);
  uint32_t Bsm_sa = (uint32_t)__cvta_generic_to_shared(Bsm);

  int tid = threadIdx.x, lane = tid & 31, wid = tid >> 5;
  int g = lane >> 2, c = lane & 3;
  int lane7 = lane & 7, mat = lane >> 3;
  int rsel = (mat & 1) * 8 + lane7;
  int akw  = (mat >> 1) * 4;
  int bkw  = mat * 4;
  int wm0 = (wid >> 2) * 64, wn0 = (wid & 3) * 32;
  int bm = blockIdx.y * 128, bn = blockIdx.x * 128;

  const __half* Ah = nullptr; const float* Af = nullptr;
  const __half* Bh; const float* bias = nullptr;
  float* Cf = nullptr; __half* Chf = nullptr;
  int Mg = 1 << 30;
  constexpr int nsteps = 24;   // K = 768

  if (MODE == 0) {
    Ah = g_AO; Bh = g_Wh + 3*WSZ; bias = b0p; Cf = Cout;
  } else {
    int z = blockIdx.z;
    if (z == 0)      { Af = Aq; bias = b0p; Chf = g_Q; Bh = g_Wh; }
    else if (z == 1) { Af = Ak; bias = b1p; Chf = g_K; Bh = g_Wh + WSZ; }
    else if (z == 2) { Af = Av; bias = b2p; Chf = g_V; Bh = g_Wh + 2*WSZ; }
    else {
      if (blockIdx.y >= 8) return;
      Af = g_pe; bias = b3p; Bh = g_Wh + 4*WSZ; Mg = NPOS;
    }
  }

  int srow = tid >> 1;
  int scol = (tid & 1) * 8;
  bool arow_ok = (bm + srow) < Mg;

  float acc[4][4][4];
  #pragma unroll
  for (int i = 0; i < 4; i++)
    #pragma unroll
    for (int j = 0; j < 4; j++)
      #pragma unroll
      for (int r = 0; r < 4; r++) acc[i][j][r] = 0.f;

  uint4 au0, au1;

  auto issue_step = [&](int buf, int k0) {
    #pragma unroll
    for (int it = 0; it < 2; it++) {
      int ch = (tid & 1) * 2 + it;
      cpa16(Bsm_sa + (buf*GSZ + srow*GA_W + ch*4)*4,
            Bh + (size_t)(bn + srow) * EMB + k0 + ch*8);
    }
    if (MODE == 0) {
      #pragma unroll
      for (int it = 0; it < 2; it++) {
        int ch = (tid & 1) * 2 + it;
        cpa16(Asm_sa + (buf*GSZ + srow*GA_W + ch*4)*4,
              Ah + (size_t)(bm + srow) * EMB + k0 + ch*8);
      }
    } else {
      const float* Ap = Af + (size_t)(bm + srow) * EMB + k0 + scol*2;
      float4 v0 = arow_ok ? *(const float4*)(Ap)      : make_float4(0,0,0,0);
      float4 v1 = arow_ok ? *(const float4*)(Ap + 4)  : make_float4(0,0,0,0);
      float4 v2 = arow_ok ? *(const float4*)(Ap + 8)  : make_float4(0,0,0,0);
      float4 v3 = arow_ok ? *(const float4*)(Ap + 12) : make_float4(0,0,0,0);
      au0 = make_uint4(packh2(v0.x,v0.y), packh2(v0.z,v0.w),
                       packh2(v1.x,v1.y), packh2(v1.z,v1.w));
      au1 = make_uint4(packh2(v2.x,v2.y), packh2(v2.z,v2.w),
                       packh2(v3.x,v3.y), packh2(v3.z,v3.w));
    }
  };

  auto sts_step = [&](int buf) {
    if (MODE != 0) {
      uint32_t* Ab = Asm + buf*GSZ + srow*GA_W + scol;
      *(uint4*)(Ab)     = au0;
      *(uint4*)(Ab + 4) = au1;
    }
  };

  issue_step(0, 0);
  sts_step(0);
  cpa_wait_all();
  __syncthreads();

  for (int s = 0; s < nsteps; s++) {
    int buf = s & 1;
    if (s + 1 < nsteps) issue_step(buf ^ 1, (s + 1) * 32);

    uint32_t Ab = Asm_sa + buf*GSZ*4;
    uint32_t Bb = Bsm_sa + buf*GSZ*4;
    uint32_t bf[4][4];
    #pragma unroll
    for (int j = 0; j < 4; j++)
      ldsm_x4(bf[j], Bb + ((wn0 + j*8 + lane7)*GA_W + bkw)*4);
    #pragma unroll
    for (int ks = 0; ks < 2; ks++) {
      uint32_t af[4][4];
      #pragma unroll
      for (int i = 0; i < 4; i++)
        ldsm_x4(af[i], Ab + ((wm0 + i*16 + rsel)*GA_W + akw + ks*8)*4);
      #pragma unroll
      for (int i = 0; i < 4; i++)
        #pragma unroll
        for (int j = 0; j < 4; j++)
          mma_h(acc[i][j], af[i], bf[j][ks*2], bf[j][ks*2+1]);
    }

    if (s + 1 < nsteps) {
      sts_step(buf ^ 1);
      cpa_wait_all();
    }
    __syncthreads();
  }

  if (MODE == 0) {
    #pragma unroll
    for (int j = 0; j < 4; j++) {
      int col = bn + wn0 + j*8 + 2*c;
      float b0 = bias[col], b1 = bias[col + 1];
      #pragma unroll
      for (int i = 0; i < 4; i++) {
        int r0 = bm + wm0 + i*16 + g;
        *(float2*)(Cf + (size_t)r0 * EMB + col) =
            make_float2(acc[i][j][0] + b0, acc[i][j][1] + b1);
        int r1 = r0 + 8;
        *(float2*)(Cf + (size_t)r1 * EMB + col) =
            make_float2(acc[i][j][2] + b0, acc[i][j][3] + b1);
      }
    }
  } else {
    bool toR = (blockIdx.z == 3);
    #pragma unroll
    for (int j = 0; j < 4; j++) {
      int col = bn + wn0 + j*8 + 2*c;
      float b0 = bias[col], b1 = bias[col + 1];
      #pragma unroll
      for (int i = 0; i < 4; i++) {
        #pragma unroll
        for (int rr = 0; rr < 2; rr++) {
          int r = bm + wm0 + i*16 + g + rr*8;
          uint32_t w = packh2(acc[i][j][rr*2+0] + b0, acc[i][j][rr*2+1] + b1);
          if (toR) {
            // zero-fill row 1023 so bd_kernel never reads garbage
            uint32_t wv = (r < NPOS) ? w : 0u;
            *(uint32_t*)(g_Rh + (size_t)r*EMB + col) = wv;
          } else {
            *(uint32_t*)(Chf + (size_t)r*EMB + col) = w;
          }
        }
      }
    }
  }
}

// ---------------------------------------------------------------------------
// BD kernel: one CTA per (n, q-tile, h). A (Qr tile, rrb folded) resident in
// smem; loop over the exactly-5 j-tiles of the band j in [q0, q0+638],
// double-buffering the R window via cp.async; coalesced smem-staged writeback.
// ---------------------------------------------------------------------------
#define BD_AW 36                 // row stride in words (32 data + 4 pad)
#define BD_ASZ (128*BD_AW)       // words per 128-row tile
#define CS_W 132                 // epilogue smem row stride in halfs
#define BD_SMEM (3*BD_ASZ*4 + 128*CS_W*2)   // As + 2*Bs + Csm = 89088 B

__global__ __launch_bounds__(256, 2) void bd_kernel(const float* __restrict__ rrb)
{
  extern __shared__ uint32_t sm[];
  uint32_t* As = sm;                       // [128][BD_AW]
  uint32_t* Bs = sm + BD_ASZ;              // [2][128][BD_AW]
  __half*  Csm = (__half*)(sm + 3*BD_ASZ); // [128][CS_W]
  uint32_t As_sa = (uint32_t)__cvta_generic_to_shared(As);
  uint32_t Bs_sa = (uint32_t)__cvta_generic_to_shared(Bs);

  int tid = threadIdx.x, lane = tid & 31, wid = tid >> 5;
  int g = lane >> 2, c = lane & 3;
  int lane7 = lane & 7, mat = lane >> 3;
  int rsel = (mat & 1) * 8 + lane7;
  int akw  = (mat >> 1) * 4;
  int bkw  = mat * 4;
  int wm0 = (wid >> 2) * 64, wn0 = (wid & 3) * 32;

  int x = blockIdx.x;
  int n = x >> 2, qt2 = x & 3;
  int q0 = qt2 * 128;
  int h = blockIdx.y;

  auto issue_B = [&](int buf, int jt) {
    int j0 = (qt2 + jt) * 128;
    const __half* Bg = g_Rh + (size_t)j0 * EMB + h*DH;
    #pragma unroll
    for (int it = 0; it < 4; it++) {
      int u = tid + it*256;
      int r = u >> 3, ch = u & 7;
      cpa16(Bs_sa + (buf*BD_ASZ + r*BD_AW + ch*4)*4,
            Bg + (size_t)r*EMB + ch*8);
    }
  };

  issue_B(0, 0);

  // stage A = Qr tile (g_Q fp16 + rrb), 128 rows x 64 halfs; 2 threads/row
  {
    int r = tid >> 1;
    int cw = (tid & 1) * 16;   // word offset 0/16 (half offset 0/32)
    const __half* Ap = g_Q + ((size_t)n*LQ + q0 + r)*EMB + h*DH + cw*2;
    uint4 a0 = *(const uint4*)(Ap);
    uint4 a1 = *(const uint4*)(Ap + 8);
    uint4 a2 = *(const uint4*)(Ap + 16);
    uint4 a3 = *(const uint4*)(Ap + 24);
    const float* rp = rrb + h*DH + cw*2;
    float4 r0 = *(const float4*)(rp);
    float4 r1 = *(const float4*)(rp + 4);
    float4 r2 = *(const float4*)(rp + 8);
    float4 r3 = *(const float4*)(rp + 12);
    float4 r4 = *(const float4*)(rp + 16);
    float4 r5 = *(const float4*)(rp + 20);
    float4 r6 = *(const float4*)(rp + 24);
    float4 r7 = *(const float4*)(rp + 28);
    uint32_t* dst = As + r*BD_AW + cw;
    dst[0]  = hadd2u(a0.x, packh2(r0.x, r0.y));
    dst[1]  = hadd2u(a0.y, packh2(r0.z, r0.w));
    dst[2]  = hadd2u(a0.z, packh2(r1.x, r1.y));
    dst[3]  = hadd2u(a0.w, packh2(r1.z, r1.w));
    dst[4]  = hadd2u(a1.x, packh2(r2.x, r2.y));
    dst[5]  = hadd2u(a1.y, packh2(r2.z, r2.w));
    dst[6]  = hadd2u(a1.z, packh2(r3.x, r3.y));
    dst[7]  = hadd2u(a1.w, packh2(r3.z, r3.w));
    dst[8]  = hadd2u(a2.x, packh2(r4.x, r4.y));
    dst[9]  = hadd2u(a2.y, packh2(r4.z, r4.w));
    dst[10] = hadd2u(a2.z, packh2(r5.x, r5.y));
    dst[11] = hadd2u(a2.w, packh2(r5.z, r5.w));
    dst[12] = hadd2u(a3.x, packh2(r6.x, r6.y));
    dst[13] = hadd2u(a3.y, packh2(r6.z, r6.w));
    dst[14] = hadd2u(a3.z, packh2(r7.x, r7.y));
    dst[15] = hadd2u(a3.w, packh2(r7.z, r7.w));
  }

  cpa_wait_all();
  __syncthreads();

  int tsub  = tid & 7;
  int rbase = tid >> 3;

  for (int jt = 0; jt < 5; jt++) {
    int buf = jt & 1;
    if (jt + 1 < 5) issue_B(buf ^ 1, jt + 1);

    float acc[4][4][4];
    #pragma unroll
    for (int i = 0; i < 4; i++)
      #pragma unroll
      for (int j = 0; j < 4; j++)
        #pragma unroll
        for (int r = 0; r < 4; r++) acc[i][j][r] = 0.f;

    uint32_t Bb = Bs_sa + buf*BD_ASZ*4;
    #pragma unroll
    for (int s2 = 0; s2 < 2; s2++) {
      uint32_t bf[4][4];
      #pragma unroll
      for (int j = 0; j < 4; j++)
        ldsm_x4(bf[j], Bb + ((wn0 + j*8 + lane7)*BD_AW + s2*16 + bkw)*4);
      #pragma unroll
      for (int ks = 0; ks < 2; ks++) {
        uint32_t af[4][4];
        #pragma unroll
        for (int i = 0; i < 4; i++)
          ldsm_x4(af[i], As_sa + ((wm0 + i*16 + rsel)*BD_AW + s2*16 + akw + ks*8)*4);
        #pragma unroll
        for (int i = 0; i < 4; i++)
          #pragma unroll
          for (int j = 0; j < 4; j++)
            mma_h(acc[i][j], af[i], bf[j][ks*2], bf[j][ks*2+1]);
      }
    }

    // stage acc -> Csm
    #pragma unroll
    for (int j = 0; j < 4; j++) {
      int colp = wn0 + j*8 + 2*c;
      #pragma unroll
      for (int i = 0; i < 4; i++) {
        #pragma unroll
        for (int rr = 0; rr < 2; rr++) {
          int rloc = wm0 + i*16 + g + rr*8;
          *(uint32_t*)(Csm + rloc*CS_W + colp) =
              packh2(acc[i][j][rr*2+0], acc[i][j][rr*2+1]);
        }
      }
    }
    __syncthreads();

    // coalesced writeback: colp = kbase - k, kbase = q + 511 - j0
    int j0 = (qt2 + jt) * 128;
    #pragma unroll
    for (int ps = 0; ps < 4; ps++) {
      int r = ps*32 + rbase;
      int q = q0 + r;
      __half* rowp = g_BD + (((size_t)(n*NH + h) * LQ) + q) * LQ;
      const __half* srowp = Csm + r*CS_W;
      int kbase = q + 511 - j0;
      int klo = max(0, kbase - 127);
      int khi = min(LQ - 1, kbase);
      for (int k8 = (klo & ~7) + tsub*8; k8 <= khi; k8 += 64) {
        if (k8 >= klo && k8 + 7 <= khi) {
          __half tmp[8];
          #pragma unroll
          for (int t = 0; t < 8; t++) tmp[t] = srowp[kbase - (k8 + t)];
          *(uint4*)(rowp + k8) = *(uint4*)tmp;
        } else {
          #pragma unroll
          for (int t = 0; t < 8; t++) {
            int k = k8 + t;
            if (k >= klo && k <= khi) rowp[k] = srowp[kbase - k];
          }
        }
      }
    }
    cpa_wait_all();
    __syncthreads();
  }
}

// ---------------------------------------------------------------------------
// Tensor-core fused attention: fp16 operands, ldmatrix frag loads,
// cp.async K staging (unchanged from R13).
// ---------------------------------------------------------------------------
#define QH_W 36
#define VS_W 72
#define ATTN_SMEM ((128*QH_W + 64*QH_W + 32*VS_W + 32) * 4)

__global__ __launch_bounds__(256) void attn_mma(const float* __restrict__ rwb)
{
  extern __shared__ uint32_t sm[];
  uint32_t* Qs   = sm;
  uint32_t* Ks   = Qs + 128*QH_W;
  uint32_t* Vs   = Ks + 64*QH_W;
  uint32_t* rwbh = Vs + 32*VS_W;
  uint32_t Qs_sa = (uint32_t)__cvta_generic_to_shared(Qs);
  uint32_t Ks_sa = (uint32_t)__cvta_generic_to_shared(Ks);

  int tid = threadIdx.x, lane = tid & 31, wid = tid >> 5;
  int g = lane >> 2, c = lane & 3;
  int lane7 = lane & 7, mat = lane >> 3;
  int rsel = (mat & 1) * 8 + lane7;
  int akw  = (mat >> 1) * 4;
  int bkw  = mat * 4;
  int b = blockIdx.x;
  int qt = b & 3; b >>= 2;
  int h = b % NH, n = b / NH;
  int q0 = qt * 128;
  int wm = wid * 16;

  if (tid < 32) {
    float2 r = *(const float2*)(rwb + h*DH + 2*tid);
    rwbh[tid] = packh2(r.x, r.y);
  }
  __syncthreads();

  const __half* Qg = g_Q + ((size_t)n*LQ + q0)*EMB + h*DH;
  for (int u = tid; u < 128*8; u += 256) {
    int r = u >> 3, ch = u & 7;
    uint4 v = *(const uint4*)(Qg + (size_t)r*EMB + ch*8);
    uint32_t* dst = Qs + r*QH_W + ch*4;
    dst[0] = hadd2u(v.x, rwbh[ch*4+0]);
    dst[1] = hadd2u(v.y, rwbh[ch*4+1]);
    dst[2] = hadd2u(v.z, rwbh[ch*4+2]);
    dst[3] = hadd2u(v.w, rwbh[ch*4+3]);
  }

  float oacc[8][4];
  #pragma unroll
  for (int j = 0; j < 8; j++)
    #pragma unroll
    for (int r = 0; r < 4; r++) oacc[j][r] = 0.f;
  float m_a = -1e30f, m_b = -1e30f, l_a = 0.f, l_b = 0.f;

  int qa = q0 + wm + g;
  const __half* bdra = g_BD + ((size_t)(n*NH + h)*LQ + qa)*LQ;
  const __half* bdrb = bdra + 8*LQ;

  for (int k0 = 0; k0 < LQ; k0 += 64) {
    const __half* Kg = g_K + ((size_t)n*LQ + k0)*EMB + h*DH;
    const __half* Vg = g_V + ((size_t)n*LQ + k0)*EMB + h*DH;
    for (int u = tid; u < 64*8; u += 256) {
      int r = u >> 3, ch = u & 7;
      cpa16(Ks_sa + (r*QH_W + ch*4)*4, Kg + (size_t)r*EMB + ch*8);
    }
    for (int u = tid; u < 32*16; u += 256) {
      int kk = u >> 4, dc = (u & 15) * 4;
      uint2 a  = *(const uint2*)(Vg + (size_t)(2*kk  )*EMB + dc);
      uint2 bb = *(const uint2*)(Vg + (size_t)(2*kk+1)*EMB + dc);
      uint32_t* dst = Vs + kk*VS_W + dc;
      dst[0] = __byte_perm(a.x, bb.x, 0x5410);
      dst[1] = __byte_perm(a.x, bb.x, 0x7632);
      dst[2] = __byte_perm(a.y, bb.y, 0x5410);
      dst[3] = __byte_perm(a.y, bb.y, 0x7632);
    }
    cpa_wait_all();
    __syncthreads();

    float sacc[8][4];
    #pragma unroll
    for (int j = 0; j < 8; j++) {
      uint32_t w0 = *(const uint32_t*)(bdra + k0 + j*8 + 2*c);
      uint32_t w1 = *(const uint32_t*)(bdrb + k0 + j*8 + 2*c);
      float2 f0 = __half22float2(*(__half2*)&w0);
      float2 f1 = __half22float2(*(__half2*)&w1);
      sacc[j][0] = f0.x; sacc[j][1] = f0.y;
      sacc[j][2] = f1.x; sacc[j][3] = f1.y;
    }

    uint32_t af[4][4];
    #pragma unroll
    for (int ks = 0; ks < 4; ks++)
      ldsm_x4(af[ks], Qs_sa + ((wm + rsel)*QH_W + akw + ks*8)*4);
    #pragma unroll
    for (int j = 0; j < 8; j++) {
      uint32_t bf[8];
      ldsm_x4(bf+0, Ks_sa + ((j*8 + lane7)*QH_W + bkw +  0)*4);
      ldsm_x4(bf+4, Ks_sa + ((j*8 + lane7)*QH_W + bkw + 16)*4);
      #pragma unroll
      for (int ks = 0; ks < 4; ks++)
        mma_h(sacc[j], af[ks], bf[ks*2], bf[ks*2+1]);
    }

    float mx_a = -1e30f, mx_b = -1e30f;
    #pragma unroll
    for (int j = 0; j < 8; j++) {
      sacc[j][0] *= 0.125f; sacc[j][1] *= 0.125f;
      sacc[j][2] *= 0.125f; sacc[j][3] *= 0.125f;
      mx_a = fmaxf(mx_a, fmaxf(sacc[j][0], sacc[j][1]));
      mx_b = fmaxf(mx_b, fmaxf(sacc[j][2], sacc[j][3]));
    }
    mx_a = fmaxf(mx_a, __shfl_xor_sync(0xffffffffu, mx_a, 1));
    mx_a = fmaxf(mx_a, __shfl_xor_sync(0xffffffffu, mx_a, 2));
    mx_b = fmaxf(mx_b, __shfl_xor_sync(0xffffffffu, mx_b, 1));
    mx_b = fmaxf(mx_b, __shfl_xor_sync(0xffffffffu, mx_b, 2));
    float mna = fmaxf(m_a, mx_a), mnb = fmaxf(m_b, mx_b);
    float ca = __expf(m_a - mna), cb = __expf(m_b - mnb);
    m_a = mna; m_b = mnb;
    l_a *= ca; l_b *= cb;
    #pragma unroll
    for (int j = 0; j < 8; j++) {
      oacc[j][0] *= ca; oacc[j][1] *= ca;
      oacc[j][2] *= cb; oacc[j][3] *= cb;
    }
    #pragma unroll
    for (int j = 0; j < 8; j++) {
      sacc[j][0] = __expf(sacc[j][0] - m_a); l_a += sacc[j][0];
      sacc[j][1] = __expf(sacc[j][1] - m_a); l_a += sacc[j][1];
      sacc[j][2] = __expf(sacc[j][2] - m_b); l_b += sacc[j][2];
      sacc[j][3] = __expf(sacc[j][3] - m_b); l_b += sacc[j][3];
    }

    #pragma unroll
    for (int jj = 0; jj < 4; jj++) {
      uint32_t pa[4];
      pa[0] = packh2(sacc[2*jj  ][0], sacc[2*jj  ][1]);
      pa[1] = packh2(sacc[2*jj  ][2], sacc[2*jj  ][3]);
      pa[2] = packh2(sacc[2*jj+1][0], sacc[2*jj+1][1]);
      pa[3] = packh2(sacc[2*jj+1][2], sacc[2*jj+1][3]);
      #pragma unroll
      for (int jd = 0; jd < 8; jd++) {
        uint32_t b0 = Vs[(jj*8 + c    )*VS_W + jd*8 + g];
        uint32_t b1 = Vs[(jj*8 + c + 4)*VS_W + jd*8 + g];
        mma_h(oacc[jd], pa, b0, b1);
      }
    }
    __syncthreads();
  }

  l_a += __shfl_xor_sync(0xffffffffu, l_a, 1);
  l_a += __shfl_xor_sync(0xffffffffu, l_a, 2);
  l_b += __shfl_xor_sync(0xffffffffu, l_b, 1);
  l_b += __shfl_xor_sync(0xffffffffu, l_b, 2);
  float ia = 1.f / l_a, ib = 1.f / l_b;
  __half* oa = g_AO + ((size_t)n*LQ + qa)*EMB + h*DH;
  __half* ob = oa + 8*EMB;
  #pragma unroll
  for (int jd = 0; jd < 8; jd++) {
    *(uint32_t*)(oa + jd*8 + 2*c) = packh2(oacc[jd][0]*ia, oacc[jd][1]*ia);
    *(uint32_t*)(ob + jd*8 + 2*c) = packh2(oacc[jd][2]*ib, oacc[jd][3]*ib);
  }
}

// ---------------------------------------------------------------------------
extern "C" void kernel_launch(void* const* d_in, const int* in_sizes, int n_in,
                              void* d_out, int out_size) {
  (void)in_sizes; (void)n_in; (void)out_size;
  const float* values = (const float*)d_in[0];
  const float* keys   = (const float*)d_in[1];
  const float* query  = (const float*)d_in[2];
  const float* Wq   = (const float*)d_in[3];
  const float* bq   = (const float*)d_in[4];
  const float* Wk   = (const float*)d_in[5];
  const float* bk   = (const float*)d_in[6];
  const float* Wv   = (const float*)d_in[7];
  const float* bv   = (const float*)d_in[8];
  const float* Wo   = (const float*)d_in[9];
  const float* bo   = (const float*)d_in[10];
  const float* Wpos = (const float*)d_in[11];
  const float* bpos = (const float*)d_in[12];
  const float* rwb  = (const float*)d_in[13];
  const float* rrb  = (const float*)d_in[14];
  float* out = (float*)d_out;

  cudaFuncSetAttribute(gemm_h<0>, cudaFuncAttributeMaxDynamicSharedMemorySize,
                       GEMM_SMEM);
  cudaFuncSetAttribute(gemm_h<2>, cudaFuncAttributeMaxDynamicSharedMemorySize,
                       GEMM_SMEM);
  cudaFuncSetAttribute(bd_kernel, cudaFuncAttributeMaxDynamicSharedMemorySize,
                       BD_SMEM);
  cudaFuncSetAttribute(attn_mma, cudaFuncAttributeMaxDynamicSharedMemorySize,
                       ATTN_SMEM);

  // 1) sinusoid table
  pe_kernel<<<(NPOS*EMB + 255)/256, 256>>>();
  // 2) weight transpose+convert to fp16 [n][k]
  wconv5<<<dim3(24, 24, 5), dim3(32, 8)>>>(Wq, Wk, Wv, Wo, Wpos);
  // 3) batched Q/K/V projections + R = pe@Wpos, fp16 outputs
  gemm_h<2><<<dim3(6, 32, 4), 256, GEMM_SMEM>>>(
      query, keys, values, bq, bk, bv, bpos, nullptr);
  // 4) BD: persistent band kernel, one CTA per (n, q-tile, h)
  bd_kernel<<<dim3(32, NH), 256, BD_SMEM>>>(rrb);
  // 5) tensor-core fused attention (all fp16 operands)
  attn_mma<<<NB*NH*(LQ/128), 256, ATTN_SMEM>>>(rwb);
  // 6) output projection (f32 out)
  gemm_h<0><<<dim3(6, 32), 256, GEMM_SMEM>>>(
      nullptr, nullptr, nullptr, bo, nullptr, nullptr, nullptr, out);
}

// round 16
// speedup vs baseline: 6.0995x; 1.1371x over previous
#include <cuda_runtime.h>
#include <cuda_fp16.h>
#include <math.h>
#include <stdint.h>
#include <stddef.h>

#define NB   8
#define LQ   512
#define EMB  768
#define NH   12
#define DH   64
#define NPOS 1023   // 2*MAXLEN-1
#define JPAD 1024
#define WSZ  (EMB*EMB)
#define MROWS (NB*LQ)

// ---------------- scratch (__device__ globals: allocation-free rule) --------
__device__ __align__(16) __half g_peh[(size_t)JPAD*EMB];  // sinusoid table fp16 (row 1023 = 0)
__device__ __align__(16) __half g_Ih[(size_t)3*MROWS*EMB]; // fp16 copies of query/keys/values
__device__ __align__(16) __half g_Wh[5*WSZ];              // weights transposed [n][k] fp16
__device__ __align__(16) __half g_Rh[(size_t)JPAD*EMB];   // R[j][e] fp16
__device__ __align__(16) __half g_Q [MROWS*EMB];
__device__ __align__(16) __half g_K [MROWS*EMB];
__device__ __align__(16) __half g_V [MROWS*EMB];
__device__ __align__(16) __half g_BD[(size_t)NB*NH*LQ*LQ];
__device__ __align__(16) __half g_AO[MROWS*EMB];

__device__ __forceinline__ uint32_t packh2(float lo, float hi) {
  __half2 h = __floats2half2_rn(lo, hi);
  return *(uint32_t*)&h;
}
__device__ __forceinline__ uint32_t hadd2u(uint32_t a, uint32_t b) {
  __half2 r = __hadd2(*(__half2*)&a, *(__half2*)&b);
  return *(uint32_t*)&r;
}
__device__ __forceinline__ void ldsm_x4(uint32_t* r, uint32_t addr) {
  asm volatile("ldmatrix.sync.aligned.m8n8.x4.shared.b16 {%0,%1,%2,%3}, [%4];"
    : "=r"(r[0]), "=r"(r[1]), "=r"(r[2]), "=r"(r[3]) : "r"(addr));
}
__device__ __forceinline__ void cpa16(uint32_t dst, const void* src) {
  asm volatile("cp.async.cg.shared.global [%0], [%1], 16;" :: "r"(dst), "l"(src));
}
__device__ __forceinline__ void cpa_commit() {
  asm volatile("cp.async.commit_group;" ::: "memory");
}
__device__ __forceinline__ void cpa_wait2() {
  asm volatile("cp.async.wait_group 2;" ::: "memory");
}
__device__ __forceinline__ void cpa_wait_all() {
  asm volatile("cp.async.wait_all;" ::: "memory");
}
__device__ __forceinline__ void mma_h(float* d, const uint32_t* a,
                                      uint32_t b0, uint32_t b1) {
  asm volatile(
    "mma.sync.aligned.m16n8k16.row.col.f32.f16.f16.f32 "
    "{%0,%1,%2,%3},{%4,%5,%6,%7},{%8,%9},{%0,%1,%2,%3};"
    : "+f"(d[0]), "+f"(d[1]), "+f"(d[2]), "+f"(d[3])
    : "r"(a[0]), "r"(a[1]), "r"(a[2]), "r"(a[3]), "r"(b0), "r"(b1));
}

// ---------------------------------------------------------------------------
// Sinusoid table, fp16 direct (row 1023 zeroed)
// ---------------------------------------------------------------------------
__global__ void pe_kernel() {
  int idx = blockIdx.x * 256 + threadIdx.x;
  if (idx >= JPAD*EMB) return;
  int p = idx / EMB;
  int e = idx - p * EMB;
  if (p >= NPOS) { g_peh[idx] = __float2half(0.f); return; }
  int i2 = e & ~1;
  float div = expf(-(float)i2 * (9.210340371976184f / (float)EMB));
  float ang = (float)p * div;
  g_peh[idx] = __float2half((e & 1) ? cosf(ang) : sinf(ang));
}

// ---------------------------------------------------------------------------
// Input conversion: query/keys/values f32 -> fp16
// ---------------------------------------------------------------------------
__global__ void in2h(const float* __restrict__ q, const float* __restrict__ k,
                     const float* __restrict__ v) {
  int z = blockIdx.y;
  const float* src = (z == 0) ? q : (z == 1) ? k : v;
  __half* dst = g_Ih + (size_t)z * MROWS * EMB;
  int i = blockIdx.x * 256 + threadIdx.x;          // 8-elem units
  if (i >= MROWS*EMB/8) return;
  const float4* s4 = (const float4*)src + (size_t)i*2;
  float4 v0 = s4[0], v1 = s4[1];
  *(uint4*)(dst + (size_t)i*8) =
      make_uint4(packh2(v0.x, v0.y), packh2(v0.z, v0.w),
                 packh2(v1.x, v1.y), packh2(v1.z, v1.w));
}

// ---------------------------------------------------------------------------
__global__ void wconv5(const float* __restrict__ W0, const float* __restrict__ W1,
                       const float* __restrict__ W2, const float* __restrict__ W3,
                       const float* __restrict__ W4) {
  __shared__ float t[32][33];
  int z = blockIdx.z;
  const float* W = (z==0)?W0:(z==1)?W1:(z==2)?W2:(z==3)?W3:W4;
  __half* Wh = g_Wh + (size_t)z*WSZ;
  int k0 = blockIdx.x*32, n0 = blockIdx.y*32;
  int tx = threadIdx.x, ty = threadIdx.y;
  #pragma unroll
  for (int i = 0; i < 4; i++)
    t[ty+8*i][tx] = W[(size_t)(k0+ty+8*i)*EMB + n0+tx];
  __syncthreads();
  #pragma unroll
  for (int i = 0; i < 4; i++)
    Wh[(size_t)(n0+ty+8*i)*EMB + k0+tx] = __float2half(t[tx][ty+8*i]);
}

// ---------------------------------------------------------------------------
// fp16 MMA GEMM core: 4-buffer / 3-ahead cp.async pipeline, 1 sync/step.
// MODE 0: out-proj  (A=g_AO, B=Wh[3], bias=bo, C f32 -> Cout)
// MODE 2: QKV+R over z (A=g_Ih[z] or g_peh; fp16 epilogue -> g_Q/K/V or g_Rh)
// ---------------------------------------------------------------------------
#define GA_W 20
#define GSZ  (128*GA_W)
#define NSTG 4
#define GEMM_SMEM (NSTG*2*GSZ*4)   // 81920 B

template<int MODE>
__global__ __launch_bounds__(256, 2) void gemm_h(
    const float* __restrict__ b0p, const float* __restrict__ b1p,
    const float* __restrict__ b2p, const float* __restrict__ b3p,
    float* __restrict__ Cout)
{
  extern __shared__ uint32_t sm[];
  uint32_t Asm_sa = (uint32_t)__cvta_generic_to_shared(sm);
  uint32_t Bsm_sa = Asm_sa + NSTG*GSZ*4;

  int tid = threadIdx.x, lane = tid & 31, wid = tid >> 5;
  int g = lane >> 2, c = lane & 3;
  int lane7 = lane & 7, mat = lane >> 3;
  int rsel = (mat & 1) * 8 + lane7;
  int akw  = (mat >> 1) * 4;
  int bkw  = mat * 4;
  int wm0 = (wid >> 2) * 64, wn0 = (wid & 3) * 32;
  int bm = blockIdx.y * 128, bn = blockIdx.x * 128;

  const __half* Ah; const __half* Bh; const float* bias = nullptr;
  float* Cf = nullptr; __half* Chf = nullptr;
  constexpr int nsteps = 24;   // K = 768

  if (MODE == 0) {
    Ah = g_AO; Bh = g_Wh + 3*WSZ; bias = b0p; Cf = Cout;
  } else {
    int z = blockIdx.z;
    if (z == 0)      { Ah = g_Ih;              bias = b0p; Chf = g_Q;  Bh = g_Wh; }
    else if (z == 1) { Ah = g_Ih +   (size_t)MROWS*EMB; bias = b1p; Chf = g_K;  Bh = g_Wh + WSZ; }
    else if (z == 2) { Ah = g_Ih + (size_t)2*MROWS*EMB; bias = b2p; Chf = g_V;  Bh = g_Wh + 2*WSZ; }
    else {
      if (blockIdx.y >= 8) return;
      Ah = g_peh; bias = b3p; Chf = g_Rh; Bh = g_Wh + 4*WSZ;
    }
  }

  int srow = tid >> 1;            // staging row 0..127
  int sch  = (tid & 1) * 2;       // chunk pair 0-1 / 2-3 (8 halfs each)

  float acc[4][4][4];
  #pragma unroll
  for (int i = 0; i < 4; i++)
    #pragma unroll
    for (int j = 0; j < 4; j++)
      #pragma unroll
      for (int r = 0; r < 4; r++) acc[i][j][r] = 0.f;

  const __half* Apr = Ah + (size_t)(bm + srow) * EMB + sch*8;
  const __half* Bpr = Bh + (size_t)(bn + srow) * EMB + sch*8;
  uint32_t Asta = Asm_sa + (srow*GA_W + sch*4)*4;
  uint32_t Bsta = Bsm_sa + (srow*GA_W + sch*4)*4;

  auto issue = [&](int s) {
    if (s < nsteps) {
      int bo = (s & 3) * GSZ * 4;
      int k0 = s * 32;
      cpa16(Bsta + bo,      Bpr + k0);
      cpa16(Bsta + bo + 16, Bpr + k0 + 8);
      cpa16(Asta + bo,      Apr + k0);
      cpa16(Asta + bo + 16, Apr + k0 + 8);
    }
    cpa_commit();
  };

  issue(0); issue(1); issue(2);

  for (int s = 0; s < nsteps; s++) {
    cpa_wait2();
    __syncthreads();
    issue(s + 3);

    uint32_t Ab = Asm_sa + (s & 3)*GSZ*4;
    uint32_t Bb = Bsm_sa + (s & 3)*GSZ*4;
    uint32_t bf[4][4];
    #pragma unroll
    for (int j = 0; j < 4; j++)
      ldsm_x4(bf[j], Bb + ((wn0 + j*8 + lane7)*GA_W + bkw)*4);
    #pragma unroll
    for (int ks = 0; ks < 2; ks++) {
      uint32_t af[4][4];
      #pragma unroll
      for (int i = 0; i < 4; i++)
        ldsm_x4(af[i], Ab + ((wm0 + i*16 + rsel)*GA_W + akw + ks*8)*4);
      #pragma unroll
      for (int i = 0; i < 4; i++)
        #pragma unroll
        for (int j = 0; j < 4; j++)
          mma_h(acc[i][j], af[i], bf[j][ks*2], bf[j][ks*2+1]);
    }
  }

  if (MODE == 0) {
    #pragma unroll
    for (int j = 0; j < 4; j++) {
      int col = bn + wn0 + j*8 + 2*c;
      float b0 = bias[col], b1 = bias[col + 1];
      #pragma unroll
      for (int i = 0; i < 4; i++) {
        int r0 = bm + wm0 + i*16 + g;
        *(float2*)(Cf + (size_t)r0 * EMB + col) =
            make_float2(acc[i][j][0] + b0, acc[i][j][1] + b1);
        int r1 = r0 + 8;
        *(float2*)(Cf + (size_t)r1 * EMB + col) =
            make_float2(acc[i][j][2] + b0, acc[i][j][3] + b1);
      }
    }
  } else {
    #pragma unroll
    for (int j = 0; j < 4; j++) {
      int col = bn + wn0 + j*8 + 2*c;
      float b0 = bias[col], b1 = bias[col + 1];
      #pragma unroll
      for (int i = 0; i < 4; i++) {
        #pragma unroll
        for (int rr = 0; rr < 2; rr++) {
          int r = bm + wm0 + i*16 + g + rr*8;
          *(uint32_t*)(Chf + (size_t)r*EMB + col) =
              packh2(acc[i][j][rr*2+0] + b0, acc[i][j][rr*2+1] + b1);
        }
      }
    }
  }
}

// ---------------------------------------------------------------------------
// BD kernel (unchanged from R14): one CTA per (n, q-tile, h).
// ---------------------------------------------------------------------------
#define BD_AW 36
#define BD_ASZ (128*BD_AW)
#define CS_W 132
#define BD_SMEM (3*BD_ASZ*4 + 128*CS_W*2)

__global__ __launch_bounds__(256, 2) void bd_kernel(const float* __restrict__ rrb)
{
  extern __shared__ uint32_t sm[];
  uint32_t* As = sm;
  uint32_t* Bs = sm + BD_ASZ;
  __half*  Csm = (__half*)(sm + 3*BD_ASZ);
  uint32_t As_sa = (uint32_t)__cvta_generic_to_shared(As);
  uint32_t Bs_sa = (uint32_t)__cvta_generic_to_shared(Bs);

  int tid = threadIdx.x, lane = tid & 31, wid = tid >> 5;
  int g = lane >> 2, c = lane & 3;
  int lane7 = lane & 7, mat = lane >> 3;
  int rsel = (mat & 1) * 8 + lane7;
  int akw  = (mat >> 1) * 4;
  int bkw  = mat * 4;
  int wm0 = (wid >> 2) * 64, wn0 = (wid & 3) * 32;

  int x = blockIdx.x;
  int n = x >> 2, qt2 = x & 3;
  int q0 = qt2 * 128;
  int h = blockIdx.y;

  auto issue_B = [&](int buf, int jt) {
    int j0 = (qt2 + jt) * 128;
    const __half* Bg = g_Rh + (size_t)j0 * EMB + h*DH;
    #pragma unroll
    for (int it = 0; it < 4; it++) {
      int u = tid + it*256;
      int r = u >> 3, ch = u & 7;
      cpa16(Bs_sa + (buf*BD_ASZ + r*BD_AW + ch*4)*4,
            Bg + (size_t)r*EMB + ch*8);
    }
  };

  issue_B(0, 0);

  {
    int r = tid >> 1;
    int cw = (tid & 1) * 16;
    const __half* Ap = g_Q + ((size_t)n*LQ + q0 + r)*EMB + h*DH + cw*2;
    uint4 a0 = *(const uint4*)(Ap);
    uint4 a1 = *(const uint4*)(Ap + 8);
    uint4 a2 = *(const uint4*)(Ap + 16);
    uint4 a3 = *(const uint4*)(Ap + 24);
    const float* rp = rrb + h*DH + cw*2;
    float4 r0 = *(const float4*)(rp);
    float4 r1 = *(const float4*)(rp + 4);
    float4 r2 = *(const float4*)(rp + 8);
    float4 r3 = *(const float4*)(rp + 12);
    float4 r4 = *(const float4*)(rp + 16);
    float4 r5 = *(const float4*)(rp + 20);
    float4 r6 = *(const float4*)(rp + 24);
    float4 r7 = *(const float4*)(rp + 28);
    uint32_t* dst = As + r*BD_AW + cw;
    dst[0]  = hadd2u(a0.x, packh2(r0.x, r0.y));
    dst[1]  = hadd2u(a0.y, packh2(r0.z, r0.w));
    dst[2]  = hadd2u(a0.z, packh2(r1.x, r1.y));
    dst[3]  = hadd2u(a0.w, packh2(r1.z, r1.w));
    dst[4]  = hadd2u(a1.x, packh2(r2.x, r2.y));
    dst[5]  = hadd2u(a1.y, packh2(r2.z, r2.w));
    dst[6]  = hadd2u(a1.z, packh2(r3.x, r3.y));
    dst[7]  = hadd2u(a1.w, packh2(r3.z, r3.w));
    dst[8]  = hadd2u(a2.x, packh2(r4.x, r4.y));
    dst[9]  = hadd2u(a2.y, packh2(r4.z, r4.w));
    dst[10] = hadd2u(a2.z, packh2(r5.x, r5.y));
    dst[11] = hadd2u(a2.w, packh2(r5.z, r5.w));
    dst[12] = hadd2u(a3.x, packh2(r6.x, r6.y));
    dst[13] = hadd2u(a3.y, packh2(r6.z, r6.w));
    dst[14] = hadd2u(a3.z, packh2(r7.x, r7.y));
    dst[15] = hadd2u(a3.w, packh2(r7.z, r7.w));
  }

  cpa_wait_all();
  __syncthreads();

  int tsub  = tid & 7;
  int rbase = tid >> 3;

  for (int jt = 0; jt < 5; jt++) {
    int buf = jt & 1;
    if (jt + 1 < 5) issue_B(buf ^ 1, jt + 1);

    float acc[4][4][4];
    #pragma unroll
    for (int i = 0; i < 4; i++)
      #pragma unroll
      for (int j = 0; j < 4; j++)
        #pragma unroll
        for (int r = 0; r < 4; r++) acc[i][j][r] = 0.f;

    uint32_t Bb = Bs_sa + buf*BD_ASZ*4;
    #pragma unroll
    for (int s2 = 0; s2 < 2; s2++) {
      uint32_t bf[4][4];
      #pragma unroll
      for (int j = 0; j < 4; j++)
        ldsm_x4(bf[j], Bb + ((wn0 + j*8 + lane7)*BD_AW + s2*16 + bkw)*4);
      #pragma unroll
      for (int ks = 0; ks < 2; ks++) {
        uint32_t af[4][4];
        #pragma unroll
        for (int i = 0; i < 4; i++)
          ldsm_x4(af[i], As_sa + ((wm0 + i*16 + rsel)*BD_AW + s2*16 + akw + ks*8)*4);
        #pragma unroll
        for (int i = 0; i < 4; i++)
          #pragma unroll
          for (int j = 0; j < 4; j++)
            mma_h(acc[i][j], af[i], bf[j][ks*2], bf[j][ks*2+1]);
      }
    }

    #pragma unroll
    for (int j = 0; j < 4; j++) {
      int colp = wn0 + j*8 + 2*c;
      #pragma unroll
      for (int i = 0; i < 4; i++) {
        #pragma unroll
        for (int rr = 0; rr < 2; rr++) {
          int rloc = wm0 + i*16 + g + rr*8;
          *(uint32_t*)(Csm + rloc*CS_W + colp) =
              packh2(acc[i][j][rr*2+0], acc[i][j][rr*2+1]);
        }
      }
    }
    __syncthreads();

    int j0 = (qt2 + jt) * 128;
    #pragma unroll
    for (int ps = 0; ps < 4; ps++) {
      int r = ps*32 + rbase;
      int q = q0 + r;
      __half* rowp = g_BD + (((size_t)(n*NH + h) * LQ) + q) * LQ;
      const __half* srowp = Csm + r*CS_W;
      int kbase = q + 511 - j0;
      int klo = max(0, kbase - 127);
      int khi = min(LQ - 1, kbase);
      for (int k8 = (klo & ~7) + tsub*8; k8 <= khi; k8 += 64) {
        if (k8 >= klo && k8 + 7 <= khi) {
          __half tmp[8];
          #pragma unroll
          for (int t = 0; t < 8; t++) tmp[t] = srowp[kbase - (k8 + t)];
          *(uint4*)(rowp + k8) = *(uint4*)tmp;
        } else {
          #pragma unroll
          for (int t = 0; t < 8; t++) {
            int k = k8 + t;
            if (k >= klo && k <= khi) rowp[k] = srowp[kbase - k];
          }
        }
      }
    }
    cpa_wait_all();
    __syncthreads();
  }
}

// ---------------------------------------------------------------------------
// Tensor-core fused attention: fp16 operands, ldmatrix frags,
// double-buffered K (cp.async) + V (LDG-regs-then-STS), Q frags hoisted.
// ---------------------------------------------------------------------------
#define QH_W 36
#define VS_W 72
#define KSZ (64*QH_W)
#define VSZ (32*VS_W)
#define ATTN_SMEM ((128*QH_W + 2*KSZ + 2*VSZ + 32) * 4)

__global__ __launch_bounds__(256) void attn_mma(const float* __restrict__ rwb)
{
  extern __shared__ uint32_t sm[];
  uint32_t* Qs   = sm;                   // [128][QH_W]
  uint32_t* Ks   = Qs + 128*QH_W;        // [2][64][QH_W]
  uint32_t* Vs   = Ks + 2*KSZ;           // [2][32][VS_W]
  uint32_t* rwbh = Vs + 2*VSZ;           // [32]
  uint32_t Qs_sa = (uint32_t)__cvta_generic_to_shared(Qs);
  uint32_t Ks_sa = (uint32_t)__cvta_generic_to_shared(Ks);

  int tid = threadIdx.x, lane = tid & 31, wid = tid >> 5;
  int g = lane >> 2, c = lane & 3;
  int lane7 = lane & 7, mat = lane >> 3;
  int rsel = (mat & 1) * 8 + lane7;
  int akw  = (mat >> 1) * 4;
  int bkw  = mat * 4;
  int b = blockIdx.x;
  int qt = b & 3; b >>= 2;
  int h = b % NH, n = b / NH;
  int q0 = qt * 128;
  int wm = wid * 16;

  if (tid < 32) {
    float2 r = *(const float2*)(rwb + h*DH + 2*tid);
    rwbh[tid] = packh2(r.x, r.y);
  }
  __syncthreads();

  // stage Q + rwb (full 64-half rows)
  const __half* Qg = g_Q + ((size_t)n*LQ + q0)*EMB + h*DH;
  for (int u = tid; u < 128*8; u += 256) {
    int r = u >> 3, ch = u & 7;
    uint4 v = *(const uint4*)(Qg + (size_t)r*EMB + ch*8);
    uint32_t* dst = Qs + r*QH_W + ch*4;
    dst[0] = hadd2u(v.x, rwbh[ch*4+0]);
    dst[1] = hadd2u(v.y, rwbh[ch*4+1]);
    dst[2] = hadd2u(v.z, rwbh[ch*4+2]);
    dst[3] = hadd2u(v.w, rwbh[ch*4+3]);
  }

  const __half* Kg0 = g_K + ((size_t)n*LQ)*EMB + h*DH;
  const __half* Vg0 = g_V + ((size_t)n*LQ)*EMB + h*DH;

  // prologue: tile 0 into buf 0
  {
    #pragma unroll
    for (int it = 0; it < 2; it++) {
      int u = tid + it*256;
      int r = u >> 3, ch = u & 7;
      cpa16(Ks_sa + (r*QH_W + ch*4)*4, Kg0 + (size_t)r*EMB + ch*8);
    }
    #pragma unroll
    for (int it = 0; it < 2; it++) {
      int u = tid + it*256;
      int kk = u >> 4, dc = (u & 15) * 4;
      uint2 a  = *(const uint2*)(Vg0 + (size_t)(2*kk  )*EMB + dc);
      uint2 bb = *(const uint2*)(Vg0 + (size_t)(2*kk+1)*EMB + dc);
      uint32_t* dst = Vs + kk*VS_W + dc;
      dst[0] = __byte_perm(a.x, bb.x, 0x5410);
      dst[1] = __byte_perm(a.x, bb.x, 0x7632);
      dst[2] = __byte_perm(a.y, bb.y, 0x5410);
      dst[3] = __byte_perm(a.y, bb.y, 0x7632);
    }
  }
  cpa_wait_all();
  __syncthreads();

  // hoist Q fragments (tile-invariant)
  uint32_t af[4][4];
  #pragma unroll
  for (int ks = 0; ks < 4; ks++)
    ldsm_x4(af[ks], Qs_sa + ((wm + rsel)*QH_W + akw + ks*8)*4);

  float oacc[8][4];
  #pragma unroll
  for (int j = 0; j < 8; j++)
    #pragma unroll
    for (int r = 0; r < 4; r++) oacc[j][r] = 0.f;
  float m_a = -1e30f, m_b = -1e30f, l_a = 0.f, l_b = 0.f;

  int qa = q0 + wm + g;
  const __half* bdra = g_BD + ((size_t)(n*NH + h)*LQ + qa)*LQ;
  const __half* bdrb = bdra + 8*LQ;

  for (int t = 0; t < 8; t++) {
    int buf = t & 1;
    int k0 = t * 64;
    bool pf = (t + 1 < 8);
    uint2 va[2], vb[2];

    if (pf) {
      const __half* Kg = Kg0 + (size_t)(k0 + 64)*EMB;
      const __half* Vg = Vg0 + (size_t)(k0 + 64)*EMB;
      #pragma unroll
      for (int it = 0; it < 2; it++) {
        int u = tid + it*256;
        int r = u >> 3, ch = u & 7;
        cpa16(Ks_sa + ((buf^1)*KSZ + r*QH_W + ch*4)*4,
              Kg + (size_t)r*EMB + ch*8);
      }
      #pragma unroll
      for (int it = 0; it < 2; it++) {
        int u = tid + it*256;
        int kk = u >> 4, dc = (u & 15) * 4;
        va[it] = *(const uint2*)(Vg + (size_t)(2*kk  )*EMB + dc);
        vb[it] = *(const uint2*)(Vg + (size_t)(2*kk+1)*EMB + dc);
      }
    }

    // init S from BD
    float sacc[8][4];
    #pragma unroll
    for (int j = 0; j < 8; j++) {
      uint32_t w0 = *(const uint32_t*)(bdra + k0 + j*8 + 2*c);
      uint32_t w1 = *(const uint32_t*)(bdrb + k0 + j*8 + 2*c);
      float2 f0 = __half22float2(*(__half2*)&w0);
      float2 f1 = __half22float2(*(__half2*)&w1);
      sacc[j][0] = f0.x; sacc[j][1] = f0.y;
      sacc[j][2] = f1.x; sacc[j][3] = f1.y;
    }

    // S += (Q+rwb) . K^T
    uint32_t Kb = Ks_sa + buf*KSZ*4;
    #pragma unroll
    for (int j = 0; j < 8; j++) {
      uint32_t bf[8];
      ldsm_x4(bf+0, Kb + ((j*8 + lane7)*QH_W + bkw +  0)*4);
      ldsm_x4(bf+4, Kb + ((j*8 + lane7)*QH_W + bkw + 16)*4);
      #pragma unroll
      for (int ks = 0; ks < 4; ks++)
        mma_h(sacc[j], af[ks], bf[ks*2], bf[ks*2+1]);
    }

    // online softmax
    float mx_a = -1e30f, mx_b = -1e30f;
    #pragma unroll
    for (int j = 0; j < 8; j++) {
      sacc[j][0] *= 0.125f; sacc[j][1] *= 0.125f;
      sacc[j][2] *= 0.125f; sacc[j][3] *= 0.125f;
      mx_a = fmaxf(mx_a, fmaxf(sacc[j][0], sacc[j][1]));
      mx_b = fmaxf(mx_b, fmaxf(sacc[j][2], sacc[j][3]));
    }
    mx_a = fmaxf(mx_a, __shfl_xor_sync(0xffffffffu, mx_a, 1));
    mx_a = fmaxf(mx_a, __shfl_xor_sync(0xffffffffu, mx_a, 2));
    mx_b = fmaxf(mx_b, __shfl_xor_sync(0xffffffffu, mx_b, 1));
    mx_b = fmaxf(mx_b, __shfl_xor_sync(0xffffffffu, mx_b, 2));
    float mna = fmaxf(m_a, mx_a), mnb = fmaxf(m_b, mx_b);
    float ca = __expf(m_a - mna), cb = __expf(m_b - mnb);
    m_a = mna; m_b = mnb;
    l_a *= ca; l_b *= cb;
    #pragma unroll
    for (int j = 0; j < 8; j++) {
      oacc[j][0] *= ca; oacc[j][1] *= ca;
      oacc[j][2] *= cb; oacc[j][3] *= cb;
    }
    #pragma unroll
    for (int j = 0; j < 8; j++) {
      sacc[j][0] = __expf(sacc[j][0] - m_a); l_a += sacc[j][0];
      sacc[j][1] = __expf(sacc[j][1] - m_a); l_a += sacc[j][1];
      sacc[j][2] = __expf(sacc[j][2] - m_b); l_b += sacc[j][2];
      sacc[j][3] = __expf(sacc[j][3] - m_b); l_b += sacc[j][3];
    }

    // O += P . V
    #pragma unroll
    for (int jj = 0; jj < 4; jj++) {
      uint32_t pa[4];
      pa[0] = packh2(sacc[2*jj  ][0], sacc[2*jj  ][1]);
      pa[1] = packh2(sacc[2*jj  ][2], sacc[2*jj  ][3]);
      pa[2] = packh2(sacc[2*jj+1][0], sacc[2*jj+1][1]);
      pa[3] = packh2(sacc[2*jj+1][2], sacc[2*jj+1][3]);
      #pragma unroll
      for (int jd = 0; jd < 8; jd++) {
        uint32_t b0 = Vs[buf*VSZ + (jj*8 + c    )*VS_W + jd*8 + g];
        uint32_t b1 = Vs[buf*VSZ + (jj*8 + c + 4)*VS_W + jd*8 + g];
        mma_h(oacc[jd], pa, b0, b1);
      }
    }

    if (pf) {
      #pragma unroll
      for (int it = 0; it < 2; it++) {
        int u = tid + it*256;
        int kk = u >> 4, dc = (u & 15) * 4;
        uint32_t* dst = Vs + (buf^1)*VSZ + kk*VS_W + dc;
        dst[0] = __byte_perm(va[it].x, vb[it].x, 0x5410);
        dst[1] = __byte_perm(va[it].x, vb[it].x, 0x7632);
        dst[2] = __byte_perm(va[it].y, vb[it].y, 0x5410);
        dst[3] = __byte_perm(va[it].y, vb[it].y, 0x7632);
      }
      cpa_wait_all();
    }
    __syncthreads();
  }

  l_a += __shfl_xor_sync(0xffffffffu, l_a, 1);
  l_a += __shfl_xor_sync(0xffffffffu, l_a, 2);
  l_b += __shfl_xor_sync(0xffffffffu, l_b, 1);
  l_b += __shfl_xor_sync(0xffffffffu, l_b, 2);
  float ia = 1.f / l_a, ib = 1.f / l_b;
  __half* oa = g_AO + ((size_t)n*LQ + qa)*EMB + h*DH;
  __half* ob = oa + 8*EMB;
  #pragma unroll
  for (int jd = 0; jd < 8; jd++) {
    *(uint32_t*)(oa + jd*8 + 2*c) = packh2(oacc[jd][0]*ia, oacc[jd][1]*ia);
    *(uint32_t*)(ob + jd*8 + 2*c) = packh2(oacc[jd][2]*ib, oacc[jd][3]*ib);
  }
}

// ---------------------------------------------------------------------------
extern "C" void kernel_launch(void* const* d_in, const int* in_sizes, int n_in,
                              void* d_out, int out_size) {
  (void)in_sizes; (void)n_in; (void)out_size;
  const float* values = (const float*)d_in[0];
  const float* keys   = (const float*)d_in[1];
  const float* query  = (const float*)d_in[2];
  const float* Wq   = (const float*)d_in[3];
  const float* bq   = (const float*)d_in[4];
  const float* Wk   = (const float*)d_in[5];
  const float* bk   = (const float*)d_in[6];
  const float* Wv   = (const float*)d_in[7];
  const float* bv   = (const float*)d_in[8];
  const float* Wo   = (const float*)d_in[9];
  const float* bo   = (const float*)d_in[10];
  const float* Wpos = (const float*)d_in[11];
  const float* bpos = (const float*)d_in[12];
  const float* rwb  = (const float*)d_in[13];
  const float* rrb  = (const float*)d_in[14];
  float* out = (float*)d_out;

  cudaFuncSetAttribute(gemm_h<0>, cudaFuncAttributeMaxDynamicSharedMemorySize,
                       GEMM_SMEM);
  cudaFuncSetAttribute(gemm_h<2>, cudaFuncAttributeMaxDynamicSharedMemorySize,
                       GEMM_SMEM);
  cudaFuncSetAttribute(bd_kernel, cudaFuncAttributeMaxDynamicSharedMemorySize,
                       BD_SMEM);
  cudaFuncSetAttribute(attn_mma, cudaFuncAttributeMaxDynamicSharedMemorySize,
                       ATTN_SMEM);

  // 1) sinusoid table (fp16 direct)
  pe_kernel<<<(JPAD*EMB + 255)/256, 256>>>();
  // 2) weight transpose+convert to fp16 [n][k]
  wconv5<<<dim3(24, 24, 5), dim3(32, 8)>>>(Wq, Wk, Wv, Wo, Wpos);
  // 3) input conversion f32 -> fp16
  in2h<<<dim3((MROWS*EMB/8 + 255)/256, 3), 256>>>(query, keys, values);
  // 4) batched Q/K/V projections + R = pe@Wpos (fp16 out, pipelined)
  gemm_h<2><<<dim3(6, 32, 4), 256, GEMM_SMEM>>>(bq, bk, bv, bpos, nullptr);
  // 5) BD: persistent band kernel
  bd_kernel<<<dim3(32, NH), 256, BD_SMEM>>>(rrb);
  // 6) tensor-core fused attention (double-buffered K/V)
  attn_mma<<<NB*NH*(LQ/128), 256, ATTN_SMEM>>>(rwb);
  // 7) output projection (f32 out, pipelined)
  gemm_h<0><<<dim3(6, 32), 256, GEMM_SMEM>>>(bo, nullptr, nullptr, nullptr, out);
}